// round 1
// baseline (speedup 1.0000x reference)
#include <cuda_runtime.h>
#include <cuda_bf16.h>

// Problem constants (fixed by the dataset)
#define VOCAB_MAX 100000
#define BL_MAX    12800      // B*L = 64*200
#define DIM       128        // D == A == F
#define NHEAD     4
#define HDIM      32         // A / H
#define NEGF      (-4294967296.0f)   // float(-2^32+1) rounds to -2^32

typedef unsigned long long ull;

// ------------------------- scratch (device globals) -------------------------
__device__ float g_EK[VOCAB_MAX * DIM];     // E @ Wk
__device__ float g_EV[VOCAB_MAX * DIM];     // E @ Wv
__device__ float g_Esum[VOCAB_MAX];         // row sums of E (mask)
__device__ float g_Q[BL_MAX * DIM];         // gather(E,queries) @ Wq + bq
__device__ float g_res[BL_MAX * DIM];       // attn@V + bv + q_emb

// ------------------------- packed fp32x2 helpers ----------------------------
__device__ __forceinline__ void fma2(ull& d, ull a, ull b) {
    asm("fma.rn.f32x2 %0, %1, %2, %0;" : "+l"(d) : "l"(a), "l"(b));
}
__device__ __forceinline__ ull splat2(float x) {
    ull r; asm("mov.b64 %0, {%1, %1};" : "=l"(r) : "f"(x)); return r;
}

// ------------------------- K0: row sums of E --------------------------------
__global__ void k_esum(const float* __restrict__ E, int V) {
    int wg   = (blockIdx.x * blockDim.x + threadIdx.x) >> 5;
    int lane = threadIdx.x & 31;
    if (wg >= V) return;
    const float4 v = reinterpret_cast<const float4*>(E + (size_t)wg * DIM)[lane];
    float s = v.x + v.y + v.z + v.w;
    #pragma unroll
    for (int o = 16; o; o >>= 1) s += __shfl_xor_sync(0xffffffffu, s, o);
    if (lane == 0) g_Esum[wg] = s;
}

// ------------------------- K1: EK = E@Wk, EV = E@Wv -------------------------
// 256 threads; block tile = 64 vocab rows x 256 cols (Wk cols 0..127 | Wv 128..255)
// Per thread: 8 rows x 8 cols (4 f32x2 col-pairs). W in smem, E tile stored
// splat-duplicated as (e,e) ull so the inner loop is LDS.64 + fma.rn.f32x2 only.
#define PROJ_ROWS 64
#define PROJ_SMEM (128 * 256 * 4 + PROJ_ROWS * 128 * 8)   // 128KB W + 64KB E

__global__ void __launch_bounds__(256) k_proj(const float* __restrict__ E,
                                              const float* __restrict__ Wk,
                                              const float* __restrict__ Wv,
                                              int V) {
    extern __shared__ char smraw[];
    float* sW = reinterpret_cast<float*>(smraw);                 // [128][256]
    ull*   sE = reinterpret_cast<ull*>(smraw + 128 * 256 * 4);   // [64][128] splat

    const int t  = threadIdx.x;
    const int v0 = blockIdx.x * PROJ_ROWS;

    // stage W (both matrices, concatenated on the column axis)
    for (int i = t; i < 128 * 256; i += 256) {
        int d = i >> 8, c = i & 255;
        sW[i] = (c < 128) ? Wk[d * DIM + c] : Wv[d * DIM + (c - 128)];
    }
    // stage E tile, splat to (e,e)
    for (int i = t; i < PROJ_ROWS * 128; i += 256) {
        int r = i >> 7, d = i & 127;
        int row = v0 + r; if (row >= V) row = 0;
        sE[i] = splat2(E[(size_t)row * DIM + d]);
    }
    __syncthreads();

    const int cg = t & 31;        // 32 col-groups of 8 cols -> 256 cols
    const int rg = t >> 5;        // 8 row-groups of 8 rows  -> 64 rows
    const int c0 = cg * 8;
    const int r0 = rg * 8;

    ull acc[8][4];
    #pragma unroll
    for (int r = 0; r < 8; r++)
        #pragma unroll
        for (int j = 0; j < 4; j++) acc[r][j] = 0ULL;

    #pragma unroll 2
    for (int d = 0; d < 128; d++) {
        const ull* wp = reinterpret_cast<const ull*>(sW + d * 256 + c0);
        ull w0 = wp[0], w1 = wp[1], w2 = wp[2], w3 = wp[3];
        #pragma unroll
        for (int r = 0; r < 8; r++) {
            ull e2 = sE[(r0 + r) * 128 + d];
            fma2(acc[r][0], e2, w0);
            fma2(acc[r][1], e2, w1);
            fma2(acc[r][2], e2, w2);
            fma2(acc[r][3], e2, w3);
        }
    }

    #pragma unroll
    for (int r = 0; r < 8; r++) {
        int row = v0 + r0 + r;
        if (row >= V) continue;
        float* base = (c0 < 128) ? (g_EK + (size_t)row * DIM + c0)
                                 : (g_EV + (size_t)row * DIM + (c0 - 128));
        ull* dst = reinterpret_cast<ull*>(base);
        dst[0] = acc[r][0]; dst[1] = acc[r][1];
        dst[2] = acc[r][2]; dst[3] = acc[r][3];
    }
}

// ------------------------- K2: Q = gather(E, queries)@Wq + bq ---------------
// 128 threads (one per output col), 16 rows per block.
__global__ void __launch_bounds__(128) k_gemm_q(const float* __restrict__ E,
                                                const int* __restrict__ queries,
                                                const float* __restrict__ Wq,
                                                const float* __restrict__ bq,
                                                int M) {
    __shared__ float sA[16][128];
    const int t  = threadIdx.x;
    const int m0 = blockIdx.x * 16;
    for (int i = t; i < 16 * 128; i += 128) {
        int r = i >> 7, d = i & 127;
        int row = m0 + r;
        float v = 0.f;
        if (row < M) v = E[(size_t)queries[row] * DIM + d];
        sA[r][d] = v;
    }
    __syncthreads();
    float acc[16];
    const float b = bq[t];
    #pragma unroll
    for (int r = 0; r < 16; r++) acc[r] = b;
    for (int d = 0; d < 128; d++) {
        float w = Wq[d * DIM + t];
        #pragma unroll
        for (int r = 0; r < 16; r++) acc[r] = fmaf(sA[r][d], w, acc[r]);
    }
    #pragma unroll
    for (int r = 0; r < 16; r++)
        if (m0 + r < M) g_Q[(size_t)(m0 + r) * DIM + t] = acc[r];
}

// ------------------------- K3: attention core --------------------------------
// One CTA per (b,l). 128 threads.
// Phase 1: warp w handles keys k = w, w+4, ... ; lane holds Q[4l..4l+3];
//          score(head) via 8-lane segmented reduce (head = lane/8).
// Phase 2: warp h does softmax over its 50 scores.
// Phase 3: thread t accumulates out[t] = bv[t] + sum_k attn[h][k]*EV[kid][t] + q_emb[t].
__global__ void __launch_bounds__(128) k_attn(const int* __restrict__ queries,
                                              const int* __restrict__ keys,
                                              const float* __restrict__ E,
                                              const float* __restrict__ bk,
                                              const float* __restrict__ bv,
                                              int L2) {
    const int bl   = blockIdx.x;
    const int t    = threadIdx.x;
    const int w    = t >> 5;
    const int lane = t & 31;

    __shared__ int   s_kid[64];
    __shared__ float s_sc[NHEAD][64];
    __shared__ float s_attn[NHEAD][64];

    if (t < L2) s_kid[t] = keys[bl * L2 + t];

    const float4 q4  = reinterpret_cast<const float4*>(g_Q + (size_t)bl * DIM)[lane];
    const float4 kb4 = reinterpret_cast<const float4*>(bk)[lane];
    // per-lane contribution of the K bias to this head's score (constant over k)
    const float corr = q4.x * kb4.x + q4.y * kb4.y + q4.z * kb4.z + q4.w * kb4.w;
    __syncthreads();

    const float RS = 0.17677669529663687f;   // 1/sqrt(32)

    for (int k = w; k < L2; k += NHEAD) {
        int kid = s_kid[k];
        const float4 k4 = reinterpret_cast<const float4*>(g_EK + (size_t)kid * DIM)[lane];
        float p = corr;
        p = fmaf(q4.x, k4.x, p); p = fmaf(q4.y, k4.y, p);
        p = fmaf(q4.z, k4.z, p); p = fmaf(q4.w, k4.w, p);
        // reduce within 8-lane head segments
        p += __shfl_xor_sync(0xffffffffu, p, 4);
        p += __shfl_xor_sync(0xffffffffu, p, 2);
        p += __shfl_xor_sync(0xffffffffu, p, 1);
        if ((lane & 7) == 0) {
            float sc = p * RS;
            if (g_Esum[kid] == 0.0f) sc = NEGF;   // padding mask
            s_sc[lane >> 3][k] = sc;
        }
    }
    __syncthreads();

    // softmax: warp w == head w
    {
        float s0 = (lane      < L2) ? s_sc[w][lane]      : -3.4e38f;
        float s1 = (lane + 32 < L2) ? s_sc[w][lane + 32] : -3.4e38f;
        float m = fmaxf(s0, s1);
        #pragma unroll
        for (int o = 16; o; o >>= 1) m = fmaxf(m, __shfl_xor_sync(0xffffffffu, m, o));
        float e0 = (lane      < L2) ? expf(s0 - m) : 0.f;
        float e1 = (lane + 32 < L2) ? expf(s1 - m) : 0.f;
        float s = e0 + e1;
        #pragma unroll
        for (int o = 16; o; o >>= 1) s += __shfl_xor_sync(0xffffffffu, s, o);
        float inv = 1.0f / s;
        if (lane      < L2) s_attn[w][lane]      = e0 * inv;
        if (lane + 32 < L2) s_attn[w][lane + 32] = e1 * inv;
    }
    __syncthreads();

    // attn @ V  (+bv folded: attention weights sum to 1) + residual
    float o = bv[t];
    #pragma unroll 2
    for (int k = 0; k < L2; k++)
        o = fmaf(s_attn[w][k], g_EV[(size_t)s_kid[k] * DIM + t], o);

    const int qid = queries[bl];
    o += E[(size_t)qid * DIM + t];            // residual q_emb
    g_res[(size_t)bl * DIM + t] = o;
}

// ------------------------- K4: out = res @ Wf + bf --------------------------
__global__ void __launch_bounds__(128) k_gemm_f(const float* __restrict__ Wf,
                                                const float* __restrict__ bf,
                                                float* __restrict__ C,
                                                int M) {
    __shared__ float sA[16][128];
    const int t  = threadIdx.x;
    const int m0 = blockIdx.x * 16;
    for (int i = t; i < 16 * 128; i += 128) {
        int r = i >> 7, d = i & 127;
        int row = m0 + r;
        sA[r][d] = (row < M) ? g_res[(size_t)row * DIM + d] : 0.f;
    }
    __syncthreads();
    float acc[16];
    const float b = bf[t];
    #pragma unroll
    for (int r = 0; r < 16; r++) acc[r] = b;
    for (int d = 0; d < 128; d++) {
        float w = Wf[d * DIM + t];
        #pragma unroll
        for (int r = 0; r < 16; r++) acc[r] = fmaf(sA[r][d], w, acc[r]);
    }
    #pragma unroll
    for (int r = 0; r < 16; r++)
        if (m0 + r < M) C[(size_t)(m0 + r) * DIM + t] = acc[r];
}

// ------------------------- launch --------------------------------------------
extern "C" void kernel_launch(void* const* d_in, const int* in_sizes, int n_in,
                              void* d_out, int out_size) {
    const int*   queries = (const int*)d_in[0];
    const int*   keys    = (const int*)d_in[1];
    const float* E       = (const float*)d_in[2];
    const float* Wq      = (const float*)d_in[3];
    const float* bq      = (const float*)d_in[4];
    const float* Wk      = (const float*)d_in[5];
    const float* bk      = (const float*)d_in[6];
    const float* Wv      = (const float*)d_in[7];
    const float* bv      = (const float*)d_in[8];
    const float* Wf      = (const float*)d_in[9];
    const float* bf      = (const float*)d_in[10];
    float* out = (float*)d_out;

    const int V  = in_sizes[2] / DIM;   // 100000
    const int M  = in_sizes[0];         // 12800 = B*L
    const int L2 = in_sizes[1] / M;     // 50

    cudaFuncSetAttribute(k_proj, cudaFuncAttributeMaxDynamicSharedMemorySize, PROJ_SMEM);

    k_esum<<<(V + 7) / 8, 256>>>(E, V);
    k_proj<<<(V + PROJ_ROWS - 1) / PROJ_ROWS, 256, PROJ_SMEM>>>(E, Wk, Wv, V);
    k_gemm_q<<<(M + 15) / 16, 128>>>(E, queries, Wq, bq, M);
    k_attn<<<M, 128>>>(queries, keys, E, bk, bv, L2);
    k_gemm_f<<<(M + 15) / 16, 128>>>(Wf, bf, out, M);
}

// round 2
// speedup vs baseline: 1.1532x; 1.1532x over previous
#include <cuda_runtime.h>
#include <cuda_bf16.h>

#define VOCAB_MAX 100000
#define BL_MAX    12800
#define DIM       128
#define NHEAD     4
#define NEGF      (-4294967296.0f)

typedef unsigned long long ull;

// ------------------------- scratch (device globals) -------------------------
__device__ float g_EK[VOCAB_MAX * DIM];
__device__ float g_EV[VOCAB_MAX * DIM];
__device__ float g_Esum[VOCAB_MAX];
__device__ float g_Q[BL_MAX * DIM];
__device__ float g_res[BL_MAX * DIM];

// ------------------------- packed fp32x2 helpers ----------------------------
__device__ __forceinline__ void fma2(ull& d, ull a, ull b) {
    asm("fma.rn.f32x2 %0, %1, %2, %0;" : "+l"(d) : "l"(a), "l"(b));
}
__device__ __forceinline__ ull splat2(float x) {
    ull r; asm("mov.b64 %0, {%1, %1};" : "=l"(r) : "f"(x)); return r;
}

// ------------------------- K0: row sums of E --------------------------------
__global__ void k_esum(const float* __restrict__ E, int V) {
    int wg   = (blockIdx.x * blockDim.x + threadIdx.x) >> 5;
    int lane = threadIdx.x & 31;
    if (wg >= V) return;
    const float4 v = reinterpret_cast<const float4*>(E + (size_t)wg * DIM)[lane];
    float s = v.x + v.y + v.z + v.w;
    #pragma unroll
    for (int o = 16; o; o >>= 1) s += __shfl_xor_sync(0xffffffffu, s, o);
    if (lane == 0) g_Esum[wg] = s;
}

// ------------------------- K1: EK = E@Wk, EV = E@Wv -------------------------
// 256 threads; tile = 64 rows x 256 cols (Wk | Wv concatenated on columns).
// Thread (rg = t>>5, cg = t&31) owns rows rg*8..+7 and cols {cg*4..+3} in each
// of the two 128-col groups. All W loads are LDS.128 with 16B lane stride
// (conflict-free); E loads are LDS.128 broadcasts (4 d's at a time).
#define PROJ_ROWS 64
#define PROJ_SMEM (128 * 256 * 4 + PROJ_ROWS * 128 * 4)   // 128KB W + 32KB E

__global__ void __launch_bounds__(256) k_proj(const float* __restrict__ E,
                                              const float* __restrict__ Wk,
                                              const float* __restrict__ Wv,
                                              int V) {
    extern __shared__ char smraw[];
    float* sW = reinterpret_cast<float*>(smraw);                 // [128][256]
    float* sE = reinterpret_cast<float*>(smraw + 128 * 256 * 4); // [64][128]

    const int t  = threadIdx.x;
    const int v0 = blockIdx.x * PROJ_ROWS;

    // stage W: row d, cols 0..127 = Wk[d][*], cols 128..255 = Wv[d][*]
    for (int i = t; i < 128 * 256; i += 256) {
        int d = i >> 8, c = i & 255;
        sW[i] = (c < 128) ? Wk[d * DIM + c] : Wv[d * DIM + (c - 128)];
    }
    // stage E tile (float4 global loads)
    for (int i = t; i < PROJ_ROWS * 128 / 4; i += 256) {
        int r = i >> 5, dq = i & 31;          // 32 float4 per row
        int row = v0 + r; if (row >= V) row = 0;
        reinterpret_cast<float4*>(sE)[i] =
            reinterpret_cast<const float4*>(E + (size_t)row * DIM)[dq];
    }
    __syncthreads();

    const int cg = t & 31;
    const int rg = t >> 5;
    const int c0 = cg * 4;

    ull acc[8][4];
    #pragma unroll
    for (int r = 0; r < 8; r++)
        #pragma unroll
        for (int j = 0; j < 4; j++) acc[r][j] = 0ULL;

    for (int d0 = 0; d0 < 128; d0 += 4) {
        // W chunk: 4 d's x 2 col-groups, each a 16B (2-ull) load, conflict-free
        ulonglong2 wA[4], wB[4];
        #pragma unroll
        for (int dd = 0; dd < 4; dd++) {
            wA[dd] = *reinterpret_cast<const ulonglong2*>(sW + (d0 + dd) * 256 + c0);
            wB[dd] = *reinterpret_cast<const ulonglong2*>(sW + (d0 + dd) * 256 + 128 + c0);
        }
        #pragma unroll
        for (int r = 0; r < 8; r++) {
            const float4 e = *reinterpret_cast<const float4*>(sE + (rg * 8 + r) * 128 + d0);
            ull e0 = splat2(e.x), e1 = splat2(e.y), e2 = splat2(e.z), e3 = splat2(e.w);
            fma2(acc[r][0], e0, wA[0].x); fma2(acc[r][1], e0, wA[0].y);
            fma2(acc[r][2], e0, wB[0].x); fma2(acc[r][3], e0, wB[0].y);
            fma2(acc[r][0], e1, wA[1].x); fma2(acc[r][1], e1, wA[1].y);
            fma2(acc[r][2], e1, wB[1].x); fma2(acc[r][3], e1, wB[1].y);
            fma2(acc[r][0], e2, wA[2].x); fma2(acc[r][1], e2, wA[2].y);
            fma2(acc[r][2], e2, wB[2].x); fma2(acc[r][3], e2, wB[2].y);
            fma2(acc[r][0], e3, wA[3].x); fma2(acc[r][1], e3, wA[3].y);
            fma2(acc[r][2], e3, wB[3].x); fma2(acc[r][3], e3, wB[3].y);
        }
    }

    #pragma unroll
    for (int r = 0; r < 8; r++) {
        int row = v0 + rg * 8 + r;
        if (row >= V) continue;
        ull* dk = reinterpret_cast<ull*>(g_EK + (size_t)row * DIM + c0);
        ull* dv = reinterpret_cast<ull*>(g_EV + (size_t)row * DIM + c0);
        dk[0] = acc[r][0]; dk[1] = acc[r][1];
        dv[0] = acc[r][2]; dv[1] = acc[r][3];
    }
}

// ------------------------- K2: Q = gather(E, queries)@Wq + bq ---------------
__global__ void __launch_bounds__(128) k_gemm_q(const float* __restrict__ E,
                                                const int* __restrict__ queries,
                                                const float* __restrict__ Wq,
                                                const float* __restrict__ bq,
                                                int M) {
    __shared__ float sA[16][128];
    const int t  = threadIdx.x;
    const int m0 = blockIdx.x * 16;
    for (int i = t; i < 16 * 128; i += 128) {
        int r = i >> 7, d = i & 127;
        int row = m0 + r;
        float v = 0.f;
        if (row < M) v = E[(size_t)queries[row] * DIM + d];
        sA[r][d] = v;
    }
    __syncthreads();
    float acc[16];
    const float b = bq[t];
    #pragma unroll
    for (int r = 0; r < 16; r++) acc[r] = b;
    for (int d = 0; d < 128; d++) {
        float w = Wq[d * DIM + t];
        #pragma unroll
        for (int r = 0; r < 16; r++) acc[r] = fmaf(sA[r][d], w, acc[r]);
    }
    #pragma unroll
    for (int r = 0; r < 16; r++)
        if (m0 + r < M) g_Q[(size_t)(m0 + r) * DIM + t] = acc[r];
}

// ------------------------- K3: attention core --------------------------------
__global__ void __launch_bounds__(128) k_attn(const int* __restrict__ queries,
                                              const int* __restrict__ keys,
                                              const float* __restrict__ E,
                                              const float* __restrict__ bk,
                                              const float* __restrict__ bv,
                                              int L2) {
    const int bl   = blockIdx.x;
    const int t    = threadIdx.x;
    const int w    = t >> 5;
    const int lane = t & 31;

    __shared__ int   s_kid[64];
    __shared__ float s_sc[NHEAD][64];
    __shared__ float s_attn[NHEAD][64];

    if (t < L2) s_kid[t] = keys[bl * L2 + t];

    const float4 q4  = reinterpret_cast<const float4*>(g_Q + (size_t)bl * DIM)[lane];
    const float4 kb4 = reinterpret_cast<const float4*>(bk)[lane];
    const float corr = q4.x * kb4.x + q4.y * kb4.y + q4.z * kb4.z + q4.w * kb4.w;
    __syncthreads();

    const float RS = 0.17677669529663687f;   // 1/sqrt(32)

    // phase 1: scores, 2 keys in flight per warp
    for (int k = w; k < L2; k += 2 * NHEAD) {
        int kid0 = s_kid[k];
        int k1   = k + NHEAD;
        int kid1 = (k1 < L2) ? s_kid[k1] : kid0;
        const float4 ka = reinterpret_cast<const float4*>(g_EK + (size_t)kid0 * DIM)[lane];
        const float4 kb = reinterpret_cast<const float4*>(g_EK + (size_t)kid1 * DIM)[lane];
        float p0 = corr, p1 = corr;
        p0 = fmaf(q4.x, ka.x, p0); p1 = fmaf(q4.x, kb.x, p1);
        p0 = fmaf(q4.y, ka.y, p0); p1 = fmaf(q4.y, kb.y, p1);
        p0 = fmaf(q4.z, ka.z, p0); p1 = fmaf(q4.z, kb.z, p1);
        p0 = fmaf(q4.w, ka.w, p0); p1 = fmaf(q4.w, kb.w, p1);
        #pragma unroll
        for (int o = 4; o; o >>= 1) {
            p0 += __shfl_xor_sync(0xffffffffu, p0, o);
            p1 += __shfl_xor_sync(0xffffffffu, p1, o);
        }
        if ((lane & 7) == 0) {
            float sc0 = p0 * RS;
            if (g_Esum[kid0] == 0.0f) sc0 = NEGF;
            s_sc[lane >> 3][k] = sc0;
            if (k1 < L2) {
                float sc1 = p1 * RS;
                if (g_Esum[kid1] == 0.0f) sc1 = NEGF;
                s_sc[lane >> 3][k1] = sc1;
            }
        }
    }
    __syncthreads();

    // phase 2: softmax, warp w == head w
    {
        float s0 = (lane      < L2) ? s_sc[w][lane]      : -3.4e38f;
        float s1 = (lane + 32 < L2) ? s_sc[w][lane + 32] : -3.4e38f;
        float m = fmaxf(s0, s1);
        #pragma unroll
        for (int o = 16; o; o >>= 1) m = fmaxf(m, __shfl_xor_sync(0xffffffffu, m, o));
        float e0 = (lane      < L2) ? expf(s0 - m) : 0.f;
        float e1 = (lane + 32 < L2) ? expf(s1 - m) : 0.f;
        float s = e0 + e1;
        #pragma unroll
        for (int o = 16; o; o >>= 1) s += __shfl_xor_sync(0xffffffffu, s, o);
        float inv = 1.0f / s;
        if (lane      < L2) s_attn[w][lane]      = e0 * inv;
        if (lane + 32 < L2) s_attn[w][lane + 32] = e1 * inv;
    }
    __syncthreads();

    // phase 3: attn @ V with 5 independent accumulators (MLP)
    float o0 = bv[t], o1 = 0.f, o2 = 0.f, o3 = 0.f, o4 = 0.f;
    int k = 0;
    for (; k + 5 <= L2; k += 5) {
        int i0 = s_kid[k],     i1 = s_kid[k + 1], i2 = s_kid[k + 2];
        int i3 = s_kid[k + 3], i4 = s_kid[k + 4];
        float v0 = g_EV[(size_t)i0 * DIM + t];
        float v1 = g_EV[(size_t)i1 * DIM + t];
        float v2 = g_EV[(size_t)i2 * DIM + t];
        float v3 = g_EV[(size_t)i3 * DIM + t];
        float v4 = g_EV[(size_t)i4 * DIM + t];
        o0 = fmaf(s_attn[w][k],     v0, o0);
        o1 = fmaf(s_attn[w][k + 1], v1, o1);
        o2 = fmaf(s_attn[w][k + 2], v2, o2);
        o3 = fmaf(s_attn[w][k + 3], v3, o3);
        o4 = fmaf(s_attn[w][k + 4], v4, o4);
    }
    for (; k < L2; k++)
        o0 = fmaf(s_attn[w][k], g_EV[(size_t)s_kid[k] * DIM + t], o0);
    float o = ((o0 + o1) + (o2 + o3)) + o4;

    const int qid = queries[bl];
    o += E[(size_t)qid * DIM + t];
    g_res[(size_t)bl * DIM + t] = o;
}

// ------------------------- K4: out = res @ Wf + bf --------------------------
__global__ void __launch_bounds__(128) k_gemm_f(const float* __restrict__ Wf,
                                                const float* __restrict__ bf,
                                                float* __restrict__ C,
                                                int M) {
    __shared__ float sA[16][128];
    const int t  = threadIdx.x;
    const int m0 = blockIdx.x * 16;
    for (int i = t; i < 16 * 128; i += 128) {
        int r = i >> 7, d = i & 127;
        int row = m0 + r;
        sA[r][d] = (row < M) ? g_res[(size_t)row * DIM + d] : 0.f;
    }
    __syncthreads();
    float acc[16];
    const float b = bf[t];
    #pragma unroll
    for (int r = 0; r < 16; r++) acc[r] = b;
    for (int d = 0; d < 128; d++) {
        float w = Wf[d * DIM + t];
        #pragma unroll
        for (int r = 0; r < 16; r++) acc[r] = fmaf(sA[r][d], w, acc[r]);
    }
    #pragma unroll
    for (int r = 0; r < 16; r++)
        if (m0 + r < M) C[(size_t)(m0 + r) * DIM + t] = acc[r];
}

// ------------------------- launch --------------------------------------------
extern "C" void kernel_launch(void* const* d_in, const int* in_sizes, int n_in,
                              void* d_out, int out_size) {
    const int*   queries = (const int*)d_in[0];
    const int*   keys    = (const int*)d_in[1];
    const float* E       = (const float*)d_in[2];
    const float* Wq      = (const float*)d_in[3];
    const float* bq      = (const float*)d_in[4];
    const float* Wk      = (const float*)d_in[5];
    const float* bk      = (const float*)d_in[6];
    const float* Wv      = (const float*)d_in[7];
    const float* bv      = (const float*)d_in[8];
    const float* Wf      = (const float*)d_in[9];
    const float* bf      = (const float*)d_in[10];
    float* out = (float*)d_out;

    const int V  = in_sizes[2] / DIM;
    const int M  = in_sizes[0];
    const int L2 = in_sizes[1] / M;

    cudaFuncSetAttribute(k_proj, cudaFuncAttributeMaxDynamicSharedMemorySize, PROJ_SMEM);

    k_esum<<<(V + 7) / 8, 256>>>(E, V);
    k_proj<<<(V + PROJ_ROWS - 1) / PROJ_ROWS, 256, PROJ_SMEM>>>(E, Wk, Wv, V);
    k_gemm_q<<<(M + 15) / 16, 128>>>(E, queries, Wq, bq, M);
    k_attn<<<M, 128>>>(queries, keys, E, bk, bv, L2);
    k_gemm_f<<<(M + 15) / 16, 128>>>(Wf, bf, out, M);
}

// round 4
// speedup vs baseline: 1.6552x; 1.4353x over previous
#include <cuda_runtime.h>
#include <cuda_bf16.h>
#include <cstdint>

#define VOCAB_MAX 100000
#define BL_MAX    12800
#define DIM       128
#define NHEAD     4
#define NEGF      (-4294967296.0f)

// ------------------------- scratch (device globals) -------------------------
__device__ float g_EK[VOCAB_MAX * DIM];
__device__ float g_EV[VOCAB_MAX * DIM];
__device__ float g_Esum[VOCAB_MAX];
__device__ float g_Q[BL_MAX * DIM];
__device__ float g_res[BL_MAX * DIM];
// swizzled bf16 images of [Wk|Wv]^T (n-major, k contiguous), hi/lo split
__device__ uint4 g_WThi[4096];   // 64KB: [n=256][kchunk=16] with chunk ^= n&7
__device__ uint4 g_WTlo[4096];

// ------------------------- helpers ------------------------------------------
__device__ __forceinline__ uint32_t smem_to_u32(const void* p) {
    uint32_t a;
    asm("{ .reg .u64 t; cvta.to.shared.u64 t, %1; cvt.u32.u64 %0, t; }" : "=r"(a) : "l"(p));
    return a;
}
// pack two fp32 -> bf16x2 (first arg = low 16 bits)
__device__ __forceinline__ uint32_t pack_bf2(float lo, float hi) {
    uint32_t r; asm("cvt.rn.bf16x2.f32 %0, %1, %2;" : "=r"(r) : "f"(hi), "f"(lo)); return r;
}
__device__ __forceinline__ void ldsm_x4(uint32_t addr, uint32_t* r) {
    asm volatile("ldmatrix.sync.aligned.m8n8.x4.shared.b16 {%0,%1,%2,%3}, [%4];"
                 : "=r"(r[0]), "=r"(r[1]), "=r"(r[2]), "=r"(r[3]) : "r"(addr));
}
__device__ __forceinline__ void mma_bf16(float* c, const uint32_t* a, uint32_t b0, uint32_t b1) {
    asm volatile("mma.sync.aligned.m16n8k16.row.col.f32.bf16.bf16.f32 "
                 "{%0,%1,%2,%3}, {%4,%5,%6,%7}, {%8,%9}, {%0,%1,%2,%3};"
                 : "+f"(c[0]), "+f"(c[1]), "+f"(c[2]), "+f"(c[3])
                 : "r"(a[0]), "r"(a[1]), "r"(a[2]), "r"(a[3]), "r"(b0), "r"(b1));
}

// ------------------------- K0: row sums of E --------------------------------
__global__ void k_esum(const float* __restrict__ E, int V) {
    int wg   = (blockIdx.x * blockDim.x + threadIdx.x) >> 5;
    int lane = threadIdx.x & 31;
    if (wg >= V) return;
    const float4 v = reinterpret_cast<const float4*>(E + (size_t)wg * DIM)[lane];
    float s = v.x + v.y + v.z + v.w;
    #pragma unroll
    for (int o = 16; o; o >>= 1) s += __shfl_xor_sync(0xffffffffu, s, o);
    if (lane == 0) g_Esum[wg] = s;
}

// ------------------------- K0b: prep swizzled W^T hi/lo images ---------------
// unit u = (n, kchunk): read 8 strided W values, write one 16B hi + 16B lo.
__global__ void k_wprep(const float* __restrict__ Wk, const float* __restrict__ Wv) {
    int u  = blockIdx.x * blockDim.x + threadIdx.x;   // 4096 units
    int n  = u & 255;
    int kc = u >> 8;                                  // 0..15
    const float* src = (n < 128) ? (Wk + n) : (Wv + (n - 128));
    float f[8];
    #pragma unroll
    for (int i = 0; i < 8; i++) f[i] = src[(size_t)(kc * 8 + i) * DIM];
    uint32_t h[4], l[4];
    #pragma unroll
    for (int i = 0; i < 4; i++) {
        h[i] = pack_bf2(f[2 * i], f[2 * i + 1]);
        l[i] = pack_bf2(f[2 * i]     - __uint_as_float(h[i] << 16),
                        f[2 * i + 1] - __uint_as_float(h[i] & 0xffff0000u));
    }
    int idx = n * 16 + (kc ^ (n & 7));
    g_WThi[idx] = make_uint4(h[0], h[1], h[2], h[3]);
    g_WTlo[idx] = make_uint4(l[0], l[1], l[2], l[3]);
}

// ------------------------- K1: HMMA projection -------------------------------
// EK|EV = E @ [Wk|Wv] via mma.sync bf16 hi/lo 3-pass split.
// CTA tile: M=128 vocab rows x N=256 cols, K=128. 16 warps, each 32x64.
#define A_HI 0
#define A_LO 32768
#define B_HI 65536
#define B_LO 131072
#define PROJ_SMEM 196608

__global__ void __launch_bounds__(512, 1)
k_proj_mma(const float* __restrict__ E, int V) {
    extern __shared__ char smem[];
    const uint32_t sb = smem_to_u32(smem);
    const int t    = threadIdx.x;
    const int w    = t >> 5;
    const int lane = t & 31;
    const int v0   = blockIdx.x * 128;

    // ---- stage A: E tile -> bf16 hi/lo, row-major 256B rows, chunk ^= row&7
    #pragma unroll
    for (int i = 0; i < 4; i++) {
        int u   = t + 512 * i;           // 2048 units of 8 k
        int row = u >> 4;
        int kc  = u & 15;
        int gr  = v0 + row; if (gr >= V) gr = 0;
        const float4* src = reinterpret_cast<const float4*>(E + (size_t)gr * DIM + kc * 8);
        float4 f0 = src[0], f1 = src[1];
        uint32_t h0 = pack_bf2(f0.x, f0.y), h1 = pack_bf2(f0.z, f0.w);
        uint32_t h2 = pack_bf2(f1.x, f1.y), h3 = pack_bf2(f1.z, f1.w);
        uint32_t l0 = pack_bf2(f0.x - __uint_as_float(h0 << 16), f0.y - __uint_as_float(h0 & 0xffff0000u));
        uint32_t l1 = pack_bf2(f0.z - __uint_as_float(h1 << 16), f0.w - __uint_as_float(h1 & 0xffff0000u));
        uint32_t l2 = pack_bf2(f1.x - __uint_as_float(h2 << 16), f1.y - __uint_as_float(h2 & 0xffff0000u));
        uint32_t l3 = pack_bf2(f1.z - __uint_as_float(h3 << 16), f1.w - __uint_as_float(h3 & 0xffff0000u));
        uint32_t off = (uint32_t)row * 256 + (uint32_t)((kc ^ (row & 7)) << 4);
        *reinterpret_cast<uint4*>(smem + A_HI + off) = make_uint4(h0, h1, h2, h3);
        *reinterpret_cast<uint4*>(smem + A_LO + off) = make_uint4(l0, l1, l2, l3);
    }
    // ---- stage B: straight copy of prebuilt swizzled images (L2-resident)
    {
        uint4* dh = reinterpret_cast<uint4*>(smem + B_HI);
        uint4* dl = reinterpret_cast<uint4*>(smem + B_LO);
        #pragma unroll
        for (int i = 0; i < 8; i++) {
            int idx = t + 512 * i;
            dh[idx] = g_WThi[idx];
            dl[idx] = g_WTlo[idx];
        }
    }
    __syncthreads();

    // ---- compute: warp = (mg = w&3) rows mg*32.., (ng = w>>2) cols ng*64..
    const int mg = w & 3;
    const int ng = w >> 2;

    float acc[2][8][4];
    #pragma unroll
    for (int mt = 0; mt < 2; mt++)
        #pragma unroll
        for (int nt = 0; nt < 8; nt++)
            #pragma unroll
            for (int j = 0; j < 4; j++) acc[mt][nt][j] = 0.f;

    // per-lane fixed pieces of ldmatrix addressing
    const int aRow  = mg * 32 + ((lane >> 3) & 1) * 8 + (lane & 7);   // + mt*16
    const int aKsel = (lane >> 4);                                    // kc offset
    const int bN    = ng * 64 + ((lane >> 4) & 1) * 8 + (lane & 7);   // + bt*16
    const int bKsel = (lane >> 3) & 1;

    #pragma unroll
    for (int p = 0; p < 3; p++) {
        const uint32_t abase = sb + (p == 2 ? A_LO : A_HI);
        const uint32_t bbase = sb + (p == 1 ? B_LO : B_HI);
        #pragma unroll
        for (int ks = 0; ks < 8; ks++) {
            uint32_t a[2][4];
            #pragma unroll
            for (int mt = 0; mt < 2; mt++) {
                int row = aRow + mt * 16;
                int kc  = ks * 2 + aKsel;
                ldsm_x4(abase + row * 256 + (((kc ^ (row & 7)) << 4)), a[mt]);
            }
            uint32_t b[4][4];
            #pragma unroll
            for (int bt = 0; bt < 4; bt++) {
                int n  = bN + bt * 16;
                int kc = ks * 2 + bKsel;
                ldsm_x4(bbase + n * 256 + (((kc ^ (n & 7)) << 4)), b[bt]);
            }
            #pragma unroll
            for (int mt = 0; mt < 2; mt++)
                #pragma unroll
                for (int nt = 0; nt < 8; nt++)
                    mma_bf16(acc[mt][nt], a[mt], b[nt >> 1][(nt & 1) * 2], b[nt >> 1][(nt & 1) * 2 + 1]);
        }
    }

    // ---- epilogue: write fp32 EK/EV directly from accumulators
    #pragma unroll
    for (int mt = 0; mt < 2; mt++) {
        int row = v0 + mg * 32 + mt * 16 + (lane >> 2);
        #pragma unroll
        for (int nt = 0; nt < 8; nt++) {
            int col = ng * 64 + nt * 8 + (lane & 3) * 2;
            float* base = (col < 128) ? (g_EK + (size_t)row * DIM + col)
                                      : (g_EV + (size_t)row * DIM + (col - 128));
            if (row < V) {
                *reinterpret_cast<float2*>(base)             = make_float2(acc[mt][nt][0], acc[mt][nt][1]);
                *reinterpret_cast<float2*>(base + 8 * DIM)   = make_float2(acc[mt][nt][2], acc[mt][nt][3]);
            }
        }
    }
}

// ------------------------- K2: Q = gather(E, queries)@Wq + bq ---------------
__global__ void __launch_bounds__(128) k_gemm_q(const float* __restrict__ E,
                                                const int* __restrict__ queries,
                                                const float* __restrict__ Wq,
                                                const float* __restrict__ bq,
                                                int M) {
    __shared__ float sA[16][128];
    const int t  = threadIdx.x;
    const int m0 = blockIdx.x * 16;
    for (int i = t; i < 16 * 128; i += 128) {
        int r = i >> 7, d = i & 127;
        int row = m0 + r;
        float v = 0.f;
        if (row < M) v = E[(size_t)queries[row] * DIM + d];
        sA[r][d] = v;
    }
    __syncthreads();
    float acc[16];
    const float b = bq[t];
    #pragma unroll
    for (int r = 0; r < 16; r++) acc[r] = b;
    for (int d = 0; d < 128; d++) {
        float w = Wq[d * DIM + t];
        #pragma unroll
        for (int r = 0; r < 16; r++) acc[r] = fmaf(sA[r][d], w, acc[r]);
    }
    #pragma unroll
    for (int r = 0; r < 16; r++)
        if (m0 + r < M) g_Q[(size_t)(m0 + r) * DIM + t] = acc[r];
}

// ------------------------- K3: attention core --------------------------------
__global__ void __launch_bounds__(128) k_attn(const int* __restrict__ queries,
                                              const int* __restrict__ keys,
                                              const float* __restrict__ E,
                                              const float* __restrict__ bk,
                                              const float* __restrict__ bv,
                                              int L2) {
    const int bl   = blockIdx.x;
    const int t    = threadIdx.x;
    const int w    = t >> 5;
    const int lane = t & 31;

    __shared__ int   s_kid[64];
    __shared__ float s_sc[NHEAD][64];
    __shared__ float s_attn[NHEAD][64];

    if (t < L2) s_kid[t] = keys[bl * L2 + t];

    const float4 q4  = reinterpret_cast<const float4*>(g_Q + (size_t)bl * DIM)[lane];
    const float4 kb4 = reinterpret_cast<const float4*>(bk)[lane];
    const float corr = q4.x * kb4.x + q4.y * kb4.y + q4.z * kb4.z + q4.w * kb4.w;
    __syncthreads();

    const float RS = 0.17677669529663687f;   // 1/sqrt(32)

    for (int k = w; k < L2; k += 2 * NHEAD) {
        int kid0 = s_kid[k];
        int k1   = k + NHEAD;
        int kid1 = (k1 < L2) ? s_kid[k1] : kid0;
        const float4 ka = reinterpret_cast<const float4*>(g_EK + (size_t)kid0 * DIM)[lane];
        const float4 kb = reinterpret_cast<const float4*>(g_EK + (size_t)kid1 * DIM)[lane];
        float p0 = corr, p1 = corr;
        p0 = fmaf(q4.x, ka.x, p0); p1 = fmaf(q4.x, kb.x, p1);
        p0 = fmaf(q4.y, ka.y, p0); p1 = fmaf(q4.y, kb.y, p1);
        p0 = fmaf(q4.z, ka.z, p0); p1 = fmaf(q4.z, kb.z, p1);
        p0 = fmaf(q4.w, ka.w, p0); p1 = fmaf(q4.w, kb.w, p1);
        #pragma unroll
        for (int o = 4; o; o >>= 1) {
            p0 += __shfl_xor_sync(0xffffffffu, p0, o);
            p1 += __shfl_xor_sync(0xffffffffu, p1, o);
        }
        if ((lane & 7) == 0) {
            float sc0 = p0 * RS;
            if (g_Esum[kid0] == 0.0f) sc0 = NEGF;
            s_sc[lane >> 3][k] = sc0;
            if (k1 < L2) {
                float sc1 = p1 * RS;
                if (g_Esum[kid1] == 0.0f) sc1 = NEGF;
                s_sc[lane >> 3][k1] = sc1;
            }
        }
    }
    __syncthreads();

    {
        float s0 = (lane      < L2) ? s_sc[w][lane]      : -3.4e38f;
        float s1 = (lane + 32 < L2) ? s_sc[w][lane + 32] : -3.4e38f;
        float m = fmaxf(s0, s1);
        #pragma unroll
        for (int o = 16; o; o >>= 1) m = fmaxf(m, __shfl_xor_sync(0xffffffffu, m, o));
        float e0 = (lane      < L2) ? expf(s0 - m) : 0.f;
        float e1 = (lane + 32 < L2) ? expf(s1 - m) : 0.f;
        float s = e0 + e1;
        #pragma unroll
        for (int o = 16; o; o >>= 1) s += __shfl_xor_sync(0xffffffffu, s, o);
        float inv = 1.0f / s;
        if (lane      < L2) s_attn[w][lane]      = e0 * inv;
        if (lane + 32 < L2) s_attn[w][lane + 32] = e1 * inv;
    }
    __syncthreads();

    float o0 = bv[t], o1 = 0.f, o2 = 0.f, o3 = 0.f, o4 = 0.f;
    int k = 0;
    for (; k + 5 <= L2; k += 5) {
        int i0 = s_kid[k],     i1 = s_kid[k + 1], i2 = s_kid[k + 2];
        int i3 = s_kid[k + 3], i4 = s_kid[k + 4];
        float v0 = g_EV[(size_t)i0 * DIM + t];
        float v1 = g_EV[(size_t)i1 * DIM + t];
        float v2 = g_EV[(size_t)i2 * DIM + t];
        float v3 = g_EV[(size_t)i3 * DIM + t];
        float v4 = g_EV[(size_t)i4 * DIM + t];
        o0 = fmaf(s_attn[w][k],     v0, o0);
        o1 = fmaf(s_attn[w][k + 1], v1, o1);
        o2 = fmaf(s_attn[w][k + 2], v2, o2);
        o3 = fmaf(s_attn[w][k + 3], v3, o3);
        o4 = fmaf(s_attn[w][k + 4], v4, o4);
    }
    for (; k < L2; k++)
        o0 = fmaf(s_attn[w][k], g_EV[(size_t)s_kid[k] * DIM + t], o0);
    float o = ((o0 + o1) + (o2 + o3)) + o4;

    const int qid = queries[bl];
    o += E[(size_t)qid * DIM + t];
    g_res[(size_t)bl * DIM + t] = o;
}

// ------------------------- K4: out = res @ Wf + bf --------------------------
__global__ void __launch_bounds__(128) k_gemm_f(const float* __restrict__ Wf,
                                                const float* __restrict__ bf,
                                                float* __restrict__ C,
                                                int M) {
    __shared__ float sA[16][128];
    const int t  = threadIdx.x;
    const int m0 = blockIdx.x * 16;
    for (int i = t; i < 16 * 128; i += 128) {
        int r = i >> 7, d = i & 127;
        int row = m0 + r;
        sA[r][d] = (row < M) ? g_res[(size_t)row * DIM + d] : 0.f;
    }
    __syncthreads();
    float acc[16];
    const float b = bf[t];
    #pragma unroll
    for (int r = 0; r < 16; r++) acc[r] = b;
    for (int d = 0; d < 128; d++) {
        float w = Wf[d * DIM + t];
        #pragma unroll
        for (int r = 0; r < 16; r++) acc[r] = fmaf(sA[r][d], w, acc[r]);
    }
    #pragma unroll
    for (int r = 0; r < 16; r++)
        if (m0 + r < M) C[(size_t)(m0 + r) * DIM + t] = acc[r];
}

// ------------------------- launch --------------------------------------------
extern "C" void kernel_launch(void* const* d_in, const int* in_sizes, int n_in,
                              void* d_out, int out_size) {
    const int*   queries = (const int*)d_in[0];
    const int*   keys    = (const int*)d_in[1];
    const float* E       = (const float*)d_in[2];
    const float* Wq      = (const float*)d_in[3];
    const float* bq      = (const float*)d_in[4];
    const float* Wk      = (const float*)d_in[5];
    const float* bk      = (const float*)d_in[6];
    const float* Wv      = (const float*)d_in[7];
    const float* bv      = (const float*)d_in[8];
    const float* Wf      = (const float*)d_in[9];
    const float* bf      = (const float*)d_in[10];
    float* out = (float*)d_out;

    const int V  = in_sizes[2] / DIM;
    const int M  = in_sizes[0];
    const int L2 = in_sizes[1] / M;

    cudaFuncSetAttribute(k_proj_mma, cudaFuncAttributeMaxDynamicSharedMemorySize, PROJ_SMEM);

    k_esum<<<(V + 7) / 8, 256>>>(E, V);
    k_wprep<<<16, 256>>>(Wk, Wv);
    k_proj_mma<<<(V + 127) / 128, 512, PROJ_SMEM>>>(E, V);
    k_gemm_q<<<(M + 15) / 16, 128>>>(E, queries, Wq, bq, M);
    k_attn<<<M, 128>>>(queries, keys, E, bk, bv, L2);
    k_gemm_f<<<(M + 15) / 16, 128>>>(Wf, bf, out, M);
}

// round 5
// speedup vs baseline: 2.2477x; 1.3579x over previous
#include <cuda_runtime.h>
#include <cuda_bf16.h>
#include <cstdint>

#define VOCAB_MAX 100000
#define BL_MAX    12800
#define DIM       128
#define NHEAD     4
#define NEGF      (-4294967296.0f)

// ------------------------- scratch (device globals) -------------------------
__device__ __nv_bfloat16 g_EKbf[VOCAB_MAX * DIM];   // E @ Wk  (bf16)
__device__ __nv_bfloat16 g_EVbf[VOCAB_MAX * DIM];   // E @ Wv  (bf16)
__device__ float g_Esum[VOCAB_MAX];
__device__ float g_Q[BL_MAX * DIM];
__device__ float g_res[BL_MAX * DIM];
// swizzled bf16 images of W^T (n-major, k contiguous), hi/lo split
__device__ uint4 g_WThi[4096];   // [Wk|Wv]: [n=256][kc=16], kc ^= n&7
__device__ uint4 g_WTlo[4096];
__device__ uint4 g_WQhi[2048];   // Wq: [n=128][kc=16]
__device__ uint4 g_WQlo[2048];
__device__ uint4 g_WFhi[2048];   // Wf
__device__ uint4 g_WFlo[2048];

// ------------------------- helpers ------------------------------------------
__device__ __forceinline__ uint32_t smem_to_u32(const void* p) {
    uint32_t a;
    asm("{ .reg .u64 t; cvta.to.shared.u64 t, %1; cvt.u32.u64 %0, t; }" : "=r"(a) : "l"(p));
    return a;
}
__device__ __forceinline__ uint32_t pack_bf2(float lo, float hi) {
    uint32_t r; asm("cvt.rn.bf16x2.f32 %0, %1, %2;" : "=r"(r) : "f"(hi), "f"(lo)); return r;
}
__device__ __forceinline__ void ldsm_x4(uint32_t addr, uint32_t* r) {
    asm volatile("ldmatrix.sync.aligned.m8n8.x4.shared.b16 {%0,%1,%2,%3}, [%4];"
                 : "=r"(r[0]), "=r"(r[1]), "=r"(r[2]), "=r"(r[3]) : "r"(addr));
}
__device__ __forceinline__ void mma_bf16(float* c, const uint32_t* a, uint32_t b0, uint32_t b1) {
    asm volatile("mma.sync.aligned.m16n8k16.row.col.f32.bf16.bf16.f32 "
                 "{%0,%1,%2,%3}, {%4,%5,%6,%7}, {%8,%9}, {%0,%1,%2,%3};"
                 : "+f"(c[0]), "+f"(c[1]), "+f"(c[2]), "+f"(c[3])
                 : "r"(a[0]), "r"(a[1]), "r"(a[2]), "r"(a[3]), "r"(b0), "r"(b1));
}
// split fp32 pair -> bf16x2 hi + bf16x2 lo
__device__ __forceinline__ void split2(float x, float y, uint32_t& h, uint32_t& l) {
    h = pack_bf2(x, y);
    l = pack_bf2(x - __uint_as_float(h << 16), y - __uint_as_float(h & 0xffff0000u));
}

// ------------------------- K0: prep all W^T hi/lo images ---------------------
__global__ void k_wprep(const float* __restrict__ Wk, const float* __restrict__ Wv,
                        const float* __restrict__ Wq, const float* __restrict__ Wf) {
    int u = blockIdx.x * blockDim.x + threadIdx.x;    // 8192 units
    const float* src;
    uint4 *dh, *dl;
    int n, kc;
    if (u < 4096) {                       // [Wk|Wv]
        n = u & 255; kc = u >> 8;
        src = (n < 128) ? (Wk + n) : (Wv + (n - 128));
        int idx = n * 16 + (kc ^ (n & 7));
        dh = g_WThi + idx; dl = g_WTlo + idx;
    } else if (u < 6144) {                // Wq
        int u2 = u - 4096; n = u2 & 127; kc = u2 >> 7;
        src = Wq + n;
        int idx = n * 16 + (kc ^ (n & 7));
        dh = g_WQhi + idx; dl = g_WQlo + idx;
    } else {                              // Wf
        int u2 = u - 6144; n = u2 & 127; kc = u2 >> 7;
        src = Wf + n;
        int idx = n * 16 + (kc ^ (n & 7));
        dh = g_WFhi + idx; dl = g_WFlo + idx;
    }
    float f[8];
    #pragma unroll
    for (int i = 0; i < 8; i++) f[i] = src[(size_t)(kc * 8 + i) * DIM];
    uint32_t h[4], l[4];
    #pragma unroll
    for (int i = 0; i < 4; i++) split2(f[2 * i], f[2 * i + 1], h[i], l[i]);
    *dh = make_uint4(h[0], h[1], h[2], h[3]);
    *dl = make_uint4(l[0], l[1], l[2], l[3]);
}

// ------------------------- K1: HMMA projection + fused Esum ------------------
// EK|EV (bf16) = E @ [Wk|Wv], hi/lo 3-pass. CTA: M=128 x N=256, K=128.
#define A_HI 0
#define A_LO 32768
#define B_HI 65536
#define B_LO 131072
#define PROJ_SMEM 196608

__global__ void __launch_bounds__(512, 1)
k_proj_mma(const float* __restrict__ E, int V) {
    extern __shared__ char smem[];
    const uint32_t sb = smem_to_u32(smem);
    const int t    = threadIdx.x;
    const int w    = t >> 5;
    const int lane = t & 31;
    const int v0   = blockIdx.x * 128;

    // ---- stage A + row-sum (each E row staged exactly once grid-wide)
    #pragma unroll
    for (int i = 0; i < 4; i++) {
        int u   = t + 512 * i;           // 2048 units of 8 k
        int row = u >> 4;
        int kc  = u & 15;
        int gr  = v0 + row;
        int grc = (gr < V) ? gr : 0;
        const float4* src = reinterpret_cast<const float4*>(E + (size_t)grc * DIM + kc * 8);
        float4 f0 = src[0], f1 = src[1];
        uint32_t h0, h1, h2, h3, l0, l1, l2, l3;
        split2(f0.x, f0.y, h0, l0); split2(f0.z, f0.w, h1, l1);
        split2(f1.x, f1.y, h2, l2); split2(f1.z, f1.w, h3, l3);
        uint32_t off = (uint32_t)row * 256 + (uint32_t)((kc ^ (row & 7)) << 4);
        *reinterpret_cast<uint4*>(smem + A_HI + off) = make_uint4(h0, h1, h2, h3);
        *reinterpret_cast<uint4*>(smem + A_LO + off) = make_uint4(l0, l1, l2, l3);
        // fused Esum: 16 lanes share a row; segmented reduce
        float s8 = ((f0.x + f0.y) + (f0.z + f0.w)) + ((f1.x + f1.y) + (f1.z + f1.w));
        s8 += __shfl_xor_sync(0xffffffffu, s8, 8);
        s8 += __shfl_xor_sync(0xffffffffu, s8, 4);
        s8 += __shfl_xor_sync(0xffffffffu, s8, 2);
        s8 += __shfl_xor_sync(0xffffffffu, s8, 1);
        if ((t & 15) == 0 && gr < V) g_Esum[gr] = s8;
    }
    // ---- stage B: straight copy of prebuilt swizzled images (L2-resident)
    {
        uint4* dh = reinterpret_cast<uint4*>(smem + B_HI);
        uint4* dl = reinterpret_cast<uint4*>(smem + B_LO);
        #pragma unroll
        for (int i = 0; i < 8; i++) {
            int idx = t + 512 * i;
            dh[idx] = g_WThi[idx];
            dl[idx] = g_WTlo[idx];
        }
    }
    __syncthreads();

    const int mg = w & 3;
    const int ng = w >> 2;

    float acc[2][8][4];
    #pragma unroll
    for (int mt = 0; mt < 2; mt++)
        #pragma unroll
        for (int nt = 0; nt < 8; nt++)
            #pragma unroll
            for (int j = 0; j < 4; j++) acc[mt][nt][j] = 0.f;

    const int aRow  = mg * 32 + ((lane >> 3) & 1) * 8 + (lane & 7);
    const int aKsel = (lane >> 4);
    const int bN    = ng * 64 + ((lane >> 4) & 1) * 8 + (lane & 7);
    const int bKsel = (lane >> 3) & 1;

    #pragma unroll
    for (int p = 0; p < 3; p++) {
        const uint32_t abase = sb + (p == 2 ? A_LO : A_HI);
        const uint32_t bbase = sb + (p == 1 ? B_LO : B_HI);
        #pragma unroll
        for (int ks = 0; ks < 8; ks++) {
            uint32_t a[2][4];
            #pragma unroll
            for (int mt = 0; mt < 2; mt++) {
                int row = aRow + mt * 16;
                int kc  = ks * 2 + aKsel;
                ldsm_x4(abase + row * 256 + (((kc ^ (row & 7)) << 4)), a[mt]);
            }
            uint32_t b[4][4];
            #pragma unroll
            for (int bt = 0; bt < 4; bt++) {
                int n  = bN + bt * 16;
                int kc = ks * 2 + bKsel;
                ldsm_x4(bbase + n * 256 + (((kc ^ (n & 7)) << 4)), b[bt]);
            }
            #pragma unroll
            for (int mt = 0; mt < 2; mt++)
                #pragma unroll
                for (int nt = 0; nt < 8; nt++)
                    mma_bf16(acc[mt][nt], a[mt], b[nt >> 1][(nt & 1) * 2], b[nt >> 1][(nt & 1) * 2 + 1]);
        }
    }

    // ---- epilogue: bf16 EK/EV
    #pragma unroll
    for (int mt = 0; mt < 2; mt++) {
        int row = v0 + mg * 32 + mt * 16 + (lane >> 2);
        if (row >= V) continue;
        #pragma unroll
        for (int nt = 0; nt < 8; nt++) {
            int col = ng * 64 + nt * 8 + (lane & 3) * 2;
            __nv_bfloat16* base = (col < 128) ? (g_EKbf + (size_t)row * DIM + col)
                                              : (g_EVbf + (size_t)row * DIM + (col - 128));
            *reinterpret_cast<uint32_t*>(base)           = pack_bf2(acc[mt][nt][0], acc[mt][nt][1]);
            *reinterpret_cast<uint32_t*>(base + 8 * DIM) = pack_bf2(acc[mt][nt][2], acc[mt][nt][3]);
        }
    }
}

// ------------------------- K2: HMMA gemm (N=128) -----------------------------
// mode 0: A = E[queries[m]],  B = Wq image, bias bq, dst g_Q
// mode 1: A = g_res[m],       B = Wf image, bias bf, dst out
#define G_A_HI 0
#define G_A_LO 32768
#define G_B_HI 65536
#define G_B_LO 98304
#define GEMM_SMEM 131072

__global__ void __launch_bounds__(512, 1)
k_gemm128(const float* __restrict__ E, const int* __restrict__ queries,
          const float* __restrict__ bias, float* __restrict__ outp,
          int M, int mode) {
    extern __shared__ char smem[];
    const uint32_t sb = smem_to_u32(smem);
    const int t    = threadIdx.x;
    const int w    = t >> 5;
    const int lane = t & 31;
    const int m0   = blockIdx.x * 128;

    // stage A
    #pragma unroll
    for (int i = 0; i < 4; i++) {
        int u   = t + 512 * i;
        int row = u >> 4;
        int kc  = u & 15;
        int m   = m0 + row;
        const float* srcrow;
        if (mode == 0) {
            int mm = (m < M) ? m : 0;
            srcrow = E + (size_t)queries[mm] * DIM;
        } else {
            srcrow = g_res + (size_t)((m < M) ? m : 0) * DIM;
        }
        const float4* src = reinterpret_cast<const float4*>(srcrow + kc * 8);
        float4 f0 = src[0], f1 = src[1];
        uint32_t h0, h1, h2, h3, l0, l1, l2, l3;
        split2(f0.x, f0.y, h0, l0); split2(f0.z, f0.w, h1, l1);
        split2(f1.x, f1.y, h2, l2); split2(f1.z, f1.w, h3, l3);
        uint32_t off = (uint32_t)row * 256 + (uint32_t)((kc ^ (row & 7)) << 4);
        *reinterpret_cast<uint4*>(smem + G_A_HI + off) = make_uint4(h0, h1, h2, h3);
        *reinterpret_cast<uint4*>(smem + G_A_LO + off) = make_uint4(l0, l1, l2, l3);
    }
    // stage B (32KB hi + 32KB lo)
    {
        uint4* dh = reinterpret_cast<uint4*>(smem + G_B_HI);
        uint4* dl = reinterpret_cast<uint4*>(smem + G_B_LO);
        const uint4* sh = (mode == 0) ? g_WQhi : g_WFhi;
        const uint4* sl = (mode == 0) ? g_WQlo : g_WFlo;
        #pragma unroll
        for (int i = 0; i < 4; i++) {
            int idx = t + 512 * i;
            dh[idx] = sh[idx];
            dl[idx] = sl[idx];
        }
    }
    __syncthreads();

    const int mg = w & 3;
    const int ng = w >> 2;

    float acc[2][4][4];
    #pragma unroll
    for (int mt = 0; mt < 2; mt++)
        #pragma unroll
        for (int nt = 0; nt < 4; nt++)
            #pragma unroll
            for (int j = 0; j < 4; j++) acc[mt][nt][j] = 0.f;

    const int aRow  = mg * 32 + ((lane >> 3) & 1) * 8 + (lane & 7);
    const int aKsel = (lane >> 4);
    const int bN    = ng * 32 + ((lane >> 4) & 1) * 8 + (lane & 7);
    const int bKsel = (lane >> 3) & 1;

    #pragma unroll
    for (int p = 0; p < 3; p++) {
        const uint32_t abase = sb + (p == 2 ? G_A_LO : G_A_HI);
        const uint32_t bbase = sb + (p == 1 ? G_B_LO : G_B_HI);
        #pragma unroll
        for (int ks = 0; ks < 8; ks++) {
            uint32_t a[2][4];
            #pragma unroll
            for (int mt = 0; mt < 2; mt++) {
                int row = aRow + mt * 16;
                int kc  = ks * 2 + aKsel;
                ldsm_x4(abase + row * 256 + (((kc ^ (row & 7)) << 4)), a[mt]);
            }
            uint32_t b[2][4];
            #pragma unroll
            for (int bt = 0; bt < 2; bt++) {
                int n  = bN + bt * 16;
                int kc = ks * 2 + bKsel;
                ldsm_x4(bbase + n * 256 + (((kc ^ (n & 7)) << 4)), b[bt]);
            }
            #pragma unroll
            for (int mt = 0; mt < 2; mt++)
                #pragma unroll
                for (int nt = 0; nt < 4; nt++)
                    mma_bf16(acc[mt][nt], a[mt], b[nt >> 1][(nt & 1) * 2], b[nt >> 1][(nt & 1) * 2 + 1]);
        }
    }

    float* dst = (mode == 0) ? g_Q : outp;
    #pragma unroll
    for (int mt = 0; mt < 2; mt++) {
        int row = m0 + mg * 32 + mt * 16 + (lane >> 2);
        #pragma unroll
        for (int nt = 0; nt < 4; nt++) {
            int col = ng * 32 + nt * 8 + (lane & 3) * 2;
            float b0 = bias[col], b1 = bias[col + 1];
            if (row < M) {
                *reinterpret_cast<float2*>(dst + (size_t)row * DIM + col) =
                    make_float2(acc[mt][nt][0] + b0, acc[mt][nt][1] + b1);
                if (row + 8 < M)
                    *reinterpret_cast<float2*>(dst + (size_t)(row + 8) * DIM + col) =
                        make_float2(acc[mt][nt][2] + b0, acc[mt][nt][3] + b1);
            }
        }
    }
}

// ------------------------- K3: attention core (bf16 tables) ------------------
__global__ void __launch_bounds__(128) k_attn(const int* __restrict__ queries,
                                              const int* __restrict__ keys,
                                              const float* __restrict__ E,
                                              const float* __restrict__ bk,
                                              const float* __restrict__ bv,
                                              int L2) {
    const int bl   = blockIdx.x;
    const int t    = threadIdx.x;
    const int w    = t >> 5;
    const int lane = t & 31;

    __shared__ int   s_kid[64];
    __shared__ float s_sc[NHEAD][64];
    __shared__ float s_attn[NHEAD][64];

    if (t < L2) s_kid[t] = keys[bl * L2 + t];

    const float4 q4  = reinterpret_cast<const float4*>(g_Q + (size_t)bl * DIM)[lane];
    const float4 kb4 = reinterpret_cast<const float4*>(bk)[lane];
    const float corr = q4.x * kb4.x + q4.y * kb4.y + q4.z * kb4.z + q4.w * kb4.w;
    __syncthreads();

    const float RS = 0.17677669529663687f;   // 1/sqrt(32)

    for (int k = w; k < L2; k += 2 * NHEAD) {
        int kid0 = s_kid[k];
        int k1   = k + NHEAD;
        int kid1 = (k1 < L2) ? s_kid[k1] : kid0;
        uint2 ra = reinterpret_cast<const uint2*>(g_EKbf + (size_t)kid0 * DIM)[lane];
        uint2 rb = reinterpret_cast<const uint2*>(g_EKbf + (size_t)kid1 * DIM)[lane];
        float2 a0 = __bfloat1622float2(*reinterpret_cast<__nv_bfloat162*>(&ra.x));
        float2 a1 = __bfloat1622float2(*reinterpret_cast<__nv_bfloat162*>(&ra.y));
        float2 b0 = __bfloat1622float2(*reinterpret_cast<__nv_bfloat162*>(&rb.x));
        float2 b1 = __bfloat1622float2(*reinterpret_cast<__nv_bfloat162*>(&rb.y));
        float p0 = corr, p1 = corr;
        p0 = fmaf(q4.x, a0.x, p0); p1 = fmaf(q4.x, b0.x, p1);
        p0 = fmaf(q4.y, a0.y, p0); p1 = fmaf(q4.y, b0.y, p1);
        p0 = fmaf(q4.z, a1.x, p0); p1 = fmaf(q4.z, b1.x, p1);
        p0 = fmaf(q4.w, a1.y, p0); p1 = fmaf(q4.w, b1.y, p1);
        #pragma unroll
        for (int o = 4; o; o >>= 1) {
            p0 += __shfl_xor_sync(0xffffffffu, p0, o);
            p1 += __shfl_xor_sync(0xffffffffu, p1, o);
        }
        if ((lane & 7) == 0) {
            float sc0 = p0 * RS;
            if (g_Esum[kid0] == 0.0f) sc0 = NEGF;
            s_sc[lane >> 3][k] = sc0;
            if (k1 < L2) {
                float sc1 = p1 * RS;
                if (g_Esum[kid1] == 0.0f) sc1 = NEGF;
                s_sc[lane >> 3][k1] = sc1;
            }
        }
    }
    __syncthreads();

    {
        float s0 = (lane      < L2) ? s_sc[w][lane]      : -3.4e38f;
        float s1 = (lane + 32 < L2) ? s_sc[w][lane + 32] : -3.4e38f;
        float m = fmaxf(s0, s1);
        #pragma unroll
        for (int o = 16; o; o >>= 1) m = fmaxf(m, __shfl_xor_sync(0xffffffffu, m, o));
        float e0 = (lane      < L2) ? expf(s0 - m) : 0.f;
        float e1 = (lane + 32 < L2) ? expf(s1 - m) : 0.f;
        float s = e0 + e1;
        #pragma unroll
        for (int o = 16; o; o >>= 1) s += __shfl_xor_sync(0xffffffffu, s, o);
        float inv = 1.0f / s;
        if (lane      < L2) s_attn[w][lane]      = e0 * inv;
        if (lane + 32 < L2) s_attn[w][lane + 32] = e1 * inv;
    }
    __syncthreads();

    float o0 = bv[t], o1 = 0.f, o2 = 0.f, o3 = 0.f, o4 = 0.f;
    int k = 0;
    for (; k + 5 <= L2; k += 5) {
        int i0 = s_kid[k],     i1 = s_kid[k + 1], i2 = s_kid[k + 2];
        int i3 = s_kid[k + 3], i4 = s_kid[k + 4];
        float v0 = __bfloat162float(g_EVbf[(size_t)i0 * DIM + t]);
        float v1 = __bfloat162float(g_EVbf[(size_t)i1 * DIM + t]);
        float v2 = __bfloat162float(g_EVbf[(size_t)i2 * DIM + t]);
        float v3 = __bfloat162float(g_EVbf[(size_t)i3 * DIM + t]);
        float v4 = __bfloat162float(g_EVbf[(size_t)i4 * DIM + t]);
        o0 = fmaf(s_attn[w][k],     v0, o0);
        o1 = fmaf(s_attn[w][k + 1], v1, o1);
        o2 = fmaf(s_attn[w][k + 2], v2, o2);
        o3 = fmaf(s_attn[w][k + 3], v3, o3);
        o4 = fmaf(s_attn[w][k + 4], v4, o4);
    }
    for (; k < L2; k++)
        o0 = fmaf(s_attn[w][k], __bfloat162float(g_EVbf[(size_t)s_kid[k] * DIM + t]), o0);
    float o = ((o0 + o1) + (o2 + o3)) + o4;

    const int qid = queries[bl];
    o += E[(size_t)qid * DIM + t];
    g_res[(size_t)bl * DIM + t] = o;
}

// ------------------------- launch --------------------------------------------
extern "C" void kernel_launch(void* const* d_in, const int* in_sizes, int n_in,
                              void* d_out, int out_size) {
    const int*   queries = (const int*)d_in[0];
    const int*   keys    = (const int*)d_in[1];
    const float* E       = (const float*)d_in[2];
    const float* Wq      = (const float*)d_in[3];
    const float* bq      = (const float*)d_in[4];
    const float* Wk      = (const float*)d_in[5];
    const float* bk      = (const float*)d_in[6];
    const float* Wv      = (const float*)d_in[7];
    const float* bv      = (const float*)d_in[8];
    const float* Wf      = (const float*)d_in[9];
    const float* bf      = (const float*)d_in[10];
    float* out = (float*)d_out;

    const int V  = in_sizes[2] / DIM;
    const int M  = in_sizes[0];
    const int L2 = in_sizes[1] / M;

    cudaFuncSetAttribute(k_proj_mma, cudaFuncAttributeMaxDynamicSharedMemorySize, PROJ_SMEM);
    cudaFuncSetAttribute(k_gemm128, cudaFuncAttributeMaxDynamicSharedMemorySize, GEMM_SMEM);

    k_wprep<<<32, 256>>>(Wk, Wv, Wq, Wf);
    k_proj_mma<<<(V + 127) / 128, 512, PROJ_SMEM>>>(E, V);
    k_gemm128<<<(M + 127) / 128, 512, GEMM_SMEM>>>(E, queries, bq, out, M, 0);
    k_attn<<<M, 128>>>(queries, keys, E, bk, bv, L2);
    k_gemm128<<<(M + 127) / 128, 512, GEMM_SMEM>>>(E, queries, bf, out, M, 1);
}

// round 6
// speedup vs baseline: 3.7942x; 1.6881x over previous
#include <cuda_runtime.h>
#include <cuda_bf16.h>
#include <cstdint>

#define VOCAB_MAX 100000
#define BL_MAX    12800
#define DIM       128
#define NHEAD     4
#define NEGF      (-4294967296.0f)

// ------------------------- scratch (device globals) -------------------------
__device__ __nv_bfloat16 g_EKbf[VOCAB_MAX * DIM];   // E @ Wk  (bf16)
__device__ __nv_bfloat16 g_EVbf[VOCAB_MAX * DIM];   // E @ Wv  (bf16)
__device__ float g_Esum[VOCAB_MAX];
__device__ float g_Q[BL_MAX * DIM];
__device__ float g_res[BL_MAX * DIM];
// swizzled W^T images (n-major, k contiguous, kc ^= n&7)
__device__ uint4 g_WT16[4096];   // [Wk|Wv] fp16: [n=256][kc=16]
__device__ uint4 g_WQ16[2048];   // Wq fp16:      [n=128][kc=16]
__device__ uint4 g_WFhi[2048];   // Wf bf16 hi
__device__ uint4 g_WFlo[2048];   // Wf bf16 lo

// ------------------------- helpers ------------------------------------------
__device__ __forceinline__ uint32_t smem_to_u32(const void* p) {
    uint32_t a;
    asm("{ .reg .u64 t; cvta.to.shared.u64 t, %1; cvt.u32.u64 %0, t; }" : "=r"(a) : "l"(p));
    return a;
}
__device__ __forceinline__ uint32_t pack_bf2(float lo, float hi) {
    uint32_t r; asm("cvt.rn.bf16x2.f32 %0, %1, %2;" : "=r"(r) : "f"(hi), "f"(lo)); return r;
}
__device__ __forceinline__ uint32_t pack_h2(float lo, float hi) {
    uint32_t r; asm("cvt.rn.f16x2.f32 %0, %1, %2;" : "=r"(r) : "f"(hi), "f"(lo)); return r;
}
__device__ __forceinline__ void ldsm_x4(uint32_t addr, uint32_t* r) {
    asm volatile("ldmatrix.sync.aligned.m8n8.x4.shared.b16 {%0,%1,%2,%3}, [%4];"
                 : "=r"(r[0]), "=r"(r[1]), "=r"(r[2]), "=r"(r[3]) : "r"(addr));
}
__device__ __forceinline__ void mma_bf16(float* c, const uint32_t* a, uint32_t b0, uint32_t b1) {
    asm volatile("mma.sync.aligned.m16n8k16.row.col.f32.bf16.bf16.f32 "
                 "{%0,%1,%2,%3}, {%4,%5,%6,%7}, {%8,%9}, {%0,%1,%2,%3};"
                 : "+f"(c[0]), "+f"(c[1]), "+f"(c[2]), "+f"(c[3])
                 : "r"(a[0]), "r"(a[1]), "r"(a[2]), "r"(a[3]), "r"(b0), "r"(b1));
}
__device__ __forceinline__ void mma_f16(float* c, const uint32_t* a, uint32_t b0, uint32_t b1) {
    asm volatile("mma.sync.aligned.m16n8k16.row.col.f32.f16.f16.f32 "
                 "{%0,%1,%2,%3}, {%4,%5,%6,%7}, {%8,%9}, {%0,%1,%2,%3};"
                 : "+f"(c[0]), "+f"(c[1]), "+f"(c[2]), "+f"(c[3])
                 : "r"(a[0]), "r"(a[1]), "r"(a[2]), "r"(a[3]), "r"(b0), "r"(b1));
}
__device__ __forceinline__ void split2(float x, float y, uint32_t& h, uint32_t& l) {
    h = pack_bf2(x, y);
    l = pack_bf2(x - __uint_as_float(h << 16), y - __uint_as_float(h & 0xffff0000u));
}

// ------------------------- K0: prep all W^T images ---------------------------
__global__ void k_wprep(const float* __restrict__ Wk, const float* __restrict__ Wv,
                        const float* __restrict__ Wq, const float* __restrict__ Wf) {
    int u = blockIdx.x * blockDim.x + threadIdx.x;    // 8192 units
    const float* src;
    int n, kc, kind;          // kind: 0=fp16 WT, 1=fp16 WQ, 2=bf16 WF
    uint4 *dst16 = nullptr, *dh = nullptr, *dl = nullptr;
    if (u < 4096) {
        n = u & 255; kc = u >> 8; kind = 0;
        src = (n < 128) ? (Wk + n) : (Wv + (n - 128));
        dst16 = g_WT16 + n * 16 + (kc ^ (n & 7));
    } else if (u < 6144) {
        int u2 = u - 4096; n = u2 & 127; kc = u2 >> 7; kind = 1;
        src = Wq + n;
        dst16 = g_WQ16 + n * 16 + (kc ^ (n & 7));
    } else {
        int u2 = u - 6144; n = u2 & 127; kc = u2 >> 7; kind = 2;
        src = Wf + n;
        int idx = n * 16 + (kc ^ (n & 7));
        dh = g_WFhi + idx; dl = g_WFlo + idx;
    }
    float f[8];
    #pragma unroll
    for (int i = 0; i < 8; i++) f[i] = src[(size_t)(kc * 8 + i) * DIM];
    if (kind < 2) {
        uint32_t h[4];
        #pragma unroll
        for (int i = 0; i < 4; i++) h[i] = pack_h2(f[2 * i], f[2 * i + 1]);
        *dst16 = make_uint4(h[0], h[1], h[2], h[3]);
    } else {
        uint32_t h[4], l[4];
        #pragma unroll
        for (int i = 0; i < 4; i++) split2(f[2 * i], f[2 * i + 1], h[i], l[i]);
        *dh = make_uint4(h[0], h[1], h[2], h[3]);
        *dl = make_uint4(l[0], l[1], l[2], l[3]);
    }
}

// ------------------------- K1: fp16 HMMA projection + fused Esum -------------
// EK|EV (bf16) = E @ [Wk|Wv], single fp16 pass. CTA: M=128 x N=256, K=128.
#define A_16 0
#define B_16 32768
#define PROJ_SMEM 98304

__global__ void __launch_bounds__(512)
k_proj_mma(const float* __restrict__ E, int V) {
    extern __shared__ char smem[];
    const uint32_t sb = smem_to_u32(smem);
    const int t    = threadIdx.x;
    const int w    = t >> 5;
    const int lane = t & 31;
    const int v0   = blockIdx.x * 128;

    // ---- stage A (fp16) + fused row-sum
    #pragma unroll
    for (int i = 0; i < 4; i++) {
        int u   = t + 512 * i;           // 2048 units of 8 k
        int row = u >> 4;
        int kc  = u & 15;
        int gr  = v0 + row;
        int grc = (gr < V) ? gr : 0;
        const float4* src = reinterpret_cast<const float4*>(E + (size_t)grc * DIM + kc * 8);
        float4 f0 = src[0], f1 = src[1];
        uint32_t h0 = pack_h2(f0.x, f0.y), h1 = pack_h2(f0.z, f0.w);
        uint32_t h2 = pack_h2(f1.x, f1.y), h3 = pack_h2(f1.z, f1.w);
        uint32_t off = (uint32_t)row * 256 + (uint32_t)((kc ^ (row & 7)) << 4);
        *reinterpret_cast<uint4*>(smem + A_16 + off) = make_uint4(h0, h1, h2, h3);
        float s8 = ((f0.x + f0.y) + (f0.z + f0.w)) + ((f1.x + f1.y) + (f1.z + f1.w));
        s8 += __shfl_xor_sync(0xffffffffu, s8, 8);
        s8 += __shfl_xor_sync(0xffffffffu, s8, 4);
        s8 += __shfl_xor_sync(0xffffffffu, s8, 2);
        s8 += __shfl_xor_sync(0xffffffffu, s8, 1);
        if ((t & 15) == 0 && gr < V) g_Esum[gr] = s8;
    }
    // ---- stage B: copy prebuilt fp16 image (64KB, L2-resident)
    {
        uint4* d = reinterpret_cast<uint4*>(smem + B_16);
        #pragma unroll
        for (int i = 0; i < 8; i++) {
            int idx = t + 512 * i;
            d[idx] = g_WT16[idx];
        }
    }
    __syncthreads();

    const int mg = w & 3;
    const int ng = w >> 2;

    float acc[2][8][4];
    #pragma unroll
    for (int mt = 0; mt < 2; mt++)
        #pragma unroll
        for (int nt = 0; nt < 8; nt++)
            #pragma unroll
            for (int j = 0; j < 4; j++) acc[mt][nt][j] = 0.f;

    const int aRow  = mg * 32 + ((lane >> 3) & 1) * 8 + (lane & 7);
    const int aKsel = (lane >> 4);
    const int bN    = ng * 64 + ((lane >> 4) & 1) * 8 + (lane & 7);
    const int bKsel = (lane >> 3) & 1;

    #pragma unroll
    for (int ks = 0; ks < 8; ks++) {
        uint32_t a[2][4];
        #pragma unroll
        for (int mt = 0; mt < 2; mt++) {
            int row = aRow + mt * 16;
            int kc  = ks * 2 + aKsel;
            ldsm_x4(sb + A_16 + row * 256 + (((kc ^ (row & 7)) << 4)), a[mt]);
        }
        uint32_t b[4][4];
        #pragma unroll
        for (int bt = 0; bt < 4; bt++) {
            int n  = bN + bt * 16;
            int kc = ks * 2 + bKsel;
            ldsm_x4(sb + B_16 + n * 256 + (((kc ^ (n & 7)) << 4)), b[bt]);
        }
        #pragma unroll
        for (int mt = 0; mt < 2; mt++)
            #pragma unroll
            for (int nt = 0; nt < 8; nt++)
                mma_f16(acc[mt][nt], a[mt], b[nt >> 1][(nt & 1) * 2], b[nt >> 1][(nt & 1) * 2 + 1]);
    }

    // ---- epilogue: bf16 EK/EV
    #pragma unroll
    for (int mt = 0; mt < 2; mt++) {
        int row = v0 + mg * 32 + mt * 16 + (lane >> 2);
        if (row >= V) continue;
        #pragma unroll
        for (int nt = 0; nt < 8; nt++) {
            int col = ng * 64 + nt * 8 + (lane & 3) * 2;
            __nv_bfloat16* base = (col < 128) ? (g_EKbf + (size_t)row * DIM + col)
                                              : (g_EVbf + (size_t)row * DIM + (col - 128));
            *reinterpret_cast<uint32_t*>(base)           = pack_bf2(acc[mt][nt][0], acc[mt][nt][1]);
            *reinterpret_cast<uint32_t*>(base + 8 * DIM) = pack_bf2(acc[mt][nt][2], acc[mt][nt][3]);
        }
    }
}

// ------------------------- K2a: Q gemm (fp16 single pass, N=128) -------------
#define Q_A 0
#define Q_B 32768
#define GEMMQ_SMEM 65536

__global__ void __launch_bounds__(512)
k_gemm_q(const float* __restrict__ E, const int* __restrict__ queries,
         const float* __restrict__ bq, int M) {
    extern __shared__ char smem[];
    const uint32_t sb = smem_to_u32(smem);
    const int t    = threadIdx.x;
    const int w    = t >> 5;
    const int lane = t & 31;
    const int m0   = blockIdx.x * 128;

    #pragma unroll
    for (int i = 0; i < 4; i++) {
        int u   = t + 512 * i;
        int row = u >> 4;
        int kc  = u & 15;
        int m   = m0 + row;
        int mm  = (m < M) ? m : 0;
        const float4* src = reinterpret_cast<const float4*>(E + (size_t)queries[mm] * DIM + kc * 8);
        float4 f0 = src[0], f1 = src[1];
        uint32_t h0 = pack_h2(f0.x, f0.y), h1 = pack_h2(f0.z, f0.w);
        uint32_t h2 = pack_h2(f1.x, f1.y), h3 = pack_h2(f1.z, f1.w);
        uint32_t off = (uint32_t)row * 256 + (uint32_t)((kc ^ (row & 7)) << 4);
        *reinterpret_cast<uint4*>(smem + Q_A + off) = make_uint4(h0, h1, h2, h3);
    }
    {
        uint4* d = reinterpret_cast<uint4*>(smem + Q_B);
        #pragma unroll
        for (int i = 0; i < 4; i++) {
            int idx = t + 512 * i;
            d[idx] = g_WQ16[idx];
        }
    }
    __syncthreads();

    const int mg = w & 3;
    const int ng = w >> 2;

    float acc[2][4][4];
    #pragma unroll
    for (int mt = 0; mt < 2; mt++)
        #pragma unroll
        for (int nt = 0; nt < 4; nt++)
            #pragma unroll
            for (int j = 0; j < 4; j++) acc[mt][nt][j] = 0.f;

    const int aRow  = mg * 32 + ((lane >> 3) & 1) * 8 + (lane & 7);
    const int aKsel = (lane >> 4);
    const int bN    = ng * 32 + ((lane >> 4) & 1) * 8 + (lane & 7);
    const int bKsel = (lane >> 3) & 1;

    #pragma unroll
    for (int ks = 0; ks < 8; ks++) {
        uint32_t a[2][4];
        #pragma unroll
        for (int mt = 0; mt < 2; mt++) {
            int row = aRow + mt * 16;
            int kc  = ks * 2 + aKsel;
            ldsm_x4(sb + Q_A + row * 256 + (((kc ^ (row & 7)) << 4)), a[mt]);
        }
        uint32_t b[2][4];
        #pragma unroll
        for (int bt = 0; bt < 2; bt++) {
            int n  = bN + bt * 16;
            int kc = ks * 2 + bKsel;
            ldsm_x4(sb + Q_B + n * 256 + (((kc ^ (n & 7)) << 4)), b[bt]);
        }
        #pragma unroll
        for (int mt = 0; mt < 2; mt++)
            #pragma unroll
            for (int nt = 0; nt < 4; nt++)
                mma_f16(acc[mt][nt], a[mt], b[nt >> 1][(nt & 1) * 2], b[nt >> 1][(nt & 1) * 2 + 1]);
    }

    #pragma unroll
    for (int mt = 0; mt < 2; mt++) {
        int row = m0 + mg * 32 + mt * 16 + (lane >> 2);
        #pragma unroll
        for (int nt = 0; nt < 4; nt++) {
            int col = ng * 32 + nt * 8 + (lane & 3) * 2;
            float b0 = bq[col], b1 = bq[col + 1];
            if (row < M) {
                *reinterpret_cast<float2*>(g_Q + (size_t)row * DIM + col) =
                    make_float2(acc[mt][nt][0] + b0, acc[mt][nt][1] + b1);
                if (row + 8 < M)
                    *reinterpret_cast<float2*>(g_Q + (size_t)(row + 8) * DIM + col) =
                        make_float2(acc[mt][nt][2] + b0, acc[mt][nt][3] + b1);
            }
        }
    }
}

// ------------------------- K2b: final gemm (bf16 3-pass, N=128) --------------
#define F_A_HI 0
#define F_A_LO 32768
#define F_B_HI 65536
#define F_B_LO 98304
#define GEMMF_SMEM 131072

__global__ void __launch_bounds__(512)
k_gemm_f(const float* __restrict__ bf, float* __restrict__ outp, int M) {
    extern __shared__ char smem[];
    const uint32_t sb = smem_to_u32(smem);
    const int t    = threadIdx.x;
    const int w    = t >> 5;
    const int lane = t & 31;
    const int m0   = blockIdx.x * 128;

    #pragma unroll
    for (int i = 0; i < 4; i++) {
        int u   = t + 512 * i;
        int row = u >> 4;
        int kc  = u & 15;
        int m   = m0 + row;
        const float4* src = reinterpret_cast<const float4*>(
            g_res + (size_t)((m < M) ? m : 0) * DIM + kc * 8);
        float4 f0 = src[0], f1 = src[1];
        uint32_t h0, h1, h2, h3, l0, l1, l2, l3;
        split2(f0.x, f0.y, h0, l0); split2(f0.z, f0.w, h1, l1);
        split2(f1.x, f1.y, h2, l2); split2(f1.z, f1.w, h3, l3);
        uint32_t off = (uint32_t)row * 256 + (uint32_t)((kc ^ (row & 7)) << 4);
        *reinterpret_cast<uint4*>(smem + F_A_HI + off) = make_uint4(h0, h1, h2, h3);
        *reinterpret_cast<uint4*>(smem + F_A_LO + off) = make_uint4(l0, l1, l2, l3);
    }
    {
        uint4* dh = reinterpret_cast<uint4*>(smem + F_B_HI);
        uint4* dl = reinterpret_cast<uint4*>(smem + F_B_LO);
        #pragma unroll
        for (int i = 0; i < 4; i++) {
            int idx = t + 512 * i;
            dh[idx] = g_WFhi[idx];
            dl[idx] = g_WFlo[idx];
        }
    }
    __syncthreads();

    const int mg = w & 3;
    const int ng = w >> 2;

    float acc[2][4][4];
    #pragma unroll
    for (int mt = 0; mt < 2; mt++)
        #pragma unroll
        for (int nt = 0; nt < 4; nt++)
            #pragma unroll
            for (int j = 0; j < 4; j++) acc[mt][nt][j] = 0.f;

    const int aRow  = mg * 32 + ((lane >> 3) & 1) * 8 + (lane & 7);
    const int aKsel = (lane >> 4);
    const int bN    = ng * 32 + ((lane >> 4) & 1) * 8 + (lane & 7);
    const int bKsel = (lane >> 3) & 1;

    #pragma unroll
    for (int p = 0; p < 3; p++) {
        const uint32_t abase = sb + (p == 2 ? F_A_LO : F_A_HI);
        const uint32_t bbase = sb + (p == 1 ? F_B_LO : F_B_HI);
        #pragma unroll
        for (int ks = 0; ks < 8; ks++) {
            uint32_t a[2][4];
            #pragma unroll
            for (int mt = 0; mt < 2; mt++) {
                int row = aRow + mt * 16;
                int kc  = ks * 2 + aKsel;
                ldsm_x4(abase + row * 256 + (((kc ^ (row & 7)) << 4)), a[mt]);
            }
            uint32_t b[2][4];
            #pragma unroll
            for (int bt = 0; bt < 2; bt++) {
                int n  = bN + bt * 16;
                int kc = ks * 2 + bKsel;
                ldsm_x4(bbase + n * 256 + (((kc ^ (n & 7)) << 4)), b[bt]);
            }
            #pragma unroll
            for (int mt = 0; mt < 2; mt++)
                #pragma unroll
                for (int nt = 0; nt < 4; nt++)
                    mma_bf16(acc[mt][nt], a[mt], b[nt >> 1][(nt & 1) * 2], b[nt >> 1][(nt & 1) * 2 + 1]);
        }
    }

    #pragma unroll
    for (int mt = 0; mt < 2; mt++) {
        int row = m0 + mg * 32 + mt * 16 + (lane >> 2);
        #pragma unroll
        for (int nt = 0; nt < 4; nt++) {
            int col = ng * 32 + nt * 8 + (lane & 3) * 2;
            float b0 = bf[col], b1 = bf[col + 1];
            if (row < M) {
                *reinterpret_cast<float2*>(outp + (size_t)row * DIM + col) =
                    make_float2(acc[mt][nt][0] + b0, acc[mt][nt][1] + b1);
                if (row + 8 < M)
                    *reinterpret_cast<float2*>(outp + (size_t)(row + 8) * DIM + col) =
                        make_float2(acc[mt][nt][2] + b0, acc[mt][nt][3] + b1);
            }
        }
    }
}

// ------------------------- K3: attention core (bf16 tables) ------------------
__global__ void __launch_bounds__(128) k_attn(const int* __restrict__ queries,
                                              const int* __restrict__ keys,
                                              const float* __restrict__ E,
                                              const float* __restrict__ bk,
                                              const float* __restrict__ bv,
                                              int L2) {
    const int bl   = blockIdx.x;
    const int t    = threadIdx.x;
    const int w    = t >> 5;
    const int lane = t & 31;

    __shared__ int      s_kid[64];
    __shared__ uint32_t s_off[64];         // byte offset = kid*256
    __shared__ float    s_sc[NHEAD][64];
    __shared__ float    s_attn[NHEAD][64];
    __shared__ float    s_part[4][128];    // phase-3 partials

    if (t < L2) {
        int kid = keys[bl * L2 + t];
        s_kid[t] = kid;
        s_off[t] = (uint32_t)kid << 8;     // DIM * 2B
    }

    const float4 q4  = reinterpret_cast<const float4*>(g_Q + (size_t)bl * DIM)[lane];
    const float4 kb4 = reinterpret_cast<const float4*>(bk)[lane];
    const float corr = q4.x * kb4.x + q4.y * kb4.y + q4.z * kb4.z + q4.w * kb4.w;
    __syncthreads();

    const float RS = 0.17677669529663687f;   // 1/sqrt(32)
    const char* ekb = reinterpret_cast<const char*>(g_EKbf);
    const char* evb = reinterpret_cast<const char*>(g_EVbf);

    // phase 1: scores, 2 keys in flight per warp
    for (int k = w; k < L2; k += 2 * NHEAD) {
        int k1 = k + NHEAD;
        uint32_t off0 = s_off[k];
        uint32_t off1 = (k1 < L2) ? s_off[k1] : off0;
        uint2 ra = *reinterpret_cast<const uint2*>(ekb + off0 + lane * 8);
        uint2 rb = *reinterpret_cast<const uint2*>(ekb + off1 + lane * 8);
        float p0 = corr, p1 = corr;
        p0 = fmaf(q4.x, __uint_as_float(ra.x << 16), p0);
        p0 = fmaf(q4.y, __uint_as_float(ra.x & 0xffff0000u), p0);
        p0 = fmaf(q4.z, __uint_as_float(ra.y << 16), p0);
        p0 = fmaf(q4.w, __uint_as_float(ra.y & 0xffff0000u), p0);
        p1 = fmaf(q4.x, __uint_as_float(rb.x << 16), p1);
        p1 = fmaf(q4.y, __uint_as_float(rb.x & 0xffff0000u), p1);
        p1 = fmaf(q4.z, __uint_as_float(rb.y << 16), p1);
        p1 = fmaf(q4.w, __uint_as_float(rb.y & 0xffff0000u), p1);
        #pragma unroll
        for (int o = 4; o; o >>= 1) {
            p0 += __shfl_xor_sync(0xffffffffu, p0, o);
            p1 += __shfl_xor_sync(0xffffffffu, p1, o);
        }
        if ((lane & 7) == 0) {
            float sc0 = p0 * RS;
            if (g_Esum[s_kid[k]] == 0.0f) sc0 = NEGF;
            s_sc[lane >> 3][k] = sc0;
            if (k1 < L2) {
                float sc1 = p1 * RS;
                if (g_Esum[s_kid[k1]] == 0.0f) sc1 = NEGF;
                s_sc[lane >> 3][k1] = sc1;
            }
        }
    }
    __syncthreads();

    // phase 2: softmax, warp w == head w
    {
        float s0 = (lane      < L2) ? s_sc[w][lane]      : -3.4e38f;
        float s1 = (lane + 32 < L2) ? s_sc[w][lane + 32] : -3.4e38f;
        float m = fmaxf(s0, s1);
        #pragma unroll
        for (int o = 16; o; o >>= 1) m = fmaxf(m, __shfl_xor_sync(0xffffffffu, m, o));
        float e0 = (lane      < L2) ? expf(s0 - m) : 0.f;
        float e1 = (lane + 32 < L2) ? expf(s1 - m) : 0.f;
        float s = e0 + e1;
        #pragma unroll
        for (int o = 16; o; o >>= 1) s += __shfl_xor_sync(0xffffffffu, s, o);
        float inv = 1.0f / s;
        if (lane      < L2) s_attn[w][lane]      = e0 * inv;
        if (lane + 32 < L2) s_attn[w][lane + 32] = e1 * inv;
    }
    __syncthreads();

    // phase 3: 4-way key split; thread covers cols [lane*4, lane*4+4)
    {
        const int head = lane >> 3;       // (lane*4)>>5
        float a0 = 0.f, a1 = 0.f, a2 = 0.f, a3 = 0.f;
        for (int k = w; k < L2; k += 4) {
            uint2 v = *reinterpret_cast<const uint2*>(evb + s_off[k] + lane * 8);
            float wt = s_attn[head][k];
            a0 = fmaf(wt, __uint_as_float(v.x << 16),          a0);
            a1 = fmaf(wt, __uint_as_float(v.x & 0xffff0000u),  a1);
            a2 = fmaf(wt, __uint_as_float(v.y << 16),          a2);
            a3 = fmaf(wt, __uint_as_float(v.y & 0xffff0000u),  a3);
        }
        s_part[w][lane * 4 + 0] = a0;
        s_part[w][lane * 4 + 1] = a1;
        s_part[w][lane * 4 + 2] = a2;
        s_part[w][lane * 4 + 3] = a3;
    }
    __syncthreads();

    {
        float o = bv[t] + ((s_part[0][t] + s_part[1][t]) + (s_part[2][t] + s_part[3][t]));
        o += E[(size_t)queries[bl] * DIM + t];
        g_res[(size_t)bl * DIM + t] = o;
    }
}

// ------------------------- launch --------------------------------------------
extern "C" void kernel_launch(void* const* d_in, const int* in_sizes, int n_in,
                              void* d_out, int out_size) {
    const int*   queries = (const int*)d_in[0];
    const int*   keys    = (const int*)d_in[1];
    const float* E       = (const float*)d_in[2];
    const float* Wq      = (const float*)d_in[3];
    const float* bq      = (const float*)d_in[4];
    const float* Wk      = (const float*)d_in[5];
    const float* bk      = (const float*)d_in[6];
    const float* Wv      = (const float*)d_in[7];
    const float* bv      = (const float*)d_in[8];
    const float* Wf      = (const float*)d_in[9];
    const float* bf      = (const float*)d_in[10];
    float* out = (float*)d_out;

    const int V  = in_sizes[2] / DIM;
    const int M  = in_sizes[0];
    const int L2 = in_sizes[1] / M;

    cudaFuncSetAttribute(k_proj_mma, cudaFuncAttributeMaxDynamicSharedMemorySize, PROJ_SMEM);
    cudaFuncSetAttribute(k_gemm_q,   cudaFuncAttributeMaxDynamicSharedMemorySize, GEMMQ_SMEM);
    cudaFuncSetAttribute(k_gemm_f,   cudaFuncAttributeMaxDynamicSharedMemorySize, GEMMF_SMEM);

    k_wprep<<<32, 256>>>(Wk, Wv, Wq, Wf);
    k_proj_mma<<<(V + 127) / 128, 512, PROJ_SMEM>>>(E, V);
    k_gemm_q<<<(M + 127) / 128, 512, GEMMQ_SMEM>>>(E, queries, bq, M);
    k_attn<<<M, 128>>>(queries, keys, E, bk, bv, L2);
    k_gemm_f<<<(M + 127) / 128, 512, GEMMF_SMEM>>>(bf, out, M);
}

// round 7
// speedup vs baseline: 4.4028x; 1.1604x over previous
#include <cuda_runtime.h>
#include <cuda_bf16.h>
#include <cstdint>

#define VOCAB_MAX 100000
#define BL_MAX    12800
#define DIM       128
#define NHEAD     4

// ------------------------- scratch (device globals) -------------------------
__device__ __nv_bfloat16 g_EKbf[VOCAB_MAX * DIM];   // E @ Wk  (bf16)
__device__ __nv_bfloat16 g_EVbf[VOCAB_MAX * DIM];   // E @ Wv  (bf16)
__device__ float g_Esum[VOCAB_MAX];
__device__ float g_Q[BL_MAX * DIM];
__device__ float g_res[BL_MAX * DIM];
// swizzled W^T images (n-major, k contiguous, kc ^= n&7)
__device__ uint4 g_WT16[4096];   // [Wk|Wv] fp16: [n=256][kc=16]
__device__ uint4 g_WQ16[2048];   // Wq fp16:      [n=128][kc=16]
__device__ uint4 g_WFhi[2048];   // Wf bf16 hi
__device__ uint4 g_WFlo[2048];   // Wf bf16 lo

// ------------------------- helpers ------------------------------------------
__device__ __forceinline__ uint32_t smem_to_u32(const void* p) {
    uint32_t a;
    asm("{ .reg .u64 t; cvta.to.shared.u64 t, %1; cvt.u32.u64 %0, t; }" : "=r"(a) : "l"(p));
    return a;
}
__device__ __forceinline__ uint32_t pack_bf2(float lo, float hi) {
    uint32_t r; asm("cvt.rn.bf16x2.f32 %0, %1, %2;" : "=r"(r) : "f"(hi), "f"(lo)); return r;
}
__device__ __forceinline__ uint32_t pack_h2(float lo, float hi) {
    uint32_t r; asm("cvt.rn.f16x2.f32 %0, %1, %2;" : "=r"(r) : "f"(hi), "f"(lo)); return r;
}
__device__ __forceinline__ void ldsm_x4(uint32_t addr, uint32_t* r) {
    asm volatile("ldmatrix.sync.aligned.m8n8.x4.shared.b16 {%0,%1,%2,%3}, [%4];"
                 : "=r"(r[0]), "=r"(r[1]), "=r"(r[2]), "=r"(r[3]) : "r"(addr));
}
__device__ __forceinline__ void mma_bf16(float* c, const uint32_t* a, uint32_t b0, uint32_t b1) {
    asm volatile("mma.sync.aligned.m16n8k16.row.col.f32.bf16.bf16.f32 "
                 "{%0,%1,%2,%3}, {%4,%5,%6,%7}, {%8,%9}, {%0,%1,%2,%3};"
                 : "+f"(c[0]), "+f"(c[1]), "+f"(c[2]), "+f"(c[3])
                 : "r"(a[0]), "r"(a[1]), "r"(a[2]), "r"(a[3]), "r"(b0), "r"(b1));
}
__device__ __forceinline__ void mma_f16(float* c, const uint32_t* a, uint32_t b0, uint32_t b1) {
    asm volatile("mma.sync.aligned.m16n8k16.row.col.f32.f16.f16.f32 "
                 "{%0,%1,%2,%3}, {%4,%5,%6,%7}, {%8,%9}, {%0,%1,%2,%3};"
                 : "+f"(c[0]), "+f"(c[1]), "+f"(c[2]), "+f"(c[3])
                 : "r"(a[0]), "r"(a[1]), "r"(a[2]), "r"(a[3]), "r"(b0), "r"(b1));
}
__device__ __forceinline__ void split2(float x, float y, uint32_t& h, uint32_t& l) {
    h = pack_bf2(x, y);
    l = pack_bf2(x - __uint_as_float(h << 16), y - __uint_as_float(h & 0xffff0000u));
}

// ------------------------- K0: prep all W^T images ---------------------------
__global__ void k_wprep(const float* __restrict__ Wk, const float* __restrict__ Wv,
                        const float* __restrict__ Wq, const float* __restrict__ Wf) {
    int u = blockIdx.x * blockDim.x + threadIdx.x;    // 8192 units
    const float* src;
    int n, kc, kind;
    uint4 *dst16 = nullptr, *dh = nullptr, *dl = nullptr;
    if (u < 4096) {
        n = u & 255; kc = u >> 8; kind = 0;
        src = (n < 128) ? (Wk + n) : (Wv + (n - 128));
        dst16 = g_WT16 + n * 16 + (kc ^ (n & 7));
    } else if (u < 6144) {
        int u2 = u - 4096; n = u2 & 127; kc = u2 >> 7; kind = 1;
        src = Wq + n;
        dst16 = g_WQ16 + n * 16 + (kc ^ (n & 7));
    } else {
        int u2 = u - 6144; n = u2 & 127; kc = u2 >> 7; kind = 2;
        src = Wf + n;
        int idx = n * 16 + (kc ^ (n & 7));
        dh = g_WFhi + idx; dl = g_WFlo + idx;
    }
    float f[8];
    #pragma unroll
    for (int i = 0; i < 8; i++) f[i] = src[(size_t)(kc * 8 + i) * DIM];
    if (kind < 2) {
        uint32_t h[4];
        #pragma unroll
        for (int i = 0; i < 4; i++) h[i] = pack_h2(f[2 * i], f[2 * i + 1]);
        *dst16 = make_uint4(h[0], h[1], h[2], h[3]);
    } else {
        uint32_t h[4], l[4];
        #pragma unroll
        for (int i = 0; i < 4; i++) split2(f[2 * i], f[2 * i + 1], h[i], l[i]);
        *dh = make_uint4(h[0], h[1], h[2], h[3]);
        *dl = make_uint4(l[0], l[1], l[2], l[3]);
    }
}

// ------------------------- K1: fp16 HMMA projection + fused Esum -------------
#define A_16 0
#define B_16 32768
#define PROJ_SMEM 98304

__global__ void __launch_bounds__(512)
k_proj_mma(const float* __restrict__ E, int V) {
    extern __shared__ char smem[];
    const uint32_t sb = smem_to_u32(smem);
    const int t    = threadIdx.x;
    const int w    = t >> 5;
    const int lane = t & 31;
    const int v0   = blockIdx.x * 128;

    #pragma unroll
    for (int i = 0; i < 4; i++) {
        int u   = t + 512 * i;
        int row = u >> 4;
        int kc  = u & 15;
        int gr  = v0 + row;
        int grc = (gr < V) ? gr : 0;
        const float4* src = reinterpret_cast<const float4*>(E + (size_t)grc * DIM + kc * 8);
        float4 f0 = src[0], f1 = src[1];
        uint32_t h0 = pack_h2(f0.x, f0.y), h1 = pack_h2(f0.z, f0.w);
        uint32_t h2 = pack_h2(f1.x, f1.y), h3 = pack_h2(f1.z, f1.w);
        uint32_t off = (uint32_t)row * 256 + (uint32_t)((kc ^ (row & 7)) << 4);
        *reinterpret_cast<uint4*>(smem + A_16 + off) = make_uint4(h0, h1, h2, h3);
        float s8 = ((f0.x + f0.y) + (f0.z + f0.w)) + ((f1.x + f1.y) + (f1.z + f1.w));
        s8 += __shfl_xor_sync(0xffffffffu, s8, 8);
        s8 += __shfl_xor_sync(0xffffffffu, s8, 4);
        s8 += __shfl_xor_sync(0xffffffffu, s8, 2);
        s8 += __shfl_xor_sync(0xffffffffu, s8, 1);
        if ((t & 15) == 0 && gr < V) g_Esum[gr] = s8;
    }
    {
        uint4* d = reinterpret_cast<uint4*>(smem + B_16);
        #pragma unroll
        for (int i = 0; i < 8; i++) {
            int idx = t + 512 * i;
            d[idx] = g_WT16[idx];
        }
    }
    __syncthreads();

    const int mg = w & 3;
    const int ng = w >> 2;

    float acc[2][8][4];
    #pragma unroll
    for (int mt = 0; mt < 2; mt++)
        #pragma unroll
        for (int nt = 0; nt < 8; nt++)
            #pragma unroll
            for (int j = 0; j < 4; j++) acc[mt][nt][j] = 0.f;

    const int aRow  = mg * 32 + ((lane >> 3) & 1) * 8 + (lane & 7);
    const int aKsel = (lane >> 4);
    const int bN    = ng * 64 + ((lane >> 4) & 1) * 8 + (lane & 7);
    const int bKsel = (lane >> 3) & 1;

    #pragma unroll
    for (int ks = 0; ks < 8; ks++) {
        uint32_t a[2][4];
        #pragma unroll
        for (int mt = 0; mt < 2; mt++) {
            int row = aRow + mt * 16;
            int kc  = ks * 2 + aKsel;
            ldsm_x4(sb + A_16 + row * 256 + (((kc ^ (row & 7)) << 4)), a[mt]);
        }
        uint32_t b[4][4];
        #pragma unroll
        for (int bt = 0; bt < 4; bt++) {
            int n  = bN + bt * 16;
            int kc = ks * 2 + bKsel;
            ldsm_x4(sb + B_16 + n * 256 + (((kc ^ (n & 7)) << 4)), b[bt]);
        }
        #pragma unroll
        for (int mt = 0; mt < 2; mt++)
            #pragma unroll
            for (int nt = 0; nt < 8; nt++)
                mma_f16(acc[mt][nt], a[mt], b[nt >> 1][(nt & 1) * 2], b[nt >> 1][(nt & 1) * 2 + 1]);
    }

    #pragma unroll
    for (int mt = 0; mt < 2; mt++) {
        int row = v0 + mg * 32 + mt * 16 + (lane >> 2);
        if (row >= V) continue;
        #pragma unroll
        for (int nt = 0; nt < 8; nt++) {
            int col = ng * 64 + nt * 8 + (lane & 3) * 2;
            __nv_bfloat16* base = (col < 128) ? (g_EKbf + (size_t)row * DIM + col)
                                              : (g_EVbf + (size_t)row * DIM + (col - 128));
            *reinterpret_cast<uint32_t*>(base)           = pack_bf2(acc[mt][nt][0], acc[mt][nt][1]);
            *reinterpret_cast<uint32_t*>(base + 8 * DIM) = pack_bf2(acc[mt][nt][2], acc[mt][nt][3]);
        }
    }
}

// ------------------------- K2a: Q gemm (fp16 single pass, N=128) -------------
#define Q_A 0
#define Q_B 32768
#define GEMMQ_SMEM 65536

__global__ void __launch_bounds__(512)
k_gemm_q(const float* __restrict__ E, const int* __restrict__ queries,
         const float* __restrict__ bq, int M) {
    extern __shared__ char smem[];
    const uint32_t sb = smem_to_u32(smem);
    const int t    = threadIdx.x;
    const int w    = t >> 5;
    const int lane = t & 31;
    const int m0   = blockIdx.x * 128;

    #pragma unroll
    for (int i = 0; i < 4; i++) {
        int u   = t + 512 * i;
        int row = u >> 4;
        int kc  = u & 15;
        int m   = m0 + row;
        int mm  = (m < M) ? m : 0;
        const float4* src = reinterpret_cast<const float4*>(E + (size_t)queries[mm] * DIM + kc * 8);
        float4 f0 = src[0], f1 = src[1];
        uint32_t h0 = pack_h2(f0.x, f0.y), h1 = pack_h2(f0.z, f0.w);
        uint32_t h2 = pack_h2(f1.x, f1.y), h3 = pack_h2(f1.z, f1.w);
        uint32_t off = (uint32_t)row * 256 + (uint32_t)((kc ^ (row & 7)) << 4);
        *reinterpret_cast<uint4*>(smem + Q_A + off) = make_uint4(h0, h1, h2, h3);
    }
    {
        uint4* d = reinterpret_cast<uint4*>(smem + Q_B);
        #pragma unroll
        for (int i = 0; i < 4; i++) {
            int idx = t + 512 * i;
            d[idx] = g_WQ16[idx];
        }
    }
    __syncthreads();

    const int mg = w & 3;
    const int ng = w >> 2;

    float acc[2][4][4];
    #pragma unroll
    for (int mt = 0; mt < 2; mt++)
        #pragma unroll
        for (int nt = 0; nt < 4; nt++)
            #pragma unroll
            for (int j = 0; j < 4; j++) acc[mt][nt][j] = 0.f;

    const int aRow  = mg * 32 + ((lane >> 3) & 1) * 8 + (lane & 7);
    const int aKsel = (lane >> 4);
    const int bN    = ng * 32 + ((lane >> 4) & 1) * 8 + (lane & 7);
    const int bKsel = (lane >> 3) & 1;

    #pragma unroll
    for (int ks = 0; ks < 8; ks++) {
        uint32_t a[2][4];
        #pragma unroll
        for (int mt = 0; mt < 2; mt++) {
            int row = aRow + mt * 16;
            int kc  = ks * 2 + aKsel;
            ldsm_x4(sb + Q_A + row * 256 + (((kc ^ (row & 7)) << 4)), a[mt]);
        }
        uint32_t b[2][4];
        #pragma unroll
        for (int bt = 0; bt < 2; bt++) {
            int n  = bN + bt * 16;
            int kc = ks * 2 + bKsel;
            ldsm_x4(sb + Q_B + n * 256 + (((kc ^ (n & 7)) << 4)), b[bt]);
        }
        #pragma unroll
        for (int mt = 0; mt < 2; mt++)
            #pragma unroll
            for (int nt = 0; nt < 4; nt++)
                mma_f16(acc[mt][nt], a[mt], b[nt >> 1][(nt & 1) * 2], b[nt >> 1][(nt & 1) * 2 + 1]);
    }

    #pragma unroll
    for (int mt = 0; mt < 2; mt++) {
        int row = m0 + mg * 32 + mt * 16 + (lane >> 2);
        #pragma unroll
        for (int nt = 0; nt < 4; nt++) {
            int col = ng * 32 + nt * 8 + (lane & 3) * 2;
            float b0 = bq[col], b1 = bq[col + 1];
            if (row < M) {
                *reinterpret_cast<float2*>(g_Q + (size_t)row * DIM + col) =
                    make_float2(acc[mt][nt][0] + b0, acc[mt][nt][1] + b1);
                if (row + 8 < M)
                    *reinterpret_cast<float2*>(g_Q + (size_t)(row + 8) * DIM + col) =
                        make_float2(acc[mt][nt][2] + b0, acc[mt][nt][3] + b1);
            }
        }
    }
}

// ------------------------- K2b: final gemm (bf16 3-pass, N=128) --------------
#define F_A_HI 0
#define F_A_LO 32768
#define F_B_HI 65536
#define F_B_LO 98304
#define GEMMF_SMEM 131072

__global__ void __launch_bounds__(512)
k_gemm_f(const float* __restrict__ bf, float* __restrict__ outp, int M) {
    extern __shared__ char smem[];
    const uint32_t sb = smem_to_u32(smem);
    const int t    = threadIdx.x;
    const int w    = t >> 5;
    const int lane = t & 31;
    const int m0   = blockIdx.x * 128;

    #pragma unroll
    for (int i = 0; i < 4; i++) {
        int u   = t + 512 * i;
        int row = u >> 4;
        int kc  = u & 15;
        int m   = m0 + row;
        const float4* src = reinterpret_cast<const float4*>(
            g_res + (size_t)((m < M) ? m : 0) * DIM + kc * 8);
        float4 f0 = src[0], f1 = src[1];
        uint32_t h0, h1, h2, h3, l0, l1, l2, l3;
        split2(f0.x, f0.y, h0, l0); split2(f0.z, f0.w, h1, l1);
        split2(f1.x, f1.y, h2, l2); split2(f1.z, f1.w, h3, l3);
        uint32_t off = (uint32_t)row * 256 + (uint32_t)((kc ^ (row & 7)) << 4);
        *reinterpret_cast<uint4*>(smem + F_A_HI + off) = make_uint4(h0, h1, h2, h3);
        *reinterpret_cast<uint4*>(smem + F_A_LO + off) = make_uint4(l0, l1, l2, l3);
    }
    {
        uint4* dh = reinterpret_cast<uint4*>(smem + F_B_HI);
        uint4* dl = reinterpret_cast<uint4*>(smem + F_B_LO);
        #pragma unroll
        for (int i = 0; i < 4; i++) {
            int idx = t + 512 * i;
            dh[idx] = g_WFhi[idx];
            dl[idx] = g_WFlo[idx];
        }
    }
    __syncthreads();

    const int mg = w & 3;
    const int ng = w >> 2;

    float acc[2][4][4];
    #pragma unroll
    for (int mt = 0; mt < 2; mt++)
        #pragma unroll
        for (int nt = 0; nt < 4; nt++)
            #pragma unroll
            for (int j = 0; j < 4; j++) acc[mt][nt][j] = 0.f;

    const int aRow  = mg * 32 + ((lane >> 3) & 1) * 8 + (lane & 7);
    const int aKsel = (lane >> 4);
    const int bN    = ng * 32 + ((lane >> 4) & 1) * 8 + (lane & 7);
    const int bKsel = (lane >> 3) & 1;

    #pragma unroll
    for (int p = 0; p < 3; p++) {
        const uint32_t abase = sb + (p == 2 ? F_A_LO : F_A_HI);
        const uint32_t bbase = sb + (p == 1 ? F_B_LO : F_B_HI);
        #pragma unroll
        for (int ks = 0; ks < 8; ks++) {
            uint32_t a[2][4];
            #pragma unroll
            for (int mt = 0; mt < 2; mt++) {
                int row = aRow + mt * 16;
                int kc  = ks * 2 + aKsel;
                ldsm_x4(abase + row * 256 + (((kc ^ (row & 7)) << 4)), a[mt]);
            }
            uint32_t b[2][4];
            #pragma unroll
            for (int bt = 0; bt < 2; bt++) {
                int n  = bN + bt * 16;
                int kc = ks * 2 + bKsel;
                ldsm_x4(bbase + n * 256 + (((kc ^ (n & 7)) << 4)), b[bt]);
            }
            #pragma unroll
            for (int mt = 0; mt < 2; mt++)
                #pragma unroll
                for (int nt = 0; nt < 4; nt++)
                    mma_bf16(acc[mt][nt], a[mt], b[nt >> 1][(nt & 1) * 2], b[nt >> 1][(nt & 1) * 2 + 1]);
        }
    }

    #pragma unroll
    for (int mt = 0; mt < 2; mt++) {
        int row = m0 + mg * 32 + mt * 16 + (lane >> 2);
        #pragma unroll
        for (int nt = 0; nt < 4; nt++) {
            int col = ng * 32 + nt * 8 + (lane & 3) * 2;
            float b0 = bf[col], b1 = bf[col + 1];
            if (row < M) {
                *reinterpret_cast<float2*>(outp + (size_t)row * DIM + col) =
                    make_float2(acc[mt][nt][0] + b0, acc[mt][nt][1] + b1);
                if (row + 8 < M)
                    *reinterpret_cast<float2*>(outp + (size_t)(row + 8) * DIM + col) =
                        make_float2(acc[mt][nt][2] + b0, acc[mt][nt][3] + b1);
            }
        }
    }
}

// ------------------------- K3: fused attention, warp per (b,l) ---------------
// Softmax without max-subtraction (scores are O(1e-2); masked -> weight 0):
// out = (sum_k w_k * V_k) / (sum_k w_k) + bv + q_emb,  w_k = mask_k * exp(s_k)
__global__ void __launch_bounds__(256) k_attn(const int* __restrict__ queries,
                                              const int* __restrict__ keys,
                                              const float* __restrict__ E,
                                              const float* __restrict__ bk,
                                              const float* __restrict__ bv,
                                              int L2, int M) {
    const int t    = threadIdx.x;
    const int w    = t >> 5;
    const int lane = t & 31;
    const int bl   = blockIdx.x * 8 + w;

    __shared__ uint2 s_km[8][52];       // {byte offset kid*256, mask as float}

    if (bl < M) {
        for (int i = lane; i < L2; i += 32) {
            int kid = keys[bl * L2 + i];
            float m = (g_Esum[kid] == 0.0f) ? 0.0f : 1.0f;
            s_km[w][i] = make_uint2((uint32_t)kid << 8, __float_as_uint(m));
        }
    }
    __syncwarp();
    if (bl >= M) return;

    const float4 q4  = reinterpret_cast<const float4*>(g_Q + (size_t)bl * DIM)[lane];
    const float4 kb4 = reinterpret_cast<const float4*>(bk)[lane];
    const float corr = q4.x * kb4.x + q4.y * kb4.y + q4.z * kb4.z + q4.w * kb4.w;

    const float RS = 0.17677669529663687f;   // 1/sqrt(32)
    const char* ekb = reinterpret_cast<const char*>(g_EKbf);
    const char* evb = reinterpret_cast<const char*>(g_EVbf);
    const uint32_t lo8 = lane * 8;

    float a0 = 0.f, a1 = 0.f, a2 = 0.f, a3 = 0.f, sumw = 0.f;

    int k = 0;
    for (; k + 2 <= L2; k += 2) {
        uint2 km0 = s_km[w][k], km1 = s_km[w][k + 1];
        uint2 ka = *reinterpret_cast<const uint2*>(ekb + km0.x + lo8);
        uint2 kb_ = *reinterpret_cast<const uint2*>(ekb + km1.x + lo8);
        uint2 va = *reinterpret_cast<const uint2*>(evb + km0.x + lo8);
        uint2 vb = *reinterpret_cast<const uint2*>(evb + km1.x + lo8);
        float p0 = corr, p1 = corr;
        p0 = fmaf(q4.x, __uint_as_float(ka.x << 16),          p0);
        p0 = fmaf(q4.y, __uint_as_float(ka.x & 0xffff0000u),  p0);
        p0 = fmaf(q4.z, __uint_as_float(ka.y << 16),          p0);
        p0 = fmaf(q4.w, __uint_as_float(ka.y & 0xffff0000u),  p0);
        p1 = fmaf(q4.x, __uint_as_float(kb_.x << 16),         p1);
        p1 = fmaf(q4.y, __uint_as_float(kb_.x & 0xffff0000u), p1);
        p1 = fmaf(q4.z, __uint_as_float(kb_.y << 16),         p1);
        p1 = fmaf(q4.w, __uint_as_float(kb_.y & 0xffff0000u), p1);
        #pragma unroll
        for (int o = 4; o; o >>= 1) {
            p0 += __shfl_xor_sync(0xffffffffu, p0, o);
            p1 += __shfl_xor_sync(0xffffffffu, p1, o);
        }
        float w0 = __uint_as_float(km0.y) * __expf(p0 * RS);
        float w1 = __uint_as_float(km1.y) * __expf(p1 * RS);
        a0 = fmaf(w0, __uint_as_float(va.x << 16),          a0);
        a1 = fmaf(w0, __uint_as_float(va.x & 0xffff0000u),  a1);
        a2 = fmaf(w0, __uint_as_float(va.y << 16),          a2);
        a3 = fmaf(w0, __uint_as_float(va.y & 0xffff0000u),  a3);
        a0 = fmaf(w1, __uint_as_float(vb.x << 16),          a0);
        a1 = fmaf(w1, __uint_as_float(vb.x & 0xffff0000u),  a1);
        a2 = fmaf(w1, __uint_as_float(vb.y << 16),          a2);
        a3 = fmaf(w1, __uint_as_float(vb.y & 0xffff0000u),  a3);
        sumw += w0 + w1;
    }
    for (; k < L2; k++) {
        uint2 km0 = s_km[w][k];
        uint2 ka = *reinterpret_cast<const uint2*>(ekb + km0.x + lo8);
        uint2 va = *reinterpret_cast<const uint2*>(evb + km0.x + lo8);
        float p0 = corr;
        p0 = fmaf(q4.x, __uint_as_float(ka.x << 16),          p0);
        p0 = fmaf(q4.y, __uint_as_float(ka.x & 0xffff0000u),  p0);
        p0 = fmaf(q4.z, __uint_as_float(ka.y << 16),          p0);
        p0 = fmaf(q4.w, __uint_as_float(ka.y & 0xffff0000u),  p0);
        #pragma unroll
        for (int o = 4; o; o >>= 1) p0 += __shfl_xor_sync(0xffffffffu, p0, o);
        float w0 = __uint_as_float(km0.y) * __expf(p0 * RS);
        a0 = fmaf(w0, __uint_as_float(va.x << 16),          a0);
        a1 = fmaf(w0, __uint_as_float(va.x & 0xffff0000u),  a1);
        a2 = fmaf(w0, __uint_as_float(va.y << 16),          a2);
        a3 = fmaf(w0, __uint_as_float(va.y & 0xffff0000u),  a3);
        sumw += w0;
    }

    const float inv = 1.0f / sumw;
    const int   qid = queries[bl];
    const float4 bv4 = reinterpret_cast<const float4*>(bv)[lane];
    const float4 qe4 = reinterpret_cast<const float4*>(E + (size_t)qid * DIM)[lane];
    float4 o;
    o.x = fmaf(a0, inv, bv4.x + qe4.x);
    o.y = fmaf(a1, inv, bv4.y + qe4.y);
    o.z = fmaf(a2, inv, bv4.z + qe4.z);
    o.w = fmaf(a3, inv, bv4.w + qe4.w);
    reinterpret_cast<float4*>(g_res + (size_t)bl * DIM)[lane] = o;
}

// ------------------------- launch --------------------------------------------
extern "C" void kernel_launch(void* const* d_in, const int* in_sizes, int n_in,
                              void* d_out, int out_size) {
    const int*   queries = (const int*)d_in[0];
    const int*   keys    = (const int*)d_in[1];
    const float* E       = (const float*)d_in[2];
    const float* Wq      = (const float*)d_in[3];
    const float* bq      = (const float*)d_in[4];
    const float* Wk      = (const float*)d_in[5];
    const float* bk      = (const float*)d_in[6];
    const float* Wv      = (const float*)d_in[7];
    const float* bv      = (const float*)d_in[8];
    const float* Wf      = (const float*)d_in[9];
    const float* bf      = (const float*)d_in[10];
    float* out = (float*)d_out;

    const int V  = in_sizes[2] / DIM;
    const int M  = in_sizes[0];
    const int L2 = in_sizes[1] / M;

    cudaFuncSetAttribute(k_proj_mma, cudaFuncAttributeMaxDynamicSharedMemorySize, PROJ_SMEM);
    cudaFuncSetAttribute(k_gemm_q,   cudaFuncAttributeMaxDynamicSharedMemorySize, GEMMQ_SMEM);
    cudaFuncSetAttribute(k_gemm_f,   cudaFuncAttributeMaxDynamicSharedMemorySize, GEMMF_SMEM);

    k_wprep<<<32, 256>>>(Wk, Wv, Wq, Wf);
    k_proj_mma<<<(V + 127) / 128, 512, PROJ_SMEM>>>(E, V);
    k_gemm_q<<<(M + 127) / 128, 512, GEMMQ_SMEM>>>(E, queries, bq, M);
    k_attn<<<(M + 7) / 8, 256>>>(queries, keys, E, bk, bv, L2, M);
    k_gemm_f<<<(M + 127) / 128, 512, GEMMF_SMEM>>>(bf, out, M);
}

// round 8
// speedup vs baseline: 4.5803x; 1.0403x over previous
#include <cuda_runtime.h>
#include <cuda_bf16.h>
#include <cstdint>

#define VOCAB_MAX 100000
#define BL_MAX    12800
#define DIM       128
#define NHEAD     4

// ------------------------- scratch (device globals) -------------------------
__device__ __nv_bfloat16 g_EKbf[VOCAB_MAX * DIM];   // E @ Wk  (bf16)
__device__ __nv_bfloat16 g_EVbf[VOCAB_MAX * DIM];   // E @ Wv  (bf16)
__device__ float g_Esum[VOCAB_MAX];
__device__ float g_Q[BL_MAX * DIM];
__device__ float g_res[BL_MAX * DIM];
// swizzled W^T images (n-major, k contiguous, kc ^= n&7)
__device__ uint4 g_WT16[4096];   // [Wk|Wv] fp16: [n=256][kc=16]
__device__ uint4 g_WQ16[2048];   // Wq fp16:      [n=128][kc=16]
__device__ uint4 g_WFhi[2048];   // Wf bf16 hi
__device__ uint4 g_WFlo[2048];   // Wf bf16 lo

// ------------------------- helpers ------------------------------------------
__device__ __forceinline__ uint32_t smem_to_u32(const void* p) {
    uint32_t a;
    asm("{ .reg .u64 t; cvta.to.shared.u64 t, %1; cvt.u32.u64 %0, t; }" : "=r"(a) : "l"(p));
    return a;
}
__device__ __forceinline__ uint32_t pack_bf2(float lo, float hi) {
    uint32_t r; asm("cvt.rn.bf16x2.f32 %0, %1, %2;" : "=r"(r) : "f"(hi), "f"(lo)); return r;
}
__device__ __forceinline__ uint32_t pack_h2(float lo, float hi) {
    uint32_t r; asm("cvt.rn.f16x2.f32 %0, %1, %2;" : "=r"(r) : "f"(hi), "f"(lo)); return r;
}
__device__ __forceinline__ void ldsm_x4(uint32_t addr, uint32_t* r) {
    asm volatile("ldmatrix.sync.aligned.m8n8.x4.shared.b16 {%0,%1,%2,%3}, [%4];"
                 : "=r"(r[0]), "=r"(r[1]), "=r"(r[2]), "=r"(r[3]) : "r"(addr));
}
__device__ __forceinline__ void mma_bf16(float* c, const uint32_t* a, uint32_t b0, uint32_t b1) {
    asm volatile("mma.sync.aligned.m16n8k16.row.col.f32.bf16.bf16.f32 "
                 "{%0,%1,%2,%3}, {%4,%5,%6,%7}, {%8,%9}, {%0,%1,%2,%3};"
                 : "+f"(c[0]), "+f"(c[1]), "+f"(c[2]), "+f"(c[3])
                 : "r"(a[0]), "r"(a[1]), "r"(a[2]), "r"(a[3]), "r"(b0), "r"(b1));
}
__device__ __forceinline__ void mma_f16(float* c, const uint32_t* a, uint32_t b0, uint32_t b1) {
    asm volatile("mma.sync.aligned.m16n8k16.row.col.f32.f16.f16.f32 "
                 "{%0,%1,%2,%3}, {%4,%5,%6,%7}, {%8,%9}, {%0,%1,%2,%3};"
                 : "+f"(c[0]), "+f"(c[1]), "+f"(c[2]), "+f"(c[3])
                 : "r"(a[0]), "r"(a[1]), "r"(a[2]), "r"(a[3]), "r"(b0), "r"(b1));
}
__device__ __forceinline__ void split2(float x, float y, uint32_t& h, uint32_t& l) {
    h = pack_bf2(x, y);
    l = pack_bf2(x - __uint_as_float(h << 16), y - __uint_as_float(h & 0xffff0000u));
}
__device__ __forceinline__ float bflo(uint32_t u) { return __uint_as_float(u << 16); }
__device__ __forceinline__ float bfhi(uint32_t u) { return __uint_as_float(u & 0xffff0000u); }

// ------------------------- K0: prep all W^T images ---------------------------
__global__ void k_wprep(const float* __restrict__ Wk, const float* __restrict__ Wv,
                        const float* __restrict__ Wq, const float* __restrict__ Wf) {
    int u = blockIdx.x * blockDim.x + threadIdx.x;    // 8192 units
    const float* src;
    int n, kc, kind;
    uint4 *dst16 = nullptr, *dh = nullptr, *dl = nullptr;
    if (u < 4096) {
        n = u & 255; kc = u >> 8; kind = 0;
        src = (n < 128) ? (Wk + n) : (Wv + (n - 128));
        dst16 = g_WT16 + n * 16 + (kc ^ (n & 7));
    } else if (u < 6144) {
        int u2 = u - 4096; n = u2 & 127; kc = u2 >> 7; kind = 1;
        src = Wq + n;
        dst16 = g_WQ16 + n * 16 + (kc ^ (n & 7));
    } else {
        int u2 = u - 6144; n = u2 & 127; kc = u2 >> 7; kind = 2;
        src = Wf + n;
        int idx = n * 16 + (kc ^ (n & 7));
        dh = g_WFhi + idx; dl = g_WFlo + idx;
    }
    float f[8];
    #pragma unroll
    for (int i = 0; i < 8; i++) f[i] = src[(size_t)(kc * 8 + i) * DIM];
    if (kind < 2) {
        uint32_t h[4];
        #pragma unroll
        for (int i = 0; i < 4; i++) h[i] = pack_h2(f[2 * i], f[2 * i + 1]);
        *dst16 = make_uint4(h[0], h[1], h[2], h[3]);
    } else {
        uint32_t h[4], l[4];
        #pragma unroll
        for (int i = 0; i < 4; i++) split2(f[2 * i], f[2 * i + 1], h[i], l[i]);
        *dh = make_uint4(h[0], h[1], h[2], h[3]);
        *dl = make_uint4(l[0], l[1], l[2], l[3]);
    }
}

// ------------------------- K1: fp16 HMMA projection (N-split) ----------------
// blockIdx.y = 0 -> EK half of [Wk|Wv], 1 -> EV half. CTA: M=128 x N=128.
#define A_16 0
#define B_16 32768
#define PROJ_SMEM 65536

__global__ void __launch_bounds__(512)
k_proj_mma(const float* __restrict__ E, int V) {
    extern __shared__ char smem[];
    const uint32_t sb = smem_to_u32(smem);
    const int t    = threadIdx.x;
    const int w    = t >> 5;
    const int lane = t & 31;
    const int v0   = blockIdx.x * 128;
    const int y    = blockIdx.y;          // 0 = K half, 1 = V half

    // ---- stage A (fp16) + fused row-sum (y==0 only)
    #pragma unroll
    for (int i = 0; i < 4; i++) {
        int u   = t + 512 * i;
        int row = u >> 4;
        int kc  = u & 15;
        int gr  = v0 + row;
        int grc = (gr < V) ? gr : 0;
        const float4* src = reinterpret_cast<const float4*>(E + (size_t)grc * DIM + kc * 8);
        float4 f0 = src[0], f1 = src[1];
        uint32_t h0 = pack_h2(f0.x, f0.y), h1 = pack_h2(f0.z, f0.w);
        uint32_t h2 = pack_h2(f1.x, f1.y), h3 = pack_h2(f1.z, f1.w);
        uint32_t off = (uint32_t)row * 256 + (uint32_t)((kc ^ (row & 7)) << 4);
        *reinterpret_cast<uint4*>(smem + A_16 + off) = make_uint4(h0, h1, h2, h3);
        if (y == 0) {
            float s8 = ((f0.x + f0.y) + (f0.z + f0.w)) + ((f1.x + f1.y) + (f1.z + f1.w));
            s8 += __shfl_xor_sync(0xffffffffu, s8, 8);
            s8 += __shfl_xor_sync(0xffffffffu, s8, 4);
            s8 += __shfl_xor_sync(0xffffffffu, s8, 2);
            s8 += __shfl_xor_sync(0xffffffffu, s8, 1);
            if ((t & 15) == 0 && gr < V) g_Esum[gr] = s8;
        }
    }
    // ---- stage B: 32KB half image
    {
        uint4* d = reinterpret_cast<uint4*>(smem + B_16);
        const uint4* s = g_WT16 + y * 2048;
        #pragma unroll
        for (int i = 0; i < 4; i++) {
            int idx = t + 512 * i;
            d[idx] = s[idx];
        }
    }
    __syncthreads();

    const int mg = w & 3;
    const int ng = w >> 2;                // 0..3, 32 cols each

    float acc[2][4][4];
    #pragma unroll
    for (int mt = 0; mt < 2; mt++)
        #pragma unroll
        for (int nt = 0; nt < 4; nt++)
            #pragma unroll
            for (int j = 0; j < 4; j++) acc[mt][nt][j] = 0.f;

    const int aRow  = mg * 32 + ((lane >> 3) & 1) * 8 + (lane & 7);
    const int aKsel = (lane >> 4);
    const int bN    = ng * 32 + ((lane >> 4) & 1) * 8 + (lane & 7);
    const int bKsel = (lane >> 3) & 1;

    #pragma unroll
    for (int ks = 0; ks < 8; ks++) {
        uint32_t a[2][4];
        #pragma unroll
        for (int mt = 0; mt < 2; mt++) {
            int row = aRow + mt * 16;
            int kc  = ks * 2 + aKsel;
            ldsm_x4(sb + A_16 + row * 256 + (((kc ^ (row & 7)) << 4)), a[mt]);
        }
        uint32_t b[2][4];
        #pragma unroll
        for (int bt = 0; bt < 2; bt++) {
            int n  = bN + bt * 16;
            int kc = ks * 2 + bKsel;
            ldsm_x4(sb + B_16 + n * 256 + (((kc ^ (n & 7)) << 4)), b[bt]);
        }
        #pragma unroll
        for (int mt = 0; mt < 2; mt++)
            #pragma unroll
            for (int nt = 0; nt < 4; nt++)
                mma_f16(acc[mt][nt], a[mt], b[nt >> 1][(nt & 1) * 2], b[nt >> 1][(nt & 1) * 2 + 1]);
    }

    __nv_bfloat16* table = (y == 0) ? g_EKbf : g_EVbf;
    #pragma unroll
    for (int mt = 0; mt < 2; mt++) {
        int row = v0 + mg * 32 + mt * 16 + (lane >> 2);
        if (row >= V) continue;
        #pragma unroll
        for (int nt = 0; nt < 4; nt++) {
            int col = ng * 32 + nt * 8 + (lane & 3) * 2;
            __nv_bfloat16* base = table + (size_t)row * DIM + col;
            *reinterpret_cast<uint32_t*>(base)           = pack_bf2(acc[mt][nt][0], acc[mt][nt][1]);
            *reinterpret_cast<uint32_t*>(base + 8 * DIM) = pack_bf2(acc[mt][nt][2], acc[mt][nt][3]);
        }
    }
}

// ------------------------- K2a: Q gemm (fp16 single pass, N=128) -------------
#define Q_A 0
#define Q_B 32768
#define GEMMQ_SMEM 65536

__global__ void __launch_bounds__(512)
k_gemm_q(const float* __restrict__ E, const int* __restrict__ queries,
         const float* __restrict__ bq, int M) {
    extern __shared__ char smem[];
    const uint32_t sb = smem_to_u32(smem);
    const int t    = threadIdx.x;
    const int w    = t >> 5;
    const int lane = t & 31;
    const int m0   = blockIdx.x * 128;

    #pragma unroll
    for (int i = 0; i < 4; i++) {
        int u   = t + 512 * i;
        int row = u >> 4;
        int kc  = u & 15;
        int m   = m0 + row;
        int mm  = (m < M) ? m : 0;
        const float4* src = reinterpret_cast<const float4*>(E + (size_t)queries[mm] * DIM + kc * 8);
        float4 f0 = src[0], f1 = src[1];
        uint32_t h0 = pack_h2(f0.x, f0.y), h1 = pack_h2(f0.z, f0.w);
        uint32_t h2 = pack_h2(f1.x, f1.y), h3 = pack_h2(f1.z, f1.w);
        uint32_t off = (uint32_t)row * 256 + (uint32_t)((kc ^ (row & 7)) << 4);
        *reinterpret_cast<uint4*>(smem + Q_A + off) = make_uint4(h0, h1, h2, h3);
    }
    {
        uint4* d = reinterpret_cast<uint4*>(smem + Q_B);
        #pragma unroll
        for (int i = 0; i < 4; i++) {
            int idx = t + 512 * i;
            d[idx] = g_WQ16[idx];
        }
    }
    __syncthreads();

    const int mg = w & 3;
    const int ng = w >> 2;

    float acc[2][4][4];
    #pragma unroll
    for (int mt = 0; mt < 2; mt++)
        #pragma unroll
        for (int nt = 0; nt < 4; nt++)
            #pragma unroll
            for (int j = 0; j < 4; j++) acc[mt][nt][j] = 0.f;

    const int aRow  = mg * 32 + ((lane >> 3) & 1) * 8 + (lane & 7);
    const int aKsel = (lane >> 4);
    const int bN    = ng * 32 + ((lane >> 4) & 1) * 8 + (lane & 7);
    const int bKsel = (lane >> 3) & 1;

    #pragma unroll
    for (int ks = 0; ks < 8; ks++) {
        uint32_t a[2][4];
        #pragma unroll
        for (int mt = 0; mt < 2; mt++) {
            int row = aRow + mt * 16;
            int kc  = ks * 2 + aKsel;
            ldsm_x4(sb + Q_A + row * 256 + (((kc ^ (row & 7)) << 4)), a[mt]);
        }
        uint32_t b[2][4];
        #pragma unroll
        for (int bt = 0; bt < 2; bt++) {
            int n  = bN + bt * 16;
            int kc = ks * 2 + bKsel;
            ldsm_x4(sb + Q_B + n * 256 + (((kc ^ (n & 7)) << 4)), b[bt]);
        }
        #pragma unroll
        for (int mt = 0; mt < 2; mt++)
            #pragma unroll
            for (int nt = 0; nt < 4; nt++)
                mma_f16(acc[mt][nt], a[mt], b[nt >> 1][(nt & 1) * 2], b[nt >> 1][(nt & 1) * 2 + 1]);
    }

    #pragma unroll
    for (int mt = 0; mt < 2; mt++) {
        int row = m0 + mg * 32 + mt * 16 + (lane >> 2);
        #pragma unroll
        for (int nt = 0; nt < 4; nt++) {
            int col = ng * 32 + nt * 8 + (lane & 3) * 2;
            float b0 = bq[col], b1 = bq[col + 1];
            if (row < M) {
                *reinterpret_cast<float2*>(g_Q + (size_t)row * DIM + col) =
                    make_float2(acc[mt][nt][0] + b0, acc[mt][nt][1] + b1);
                if (row + 8 < M)
                    *reinterpret_cast<float2*>(g_Q + (size_t)(row + 8) * DIM + col) =
                        make_float2(acc[mt][nt][2] + b0, acc[mt][nt][3] + b1);
            }
        }
    }
}

// ------------------------- K2b: final gemm (bf16 3-pass, N=128) --------------
#define F_A_HI 0
#define F_A_LO 32768
#define F_B_HI 65536
#define F_B_LO 98304
#define GEMMF_SMEM 131072

__global__ void __launch_bounds__(512)
k_gemm_f(const float* __restrict__ bf, float* __restrict__ outp, int M) {
    extern __shared__ char smem[];
    const uint32_t sb = smem_to_u32(smem);
    const int t    = threadIdx.x;
    const int w    = t >> 5;
    const int lane = t & 31;
    const int m0   = blockIdx.x * 128;

    #pragma unroll
    for (int i = 0; i < 4; i++) {
        int u   = t + 512 * i;
        int row = u >> 4;
        int kc  = u & 15;
        int m   = m0 + row;
        const float4* src = reinterpret_cast<const float4*>(
            g_res + (size_t)((m < M) ? m : 0) * DIM + kc * 8);
        float4 f0 = src[0], f1 = src[1];
        uint32_t h0, h1, h2, h3, l0, l1, l2, l3;
        split2(f0.x, f0.y, h0, l0); split2(f0.z, f0.w, h1, l1);
        split2(f1.x, f1.y, h2, l2); split2(f1.z, f1.w, h3, l3);
        uint32_t off = (uint32_t)row * 256 + (uint32_t)((kc ^ (row & 7)) << 4);
        *reinterpret_cast<uint4*>(smem + F_A_HI + off) = make_uint4(h0, h1, h2, h3);
        *reinterpret_cast<uint4*>(smem + F_A_LO + off) = make_uint4(l0, l1, l2, l3);
    }
    {
        uint4* dh = reinterpret_cast<uint4*>(smem + F_B_HI);
        uint4* dl = reinterpret_cast<uint4*>(smem + F_B_LO);
        #pragma unroll
        for (int i = 0; i < 4; i++) {
            int idx = t + 512 * i;
            dh[idx] = g_WFhi[idx];
            dl[idx] = g_WFlo[idx];
        }
    }
    __syncthreads();

    const int mg = w & 3;
    const int ng = w >> 2;

    float acc[2][4][4];
    #pragma unroll
    for (int mt = 0; mt < 2; mt++)
        #pragma unroll
        for (int nt = 0; nt < 4; nt++)
            #pragma unroll
            for (int j = 0; j < 4; j++) acc[mt][nt][j] = 0.f;

    const int aRow  = mg * 32 + ((lane >> 3) & 1) * 8 + (lane & 7);
    const int aKsel = (lane >> 4);
    const int bN    = ng * 32 + ((lane >> 4) & 1) * 8 + (lane & 7);
    const int bKsel = (lane >> 3) & 1;

    #pragma unroll
    for (int p = 0; p < 3; p++) {
        const uint32_t abase = sb + (p == 2 ? F_A_LO : F_A_HI);
        const uint32_t bbase = sb + (p == 1 ? F_B_LO : F_B_HI);
        #pragma unroll
        for (int ks = 0; ks < 8; ks++) {
            uint32_t a[2][4];
            #pragma unroll
            for (int mt = 0; mt < 2; mt++) {
                int row = aRow + mt * 16;
                int kc  = ks * 2 + aKsel;
                ldsm_x4(abase + row * 256 + (((kc ^ (row & 7)) << 4)), a[mt]);
            }
            uint32_t b[2][4];
            #pragma unroll
            for (int bt = 0; bt < 2; bt++) {
                int n  = bN + bt * 16;
                int kc = ks * 2 + bKsel;
                ldsm_x4(bbase + n * 256 + (((kc ^ (n & 7)) << 4)), b[bt]);
            }
            #pragma unroll
            for (int mt = 0; mt < 2; mt++)
                #pragma unroll
                for (int nt = 0; nt < 4; nt++)
                    mma_bf16(acc[mt][nt], a[mt], b[nt >> 1][(nt & 1) * 2], b[nt >> 1][(nt & 1) * 2 + 1]);
        }
    }

    #pragma unroll
    for (int mt = 0; mt < 2; mt++) {
        int row = m0 + mg * 32 + mt * 16 + (lane >> 2);
        #pragma unroll
        for (int nt = 0; nt < 4; nt++) {
            int col = ng * 32 + nt * 8 + (lane & 3) * 2;
            float b0 = bf[col], b1 = bf[col + 1];
            if (row < M) {
                *reinterpret_cast<float2*>(outp + (size_t)row * DIM + col) =
                    make_float2(acc[mt][nt][0] + b0, acc[mt][nt][1] + b1);
                if (row + 8 < M)
                    *reinterpret_cast<float2*>(outp + (size_t)(row + 8) * DIM + col) =
                        make_float2(acc[mt][nt][2] + b0, acc[mt][nt][3] + b1);
            }
        }
    }
}

// ------------------------- K3: fused attention, warp per (b,l) ---------------
// Lane layout: lane16 = lane&15 covers dims [8*lane16, 8*lane16+8);
// sel = lane>>4 picks key parity (even/odd). Two keys per iteration in
// parallel across warp halves. Softmax without max-subtraction.
__global__ void __launch_bounds__(256) k_attn(const int* __restrict__ queries,
                                              const int* __restrict__ keys,
                                              const float* __restrict__ E,
                                              const float* __restrict__ bk,
                                              const float* __restrict__ bv,
                                              int L2, int M) {
    const int t      = threadIdx.x;
    const int w      = t >> 5;
    const int lane   = t & 31;
    const int lane16 = lane & 15;
    const int sel    = lane >> 4;
    const int bl     = blockIdx.x * 8 + w;

    __shared__ uint2 s_km[8][52];       // {byte offset kid*256, mask as float}

    if (bl < M) {
        for (int i = lane; i < L2; i += 32) {
            int kid = keys[bl * L2 + i];
            float m = (g_Esum[kid] == 0.0f) ? 0.0f : 1.0f;
            s_km[w][i] = make_uint2((uint32_t)kid << 8, __float_as_uint(m));
        }
        if (lane == 0 && (L2 & 1)) s_km[w][L2] = make_uint2(0u, 0u);  // pad
    }
    __syncwarp();
    if (bl >= M) return;

    // Q and bk: lane's 8 dims
    const float4* qp  = reinterpret_cast<const float4*>(g_Q + (size_t)bl * DIM + lane16 * 8);
    const float4* bkp = reinterpret_cast<const float4*>(bk + lane16 * 8);
    const float4 qa = qp[0], qb = qp[1];
    const float4 ba = bkp[0], bb = bkp[1];
    // partial q.bk (full head value materializes after the 4-lane reduce)
    float corrp = qa.x * ba.x + qa.y * ba.y + qa.z * ba.z + qa.w * ba.w
                + qb.x * bb.x + qb.y * bb.y + qb.z * bb.z + qb.w * bb.w;

    const float RS = 0.17677669529663687f;   // 1/sqrt(32)
    const char* ekb = reinterpret_cast<const char*>(g_EKbf);
    const char* evb = reinterpret_cast<const char*>(g_EVbf);
    const uint32_t lo16 = lane16 * 16;

    float a0 = 0.f, a1 = 0.f, a2 = 0.f, a3 = 0.f;
    float a4 = 0.f, a5 = 0.f, a6 = 0.f, a7 = 0.f;
    float sumw = 0.f;

    const int np = (L2 + 1) >> 1;
    #pragma unroll 2
    for (int i = 0; i < np; i++) {
        uint2 km = s_km[w][2 * i + sel];
        uint4 kr = *reinterpret_cast<const uint4*>(ekb + km.x + lo16);
        uint4 vr = *reinterpret_cast<const uint4*>(evb + km.x + lo16);
        float p = corrp;
        p = fmaf(qa.x, bflo(kr.x), p); p = fmaf(qa.y, bfhi(kr.x), p);
        p = fmaf(qa.z, bflo(kr.y), p); p = fmaf(qa.w, bfhi(kr.y), p);
        p = fmaf(qb.x, bflo(kr.z), p); p = fmaf(qb.y, bfhi(kr.z), p);
        p = fmaf(qb.z, bflo(kr.w), p); p = fmaf(qb.w, bfhi(kr.w), p);
        p += __shfl_xor_sync(0xffffffffu, p, 1);
        p += __shfl_xor_sync(0xffffffffu, p, 2);
        float wt = __uint_as_float(km.y) * __expf(p * RS);
        a0 = fmaf(wt, bflo(vr.x), a0); a1 = fmaf(wt, bfhi(vr.x), a1);
        a2 = fmaf(wt, bflo(vr.y), a2); a3 = fmaf(wt, bfhi(vr.y), a3);
        a4 = fmaf(wt, bflo(vr.z), a4); a5 = fmaf(wt, bfhi(vr.z), a5);
        a6 = fmaf(wt, bflo(vr.w), a6); a7 = fmaf(wt, bfhi(vr.w), a7);
        sumw += wt;
    }

    // combine parities (xor 16): acc and sumw
    sumw += __shfl_xor_sync(0xffffffffu, sumw, 16);
    a0 += __shfl_xor_sync(0xffffffffu, a0, 16);
    a1 += __shfl_xor_sync(0xffffffffu, a1, 16);
    a2 += __shfl_xor_sync(0xffffffffu, a2, 16);
    a3 += __shfl_xor_sync(0xffffffffu, a3, 16);
    a4 += __shfl_xor_sync(0xffffffffu, a4, 16);
    a5 += __shfl_xor_sync(0xffffffffu, a5, 16);
    a6 += __shfl_xor_sync(0xffffffffu, a6, 16);
    a7 += __shfl_xor_sync(0xffffffffu, a7, 16);

    const float inv = 1.0f / sumw;
    const int   qid = queries[bl];
    const int   d0  = lane16 * 8 + sel * 4;    // lane writes 4 dims
    const float4 bv4 = *reinterpret_cast<const float4*>(bv + d0);
    const float4 qe4 = *reinterpret_cast<const float4*>(E + (size_t)qid * DIM + d0);
    float4 o;
    if (sel == 0) {
        o.x = fmaf(a0, inv, bv4.x + qe4.x);
        o.y = fmaf(a1, inv, bv4.y + qe4.y);
        o.z = fmaf(a2, inv, bv4.z + qe4.z);
        o.w = fmaf(a3, inv, bv4.w + qe4.w);
    } else {
        o.x = fmaf(a4, inv, bv4.x + qe4.x);
        o.y = fmaf(a5, inv, bv4.y + qe4.y);
        o.z = fmaf(a6, inv, bv4.z + qe4.z);
        o.w = fmaf(a7, inv, bv4.w + qe4.w);
    }
    *reinterpret_cast<float4*>(g_res + (size_t)bl * DIM + d0) = o;
}

// ------------------------- launch --------------------------------------------
extern "C" void kernel_launch(void* const* d_in, const int* in_sizes, int n_in,
                              void* d_out, int out_size) {
    const int*   queries = (const int*)d_in[0];
    const int*   keys    = (const int*)d_in[1];
    const float* E       = (const float*)d_in[2];
    const float* Wq      = (const float*)d_in[3];
    const float* bq      = (const float*)d_in[4];
    const float* Wk      = (const float*)d_in[5];
    const float* bk      = (const float*)d_in[6];
    const float* Wv      = (const float*)d_in[7];
    const float* bv      = (const float*)d_in[8];
    const float* Wf      = (const float*)d_in[9];
    const float* bf      = (const float*)d_in[10];
    float* out = (float*)d_out;

    const int V  = in_sizes[2] / DIM;
    const int M  = in_sizes[0];
    const int L2 = in_sizes[1] / M;

    cudaFuncSetAttribute(k_proj_mma, cudaFuncAttributeMaxDynamicSharedMemorySize, PROJ_SMEM);
    cudaFuncSetAttribute(k_gemm_q,   cudaFuncAttributeMaxDynamicSharedMemorySize, GEMMQ_SMEM);
    cudaFuncSetAttribute(k_gemm_f,   cudaFuncAttributeMaxDynamicSharedMemorySize, GEMMF_SMEM);

    k_wprep<<<32, 256>>>(Wk, Wv, Wq, Wf);
    dim3 pg((V + 127) / 128, 2);
    k_proj_mma<<<pg, 512, PROJ_SMEM>>>(E, V);
    k_gemm_q<<<(M + 127) / 128, 512, GEMMQ_SMEM>>>(E, queries, bq, M);
    k_attn<<<(M + 7) / 8, 256>>>(queries, keys, E, bk, bv, L2, M);
    k_gemm_f<<<(M + 127) / 128, 512, GEMMF_SMEM>>>(bf, out, M);
}

// round 9
// speedup vs baseline: 4.6515x; 1.0156x over previous
#include <cuda_runtime.h>
#include <cuda_bf16.h>
#include <cstdint>

#define VOCAB_MAX 100000
#define BL_MAX    12800
#define DIM       128
#define NHEAD     4

// ------------------------- scratch (device globals) -------------------------
__device__ __nv_bfloat16 g_EKbf[VOCAB_MAX * DIM];   // E @ Wk  (bf16)
__device__ __nv_bfloat16 g_EVbf[VOCAB_MAX * DIM];   // E @ Wv  (bf16)
__device__ float g_Esum[VOCAB_MAX];
__device__ float g_Q[BL_MAX * DIM];
__device__ float g_res[BL_MAX * DIM];
// swizzled W^T images (n-major, k contiguous, kc ^= n&7)
__device__ uint4 g_WT16[4096];   // [Wk|Wv] fp16: [n=256][kc=16]
__device__ uint4 g_WQ16[2048];   // Wq fp16:      [n=128][kc=16]
__device__ uint4 g_WFhi[2048];   // Wf bf16 hi
__device__ uint4 g_WFlo[2048];   // Wf bf16 lo

// ------------------------- helpers ------------------------------------------
__device__ __forceinline__ uint32_t smem_to_u32(const void* p) {
    uint32_t a;
    asm("{ .reg .u64 t; cvta.to.shared.u64 t, %1; cvt.u32.u64 %0, t; }" : "=r"(a) : "l"(p));
    return a;
}
__device__ __forceinline__ uint32_t pack_bf2(float lo, float hi) {
    uint32_t r; asm("cvt.rn.bf16x2.f32 %0, %1, %2;" : "=r"(r) : "f"(hi), "f"(lo)); return r;
}
__device__ __forceinline__ uint32_t pack_h2(float lo, float hi) {
    uint32_t r; asm("cvt.rn.f16x2.f32 %0, %1, %2;" : "=r"(r) : "f"(hi), "f"(lo)); return r;
}
__device__ __forceinline__ void ldsm_x4(uint32_t addr, uint32_t* r) {
    asm volatile("ldmatrix.sync.aligned.m8n8.x4.shared.b16 {%0,%1,%2,%3}, [%4];"
                 : "=r"(r[0]), "=r"(r[1]), "=r"(r[2]), "=r"(r[3]) : "r"(addr));
}
__device__ __forceinline__ void mma_bf16(float* c, const uint32_t* a, uint32_t b0, uint32_t b1) {
    asm volatile("mma.sync.aligned.m16n8k16.row.col.f32.bf16.bf16.f32 "
                 "{%0,%1,%2,%3}, {%4,%5,%6,%7}, {%8,%9}, {%0,%1,%2,%3};"
                 : "+f"(c[0]), "+f"(c[1]), "+f"(c[2]), "+f"(c[3])
                 : "r"(a[0]), "r"(a[1]), "r"(a[2]), "r"(a[3]), "r"(b0), "r"(b1));
}
__device__ __forceinline__ void mma_f16(float* c, const uint32_t* a, uint32_t b0, uint32_t b1) {
    asm volatile("mma.sync.aligned.m16n8k16.row.col.f32.f16.f16.f32 "
                 "{%0,%1,%2,%3}, {%4,%5,%6,%7}, {%8,%9}, {%0,%1,%2,%3};"
                 : "+f"(c[0]), "+f"(c[1]), "+f"(c[2]), "+f"(c[3])
                 : "r"(a[0]), "r"(a[1]), "r"(a[2]), "r"(a[3]), "r"(b0), "r"(b1));
}
__device__ __forceinline__ void split2(float x, float y, uint32_t& h, uint32_t& l) {
    h = pack_bf2(x, y);
    l = pack_bf2(x - __uint_as_float(h << 16), y - __uint_as_float(h & 0xffff0000u));
}
__device__ __forceinline__ float bflo(uint32_t u) { return __uint_as_float(u << 16); }
__device__ __forceinline__ float bfhi(uint32_t u) { return __uint_as_float(u & 0xffff0000u); }

// ------------------------- K0: prep all W^T images ---------------------------
__global__ void k_wprep(const float* __restrict__ Wk, const float* __restrict__ Wv,
                        const float* __restrict__ Wq, const float* __restrict__ Wf) {
    int u = blockIdx.x * blockDim.x + threadIdx.x;    // 8192 units
    const float* src;
    int n, kc, kind;
    uint4 *dst16 = nullptr, *dh = nullptr, *dl = nullptr;
    if (u < 4096) {
        n = u & 255; kc = u >> 8; kind = 0;
        src = (n < 128) ? (Wk + n) : (Wv + (n - 128));
        dst16 = g_WT16 + n * 16 + (kc ^ (n & 7));
    } else if (u < 6144) {
        int u2 = u - 4096; n = u2 & 127; kc = u2 >> 7; kind = 1;
        src = Wq + n;
        dst16 = g_WQ16 + n * 16 + (kc ^ (n & 7));
    } else {
        int u2 = u - 6144; n = u2 & 127; kc = u2 >> 7; kind = 2;
        src = Wf + n;
        int idx = n * 16 + (kc ^ (n & 7));
        dh = g_WFhi + idx; dl = g_WFlo + idx;
    }
    float f[8];
    #pragma unroll
    for (int i = 0; i < 8; i++) f[i] = src[(size_t)(kc * 8 + i) * DIM];
    if (kind < 2) {
        uint32_t h[4];
        #pragma unroll
        for (int i = 0; i < 4; i++) h[i] = pack_h2(f[2 * i], f[2 * i + 1]);
        *dst16 = make_uint4(h[0], h[1], h[2], h[3]);
    } else {
        uint32_t h[4], l[4];
        #pragma unroll
        for (int i = 0; i < 4; i++) split2(f[2 * i], f[2 * i + 1], h[i], l[i]);
        *dh = make_uint4(h[0], h[1], h[2], h[3]);
        *dl = make_uint4(l[0], l[1], l[2], l[3]);
    }
}

// ------------------------- K1: fp16 HMMA projection (N-split, 2 CTA/SM) ------
// blockIdx.y = 0 -> EK half of [Wk|Wv], 1 -> EV half. CTA: M=128 x N=128.
#define A_16 0
#define B_16 32768
#define PROJ_SMEM 65536

__global__ void __launch_bounds__(512, 2)
k_proj_mma(const float* __restrict__ E, int V) {
    extern __shared__ char smem[];
    const uint32_t sb = smem_to_u32(smem);
    const int t    = threadIdx.x;
    const int w    = t >> 5;
    const int lane = t & 31;
    const int v0   = blockIdx.x * 128;
    const int y    = blockIdx.y;          // 0 = K half, 1 = V half

    // ---- stage A (fp16) + fused row-sum (y==0 only)
    #pragma unroll
    for (int i = 0; i < 4; i++) {
        int u   = t + 512 * i;
        int row = u >> 4;
        int kc  = u & 15;
        int gr  = v0 + row;
        int grc = (gr < V) ? gr : 0;
        const float4* src = reinterpret_cast<const float4*>(E + (size_t)grc * DIM + kc * 8);
        float4 f0 = src[0], f1 = src[1];
        uint32_t h0 = pack_h2(f0.x, f0.y), h1 = pack_h2(f0.z, f0.w);
        uint32_t h2 = pack_h2(f1.x, f1.y), h3 = pack_h2(f1.z, f1.w);
        uint32_t off = (uint32_t)row * 256 + (uint32_t)((kc ^ (row & 7)) << 4);
        *reinterpret_cast<uint4*>(smem + A_16 + off) = make_uint4(h0, h1, h2, h3);
        if (y == 0) {
            float s8 = ((f0.x + f0.y) + (f0.z + f0.w)) + ((f1.x + f1.y) + (f1.z + f1.w));
            s8 += __shfl_xor_sync(0xffffffffu, s8, 8);
            s8 += __shfl_xor_sync(0xffffffffu, s8, 4);
            s8 += __shfl_xor_sync(0xffffffffu, s8, 2);
            s8 += __shfl_xor_sync(0xffffffffu, s8, 1);
            if ((t & 15) == 0 && gr < V) g_Esum[gr] = s8;
        }
    }
    // ---- stage B: 32KB half image
    {
        uint4* d = reinterpret_cast<uint4*>(smem + B_16);
        const uint4* s = g_WT16 + y * 2048;
        #pragma unroll
        for (int i = 0; i < 4; i++) {
            int idx = t + 512 * i;
            d[idx] = s[idx];
        }
    }
    __syncthreads();

    const int mg = w & 3;
    const int ng = w >> 2;                // 0..3, 32 cols each

    float acc[2][4][4];
    #pragma unroll
    for (int mt = 0; mt < 2; mt++)
        #pragma unroll
        for (int nt = 0; nt < 4; nt++)
            #pragma unroll
            for (int j = 0; j < 4; j++) acc[mt][nt][j] = 0.f;

    const int aRow  = mg * 32 + ((lane >> 3) & 1) * 8 + (lane & 7);
    const int aKsel = (lane >> 4);
    const int bN    = ng * 32 + ((lane >> 4) & 1) * 8 + (lane & 7);
    const int bKsel = (lane >> 3) & 1;

    #pragma unroll
    for (int ks = 0; ks < 8; ks++) {
        uint32_t a[2][4];
        #pragma unroll
        for (int mt = 0; mt < 2; mt++) {
            int row = aRow + mt * 16;
            int kc  = ks * 2 + aKsel;
            ldsm_x4(sb + A_16 + row * 256 + (((kc ^ (row & 7)) << 4)), a[mt]);
        }
        uint32_t b[2][4];
        #pragma unroll
        for (int bt = 0; bt < 2; bt++) {
            int n  = bN + bt * 16;
            int kc = ks * 2 + bKsel;
            ldsm_x4(sb + B_16 + n * 256 + (((kc ^ (n & 7)) << 4)), b[bt]);
        }
        #pragma unroll
        for (int mt = 0; mt < 2; mt++)
            #pragma unroll
            for (int nt = 0; nt < 4; nt++)
                mma_f16(acc[mt][nt], a[mt], b[nt >> 1][(nt & 1) * 2], b[nt >> 1][(nt & 1) * 2 + 1]);
    }

    // ---- epilogue: stage bf16 output in smem (xor-swizzled, conflict-free),
    //      then fully coalesced uint4 copy to gmem.
    __syncthreads();
    #pragma unroll
    for (int mt = 0; mt < 2; mt++) {
        int rl = mg * 32 + mt * 16 + (lane >> 2);
        #pragma unroll
        for (int nt = 0; nt < 4; nt++) {
            int col2 = (ng * 32 + nt * 8 + (lane & 3) * 2) * 2;   // byte offset in row
            uint32_t b0 = pack_bf2(acc[mt][nt][0], acc[mt][nt][1]);
            uint32_t b1 = pack_bf2(acc[mt][nt][2], acc[mt][nt][3]);
            int rl2 = rl + 8;
            *reinterpret_cast<uint32_t*>(smem + B_16 + rl  * 256 + (col2 ^ ((rl  & 7) << 5))) = b0;
            *reinterpret_cast<uint32_t*>(smem + B_16 + rl2 * 256 + (col2 ^ ((rl2 & 7) << 5))) = b1;
        }
    }
    __syncthreads();
    {
        __nv_bfloat16* table = (y == 0) ? g_EKbf : g_EVbf;
        #pragma unroll
        for (int i = 0; i < 4; i++) {
            int idx = t + 512 * i;            // 2048 chunks of 16B
            int row = idx >> 4, c16 = idx & 15;
            int gr = v0 + row;
            if (gr < V) {
                uint4 val = *reinterpret_cast<uint4*>(
                    smem + B_16 + row * 256 + ((c16 * 16) ^ ((row & 7) << 5)));
                reinterpret_cast<uint4*>(table + (size_t)gr * DIM)[c16] = val;
            }
        }
    }
}

// ------------------------- K2a: Q gemm (fp16 single pass, N=128) -------------
#define Q_A 0
#define Q_B 32768
#define GEMMQ_SMEM 65536

__global__ void __launch_bounds__(512)
k_gemm_q(const float* __restrict__ E, const int* __restrict__ queries,
         const float* __restrict__ bq, int M) {
    extern __shared__ char smem[];
    const uint32_t sb = smem_to_u32(smem);
    const int t    = threadIdx.x;
    const int w    = t >> 5;
    const int lane = t & 31;
    const int m0   = blockIdx.x * 128;

    #pragma unroll
    for (int i = 0; i < 4; i++) {
        int u   = t + 512 * i;
        int row = u >> 4;
        int kc  = u & 15;
        int m   = m0 + row;
        int mm  = (m < M) ? m : 0;
        const float4* src = reinterpret_cast<const float4*>(E + (size_t)queries[mm] * DIM + kc * 8);
        float4 f0 = src[0], f1 = src[1];
        uint32_t h0 = pack_h2(f0.x, f0.y), h1 = pack_h2(f0.z, f0.w);
        uint32_t h2 = pack_h2(f1.x, f1.y), h3 = pack_h2(f1.z, f1.w);
        uint32_t off = (uint32_t)row * 256 + (uint32_t)((kc ^ (row & 7)) << 4);
        *reinterpret_cast<uint4*>(smem + Q_A + off) = make_uint4(h0, h1, h2, h3);
    }
    {
        uint4* d = reinterpret_cast<uint4*>(smem + Q_B);
        #pragma unroll
        for (int i = 0; i < 4; i++) {
            int idx = t + 512 * i;
            d[idx] = g_WQ16[idx];
        }
    }
    __syncthreads();

    const int mg = w & 3;
    const int ng = w >> 2;

    float acc[2][4][4];
    #pragma unroll
    for (int mt = 0; mt < 2; mt++)
        #pragma unroll
        for (int nt = 0; nt < 4; nt++)
            #pragma unroll
            for (int j = 0; j < 4; j++) acc[mt][nt][j] = 0.f;

    const int aRow  = mg * 32 + ((lane >> 3) & 1) * 8 + (lane & 7);
    const int aKsel = (lane >> 4);
    const int bN    = ng * 32 + ((lane >> 4) & 1) * 8 + (lane & 7);
    const int bKsel = (lane >> 3) & 1;

    #pragma unroll
    for (int ks = 0; ks < 8; ks++) {
        uint32_t a[2][4];
        #pragma unroll
        for (int mt = 0; mt < 2; mt++) {
            int row = aRow + mt * 16;
            int kc  = ks * 2 + aKsel;
            ldsm_x4(sb + Q_A + row * 256 + (((kc ^ (row & 7)) << 4)), a[mt]);
        }
        uint32_t b[2][4];
        #pragma unroll
        for (int bt = 0; bt < 2; bt++) {
            int n  = bN + bt * 16;
            int kc = ks * 2 + bKsel;
            ldsm_x4(sb + Q_B + n * 256 + (((kc ^ (n & 7)) << 4)), b[bt]);
        }
        #pragma unroll
        for (int mt = 0; mt < 2; mt++)
            #pragma unroll
            for (int nt = 0; nt < 4; nt++)
                mma_f16(acc[mt][nt], a[mt], b[nt >> 1][(nt & 1) * 2], b[nt >> 1][(nt & 1) * 2 + 1]);
    }

    #pragma unroll
    for (int mt = 0; mt < 2; mt++) {
        int row = m0 + mg * 32 + mt * 16 + (lane >> 2);
        #pragma unroll
        for (int nt = 0; nt < 4; nt++) {
            int col = ng * 32 + nt * 8 + (lane & 3) * 2;
            float b0 = bq[col], b1 = bq[col + 1];
            if (row < M) {
                *reinterpret_cast<float2*>(g_Q + (size_t)row * DIM + col) =
                    make_float2(acc[mt][nt][0] + b0, acc[mt][nt][1] + b1);
                if (row + 8 < M)
                    *reinterpret_cast<float2*>(g_Q + (size_t)(row + 8) * DIM + col) =
                        make_float2(acc[mt][nt][2] + b0, acc[mt][nt][3] + b1);
            }
        }
    }
}

// ------------------------- K2b: final gemm (bf16 3-pass, N=128) --------------
#define F_A_HI 0
#define F_A_LO 32768
#define F_B_HI 65536
#define F_B_LO 98304
#define GEMMF_SMEM 131072

__global__ void __launch_bounds__(512)
k_gemm_f(const float* __restrict__ bf, float* __restrict__ outp, int M) {
    extern __shared__ char smem[];
    const uint32_t sb = smem_to_u32(smem);
    const int t    = threadIdx.x;
    const int w    = t >> 5;
    const int lane = t & 31;
    const int m0   = blockIdx.x * 128;

    #pragma unroll
    for (int i = 0; i < 4; i++) {
        int u   = t + 512 * i;
        int row = u >> 4;
        int kc  = u & 15;
        int m   = m0 + row;
        const float4* src = reinterpret_cast<const float4*>(
            g_res + (size_t)((m < M) ? m : 0) * DIM + kc * 8);
        float4 f0 = src[0], f1 = src[1];
        uint32_t h0, h1, h2, h3, l0, l1, l2, l3;
        split2(f0.x, f0.y, h0, l0); split2(f0.z, f0.w, h1, l1);
        split2(f1.x, f1.y, h2, l2); split2(f1.z, f1.w, h3, l3);
        uint32_t off = (uint32_t)row * 256 + (uint32_t)((kc ^ (row & 7)) << 4);
        *reinterpret_cast<uint4*>(smem + F_A_HI + off) = make_uint4(h0, h1, h2, h3);
        *reinterpret_cast<uint4*>(smem + F_A_LO + off) = make_uint4(l0, l1, l2, l3);
    }
    {
        uint4* dh = reinterpret_cast<uint4*>(smem + F_B_HI);
        uint4* dl = reinterpret_cast<uint4*>(smem + F_B_LO);
        #pragma unroll
        for (int i = 0; i < 4; i++) {
            int idx = t + 512 * i;
            dh[idx] = g_WFhi[idx];
            dl[idx] = g_WFlo[idx];
        }
    }
    __syncthreads();

    const int mg = w & 3;
    const int ng = w >> 2;

    float acc[2][4][4];
    #pragma unroll
    for (int mt = 0; mt < 2; mt++)
        #pragma unroll
        for (int nt = 0; nt < 4; nt++)
            #pragma unroll
            for (int j = 0; j < 4; j++) acc[mt][nt][j] = 0.f;

    const int aRow  = mg * 32 + ((lane >> 3) & 1) * 8 + (lane & 7);
    const int aKsel = (lane >> 4);
    const int bN    = ng * 32 + ((lane >> 4) & 1) * 8 + (lane & 7);
    const int bKsel = (lane >> 3) & 1;

    #pragma unroll
    for (int p = 0; p < 3; p++) {
        const uint32_t abase = sb + (p == 2 ? F_A_LO : F_A_HI);
        const uint32_t bbase = sb + (p == 1 ? F_B_LO : F_B_HI);
        #pragma unroll
        for (int ks = 0; ks < 8; ks++) {
            uint32_t a[2][4];
            #pragma unroll
            for (int mt = 0; mt < 2; mt++) {
                int row = aRow + mt * 16;
                int kc  = ks * 2 + aKsel;
                ldsm_x4(abase + row * 256 + (((kc ^ (row & 7)) << 4)), a[mt]);
            }
            uint32_t b[2][4];
            #pragma unroll
            for (int bt = 0; bt < 2; bt++) {
                int n  = bN + bt * 16;
                int kc = ks * 2 + bKsel;
                ldsm_x4(bbase + n * 256 + (((kc ^ (n & 7)) << 4)), b[bt]);
            }
            #pragma unroll
            for (int mt = 0; mt < 2; mt++)
                #pragma unroll
                for (int nt = 0; nt < 4; nt++)
                    mma_bf16(acc[mt][nt], a[mt], b[nt >> 1][(nt & 1) * 2], b[nt >> 1][(nt & 1) * 2 + 1]);
        }
    }

    #pragma unroll
    for (int mt = 0; mt < 2; mt++) {
        int row = m0 + mg * 32 + mt * 16 + (lane >> 2);
        #pragma unroll
        for (int nt = 0; nt < 4; nt++) {
            int col = ng * 32 + nt * 8 + (lane & 3) * 2;
            float b0 = bf[col], b1 = bf[col + 1];
            if (row < M) {
                *reinterpret_cast<float2*>(outp + (size_t)row * DIM + col) =
                    make_float2(acc[mt][nt][0] + b0, acc[mt][nt][1] + b1);
                if (row + 8 < M)
                    *reinterpret_cast<float2*>(outp + (size_t)(row + 8) * DIM + col) =
                        make_float2(acc[mt][nt][2] + b0, acc[mt][nt][3] + b1);
            }
        }
    }
}

// ------------------------- K3: fused attention, 2 warps per (b,l) ------------
// Warp pair (2s, 2s+1) shares bl; half = w&1 picks pair-parity, sel = lane>>4
// picks key parity within pair: key = 4i + 2*half + sel (4-way parallel).
// lane16 covers dims [8*lane16, 8*lane16+8). Softmax without max-subtraction.
__global__ void __launch_bounds__(256) k_attn(const int* __restrict__ queries,
                                              const int* __restrict__ keys,
                                              const float* __restrict__ E,
                                              const float* __restrict__ bk,
                                              const float* __restrict__ bv,
                                              int L2, int M) {
    const int t      = threadIdx.x;
    const int w      = t >> 5;
    const int lane   = t & 31;
    const int lane16 = lane & 15;
    const int sel    = lane >> 4;
    const int slot   = w >> 1;
    const int half   = w & 1;
    const int bl     = blockIdx.x * 4 + slot;

    __shared__ uint2  s_km[4][52];      // {byte offset kid*256, mask as float}
    __shared__ float4 s_pa[8][32];      // per-warp partial (4 dims/lane)
    __shared__ float  s_sw[8];          // per-warp sumw

    if (bl < M) {
        int i = half * 32 + lane;       // warp pair stages 52 entries together
        if (i < 52) {
            uint2 v = make_uint2(0u, 0u);
            if (i < L2) {
                int kid = keys[bl * L2 + i];
                float m = (g_Esum[kid] == 0.0f) ? 0.0f : 1.0f;
                v = make_uint2((uint32_t)kid << 8, __float_as_uint(m));
            }
            s_km[slot][i] = v;
        }
    }
    __syncthreads();

    if (bl < M) {
        const float4* qp  = reinterpret_cast<const float4*>(g_Q + (size_t)bl * DIM + lane16 * 8);
        const float4* bkp = reinterpret_cast<const float4*>(bk + lane16 * 8);
        const float4 qa = qp[0], qb = qp[1];
        const float4 ba = bkp[0], bb = bkp[1];
        float corrp = qa.x * ba.x + qa.y * ba.y + qa.z * ba.z + qa.w * ba.w
                    + qb.x * bb.x + qb.y * bb.y + qb.z * bb.z + qb.w * bb.w;

        const float RS = 0.17677669529663687f;   // 1/sqrt(32)
        const char* ekb = reinterpret_cast<const char*>(g_EKbf);
        const char* evb = reinterpret_cast<const char*>(g_EVbf);
        const uint32_t lo16 = lane16 * 16;
        const int koff = 2 * half + sel;

        float a0 = 0.f, a1 = 0.f, a2 = 0.f, a3 = 0.f;
        float a4 = 0.f, a5 = 0.f, a6 = 0.f, a7 = 0.f;
        float sumw = 0.f;

        const int np = (L2 + 3) >> 2;
        #pragma unroll 2
        for (int i = 0; i < np; i++) {
            uint2 km = s_km[slot][4 * i + koff];
            uint4 kr = *reinterpret_cast<const uint4*>(ekb + km.x + lo16);
            uint4 vr = *reinterpret_cast<const uint4*>(evb + km.x + lo16);
            float p = corrp;
            p = fmaf(qa.x, bflo(kr.x), p); p = fmaf(qa.y, bfhi(kr.x), p);
            p = fmaf(qa.z, bflo(kr.y), p); p = fmaf(qa.w, bfhi(kr.y), p);
            p = fmaf(qb.x, bflo(kr.z), p); p = fmaf(qb.y, bfhi(kr.z), p);
            p = fmaf(qb.z, bflo(kr.w), p); p = fmaf(qb.w, bfhi(kr.w), p);
            p += __shfl_xor_sync(0xffffffffu, p, 1);
            p += __shfl_xor_sync(0xffffffffu, p, 2);
            float wt = __uint_as_float(km.y) * __expf(p * RS);
            a0 = fmaf(wt, bflo(vr.x), a0); a1 = fmaf(wt, bfhi(vr.x), a1);
            a2 = fmaf(wt, bflo(vr.y), a2); a3 = fmaf(wt, bfhi(vr.y), a3);
            a4 = fmaf(wt, bflo(vr.z), a4); a5 = fmaf(wt, bfhi(vr.z), a5);
            a6 = fmaf(wt, bflo(vr.w), a6); a7 = fmaf(wt, bfhi(vr.w), a7);
            sumw += wt;
        }

        // combine sel parities within warp (xor 16)
        sumw += __shfl_xor_sync(0xffffffffu, sumw, 16);
        a0 += __shfl_xor_sync(0xffffffffu, a0, 16);
        a1 += __shfl_xor_sync(0xffffffffu, a1, 16);
        a2 += __shfl_xor_sync(0xffffffffu, a2, 16);
        a3 += __shfl_xor_sync(0xffffffffu, a3, 16);
        a4 += __shfl_xor_sync(0xffffffffu, a4, 16);
        a5 += __shfl_xor_sync(0xffffffffu, a5, 16);
        a6 += __shfl_xor_sync(0xffffffffu, a6, 16);
        a7 += __shfl_xor_sync(0xffffffffu, a7, 16);

        s_pa[w][lane] = (sel == 0) ? make_float4(a0, a1, a2, a3)
                                   : make_float4(a4, a5, a6, a7);
        if (lane == 0) s_sw[w] = sumw;
    }
    __syncthreads();

    if (bl < M && half == 0) {
        float4 pA = s_pa[w][lane];
        float4 pB = s_pa[w + 1][lane];
        float inv = 1.0f / (s_sw[w] + s_sw[w + 1]);
        const int qid = queries[bl];
        const int d0  = lane16 * 8 + sel * 4;
        const float4 bv4 = *reinterpret_cast<const float4*>(bv + d0);
        const float4 qe4 = *reinterpret_cast<const float4*>(E + (size_t)qid * DIM + d0);
        float4 o;
        o.x = fmaf(pA.x + pB.x, inv, bv4.x + qe4.x);
        o.y = fmaf(pA.y + pB.y, inv, bv4.y + qe4.y);
        o.z = fmaf(pA.z + pB.z, inv, bv4.z + qe4.z);
        o.w = fmaf(pA.w + pB.w, inv, bv4.w + qe4.w);
        *reinterpret_cast<float4*>(g_res + (size_t)bl * DIM + d0) = o;
    }
}

// ------------------------- launch --------------------------------------------
extern "C" void kernel_launch(void* const* d_in, const int* in_sizes, int n_in,
                              void* d_out, int out_size) {
    const int*   queries = (const int*)d_in[0];
    const int*   keys    = (const int*)d_in[1];
    const float* E       = (const float*)d_in[2];
    const float* Wq      = (const float*)d_in[3];
    const float* bq      = (const float*)d_in[4];
    const float* Wk      = (const float*)d_in[5];
    const float* bk      = (const float*)d_in[6];
    const float* Wv      = (const float*)d_in[7];
    const float* bv      = (const float*)d_in[8];
    const float* Wf      = (const float*)d_in[9];
    const float* bf      = (const float*)d_in[10];
    float* out = (float*)d_out;

    const int V  = in_sizes[2] / DIM;
    const int M  = in_sizes[0];
    const int L2 = in_sizes[1] / M;

    cudaFuncSetAttribute(k_proj_mma, cudaFuncAttributeMaxDynamicSharedMemorySize, PROJ_SMEM);
    cudaFuncSetAttribute(k_gemm_q,   cudaFuncAttributeMaxDynamicSharedMemorySize, GEMMQ_SMEM);
    cudaFuncSetAttribute(k_gemm_f,   cudaFuncAttributeMaxDynamicSharedMemorySize, GEMMF_SMEM);

    k_wprep<<<32, 256>>>(Wk, Wv, Wq, Wf);
    dim3 pg((V + 127) / 128, 2);
    k_proj_mma<<<pg, 512, PROJ_SMEM>>>(E, V);
    k_gemm_q<<<(M + 127) / 128, 512, GEMMQ_SMEM>>>(E, queries, bq, M);
    k_attn<<<(M + 3) / 4, 256>>>(queries, keys, E, bk, bv, L2, M);
    k_gemm_f<<<(M + 127) / 128, 512, GEMMF_SMEM>>>(bf, out, M);
}

// round 10
// speedup vs baseline: 5.0472x; 1.0851x over previous
#include <cuda_runtime.h>
#include <cuda_bf16.h>
#include <cstdint>

#define VOCAB_MAX 100000
#define BL_MAX    12800
#define DIM       128
#define NHEAD     4

// ------------------------- scratch (device globals) -------------------------
__device__ __nv_bfloat16 g_EKbf[VOCAB_MAX * DIM];   // E @ Wk  (bf16)
__device__ __nv_bfloat16 g_EVbf[VOCAB_MAX * DIM];   // E @ Wv  (bf16)
__device__ float g_Esum[VOCAB_MAX];
__device__ float g_Q[BL_MAX * DIM];
__device__ float g_res[BL_MAX * DIM];
// swizzled W^T images (n-major, k contiguous, kc ^= n&7)
__device__ uint4 g_WT16[4096];   // [Wk|Wv] fp16: [n=256][kc=16]
__device__ uint4 g_WQ16[2048];   // Wq fp16:      [n=128][kc=16]
__device__ uint4 g_WFhi[2048];   // Wf bf16 hi
__device__ uint4 g_WFlo[2048];   // Wf bf16 lo

// ------------------------- helpers ------------------------------------------
__device__ __forceinline__ uint32_t smem_to_u32(const void* p) {
    uint32_t a;
    asm("{ .reg .u64 t; cvta.to.shared.u64 t, %1; cvt.u32.u64 %0, t; }" : "=r"(a) : "l"(p));
    return a;
}
__device__ __forceinline__ uint32_t pack_bf2(float lo, float hi) {
    uint32_t r; asm("cvt.rn.bf16x2.f32 %0, %1, %2;" : "=r"(r) : "f"(hi), "f"(lo)); return r;
}
__device__ __forceinline__ uint32_t pack_h2(float lo, float hi) {
    uint32_t r; asm("cvt.rn.f16x2.f32 %0, %1, %2;" : "=r"(r) : "f"(hi), "f"(lo)); return r;
}
__device__ __forceinline__ void ldsm_x4(uint32_t addr, uint32_t* r) {
    asm volatile("ldmatrix.sync.aligned.m8n8.x4.shared.b16 {%0,%1,%2,%3}, [%4];"
                 : "=r"(r[0]), "=r"(r[1]), "=r"(r[2]), "=r"(r[3]) : "r"(addr));
}
__device__ __forceinline__ void mma_bf16(float* c, const uint32_t* a, uint32_t b0, uint32_t b1) {
    asm volatile("mma.sync.aligned.m16n8k16.row.col.f32.bf16.bf16.f32 "
                 "{%0,%1,%2,%3}, {%4,%5,%6,%7}, {%8,%9}, {%0,%1,%2,%3};"
                 : "+f"(c[0]), "+f"(c[1]), "+f"(c[2]), "+f"(c[3])
                 : "r"(a[0]), "r"(a[1]), "r"(a[2]), "r"(a[3]), "r"(b0), "r"(b1));
}
__device__ __forceinline__ void mma_f16(float* c, const uint32_t* a, uint32_t b0, uint32_t b1) {
    asm volatile("mma.sync.aligned.m16n8k16.row.col.f32.f16.f16.f32 "
                 "{%0,%1,%2,%3}, {%4,%5,%6,%7}, {%8,%9}, {%0,%1,%2,%3};"
                 : "+f"(c[0]), "+f"(c[1]), "+f"(c[2]), "+f"(c[3])
                 : "r"(a[0]), "r"(a[1]), "r"(a[2]), "r"(a[3]), "r"(b0), "r"(b1));
}
__device__ __forceinline__ void split2(float x, float y, uint32_t& h, uint32_t& l) {
    h = pack_bf2(x, y);
    l = pack_bf2(x - __uint_as_float(h << 16), y - __uint_as_float(h & 0xffff0000u));
}
__device__ __forceinline__ float bflo(uint32_t u) { return __uint_as_float(u << 16); }
__device__ __forceinline__ float bfhi(uint32_t u) { return __uint_as_float(u & 0xffff0000u); }

// ------------------------- K0: prep all W^T images ---------------------------
__global__ void k_wprep(const float* __restrict__ Wk, const float* __restrict__ Wv,
                        const float* __restrict__ Wq, const float* __restrict__ Wf) {
    int u = blockIdx.x * blockDim.x + threadIdx.x;    // 8192 units
    const float* src;
    int n, kc, kind;
    uint4 *dst16 = nullptr, *dh = nullptr, *dl = nullptr;
    if (u < 4096) {
        n = u & 255; kc = u >> 8; kind = 0;
        src = (n < 128) ? (Wk + n) : (Wv + (n - 128));
        dst16 = g_WT16 + n * 16 + (kc ^ (n & 7));
    } else if (u < 6144) {
        int u2 = u - 4096; n = u2 & 127; kc = u2 >> 7; kind = 1;
        src = Wq + n;
        dst16 = g_WQ16 + n * 16 + (kc ^ (n & 7));
    } else {
        int u2 = u - 6144; n = u2 & 127; kc = u2 >> 7; kind = 2;
        src = Wf + n;
        int idx = n * 16 + (kc ^ (n & 7));
        dh = g_WFhi + idx; dl = g_WFlo + idx;
    }
    float f[8];
    #pragma unroll
    for (int i = 0; i < 8; i++) f[i] = src[(size_t)(kc * 8 + i) * DIM];
    if (kind < 2) {
        uint32_t h[4];
        #pragma unroll
        for (int i = 0; i < 4; i++) h[i] = pack_h2(f[2 * i], f[2 * i + 1]);
        *dst16 = make_uint4(h[0], h[1], h[2], h[3]);
    } else {
        uint32_t h[4], l[4];
        #pragma unroll
        for (int i = 0; i < 4; i++) split2(f[2 * i], f[2 * i + 1], h[i], l[i]);
        *dh = make_uint4(h[0], h[1], h[2], h[3]);
        *dl = make_uint4(l[0], l[1], l[2], l[3]);
    }
}

// ------------------------- K1: fp16 HMMA projection (N-split, 2 CTA/SM) ------
#define A_16 0
#define B_16 32768
#define PROJ_SMEM 65536

__global__ void __launch_bounds__(512, 2)
k_proj_mma(const float* __restrict__ E, int V) {
    extern __shared__ char smem[];
    const uint32_t sb = smem_to_u32(smem);
    const int t    = threadIdx.x;
    const int w    = t >> 5;
    const int lane = t & 31;
    const int v0   = blockIdx.x * 128;
    const int y    = blockIdx.y;          // 0 = K half, 1 = V half

    #pragma unroll
    for (int i = 0; i < 4; i++) {
        int u   = t + 512 * i;
        int row = u >> 4;
        int kc  = u & 15;
        int gr  = v0 + row;
        int grc = (gr < V) ? gr : 0;
        const float4* src = reinterpret_cast<const float4*>(E + (size_t)grc * DIM + kc * 8);
        float4 f0 = src[0], f1 = src[1];
        uint32_t h0 = pack_h2(f0.x, f0.y), h1 = pack_h2(f0.z, f0.w);
        uint32_t h2 = pack_h2(f1.x, f1.y), h3 = pack_h2(f1.z, f1.w);
        uint32_t off = (uint32_t)row * 256 + (uint32_t)((kc ^ (row & 7)) << 4);
        *reinterpret_cast<uint4*>(smem + A_16 + off) = make_uint4(h0, h1, h2, h3);
        if (y == 0) {
            float s8 = ((f0.x + f0.y) + (f0.z + f0.w)) + ((f1.x + f1.y) + (f1.z + f1.w));
            s8 += __shfl_xor_sync(0xffffffffu, s8, 8);
            s8 += __shfl_xor_sync(0xffffffffu, s8, 4);
            s8 += __shfl_xor_sync(0xffffffffu, s8, 2);
            s8 += __shfl_xor_sync(0xffffffffu, s8, 1);
            if ((t & 15) == 0 && gr < V) g_Esum[gr] = s8;
        }
    }
    {
        uint4* d = reinterpret_cast<uint4*>(smem + B_16);
        const uint4* s = g_WT16 + y * 2048;
        #pragma unroll
        for (int i = 0; i < 4; i++) {
            int idx = t + 512 * i;
            d[idx] = s[idx];
        }
    }
    __syncthreads();

    const int mg = w & 3;
    const int ng = w >> 2;

    float acc[2][4][4];
    #pragma unroll
    for (int mt = 0; mt < 2; mt++)
        #pragma unroll
        for (int nt = 0; nt < 4; nt++)
            #pragma unroll
            for (int j = 0; j < 4; j++) acc[mt][nt][j] = 0.f;

    const int aRow  = mg * 32 + ((lane >> 3) & 1) * 8 + (lane & 7);
    const int aKsel = (lane >> 4);
    const int bN    = ng * 32 + ((lane >> 4) & 1) * 8 + (lane & 7);
    const int bKsel = (lane >> 3) & 1;

    #pragma unroll
    for (int ks = 0; ks < 8; ks++) {
        uint32_t a[2][4];
        #pragma unroll
        for (int mt = 0; mt < 2; mt++) {
            int row = aRow + mt * 16;
            int kc  = ks * 2 + aKsel;
            ldsm_x4(sb + A_16 + row * 256 + (((kc ^ (row & 7)) << 4)), a[mt]);
        }
        uint32_t b[2][4];
        #pragma unroll
        for (int bt = 0; bt < 2; bt++) {
            int n  = bN + bt * 16;
            int kc = ks * 2 + bKsel;
            ldsm_x4(sb + B_16 + n * 256 + (((kc ^ (n & 7)) << 4)), b[bt]);
        }
        #pragma unroll
        for (int mt = 0; mt < 2; mt++)
            #pragma unroll
            for (int nt = 0; nt < 4; nt++)
                mma_f16(acc[mt][nt], a[mt], b[nt >> 1][(nt & 1) * 2], b[nt >> 1][(nt & 1) * 2 + 1]);
    }

    // epilogue: swizzled smem staging + coalesced copy
    __syncthreads();
    #pragma unroll
    for (int mt = 0; mt < 2; mt++) {
        int rl = mg * 32 + mt * 16 + (lane >> 2);
        #pragma unroll
        for (int nt = 0; nt < 4; nt++) {
            int col2 = (ng * 32 + nt * 8 + (lane & 3) * 2) * 2;
            uint32_t b0 = pack_bf2(acc[mt][nt][0], acc[mt][nt][1]);
            uint32_t b1 = pack_bf2(acc[mt][nt][2], acc[mt][nt][3]);
            int rl2 = rl + 8;
            *reinterpret_cast<uint32_t*>(smem + B_16 + rl  * 256 + (col2 ^ ((rl  & 7) << 5))) = b0;
            *reinterpret_cast<uint32_t*>(smem + B_16 + rl2 * 256 + (col2 ^ ((rl2 & 7) << 5))) = b1;
        }
    }
    __syncthreads();
    {
        __nv_bfloat16* table = (y == 0) ? g_EKbf : g_EVbf;
        #pragma unroll
        for (int i = 0; i < 4; i++) {
            int idx = t + 512 * i;
            int row = idx >> 4, c16 = idx & 15;
            int gr = v0 + row;
            if (gr < V) {
                uint4 val = *reinterpret_cast<uint4*>(
                    smem + B_16 + row * 256 + ((c16 * 16) ^ ((row & 7) << 5)));
                reinterpret_cast<uint4*>(table + (size_t)gr * DIM)[c16] = val;
            }
        }
    }
}

// ------------------------- K2a: Q gemm (fp16 single pass, N=128) -------------
#define Q_A 0
#define Q_B 32768
#define GEMMQ_SMEM 65536

__global__ void __launch_bounds__(512)
k_gemm_q(const float* __restrict__ E, const int* __restrict__ queries,
         const float* __restrict__ bq, int M) {
    extern __shared__ char smem[];
    const uint32_t sb = smem_to_u32(smem);
    const int t    = threadIdx.x;
    const int w    = t >> 5;
    const int lane = t & 31;
    const int m0   = blockIdx.x * 128;

    #pragma unroll
    for (int i = 0; i < 4; i++) {
        int u   = t + 512 * i;
        int row = u >> 4;
        int kc  = u & 15;
        int m   = m0 + row;
        int mm  = (m < M) ? m : 0;
        const float4* src = reinterpret_cast<const float4*>(E + (size_t)queries[mm] * DIM + kc * 8);
        float4 f0 = src[0], f1 = src[1];
        uint32_t h0 = pack_h2(f0.x, f0.y), h1 = pack_h2(f0.z, f0.w);
        uint32_t h2 = pack_h2(f1.x, f1.y), h3 = pack_h2(f1.z, f1.w);
        uint32_t off = (uint32_t)row * 256 + (uint32_t)((kc ^ (row & 7)) << 4);
        *reinterpret_cast<uint4*>(smem + Q_A + off) = make_uint4(h0, h1, h2, h3);
    }
    {
        uint4* d = reinterpret_cast<uint4*>(smem + Q_B);
        #pragma unroll
        for (int i = 0; i < 4; i++) {
            int idx = t + 512 * i;
            d[idx] = g_WQ16[idx];
        }
    }
    __syncthreads();

    const int mg = w & 3;
    const int ng = w >> 2;

    float acc[2][4][4];
    #pragma unroll
    for (int mt = 0; mt < 2; mt++)
        #pragma unroll
        for (int nt = 0; nt < 4; nt++)
            #pragma unroll
            for (int j = 0; j < 4; j++) acc[mt][nt][j] = 0.f;

    const int aRow  = mg * 32 + ((lane >> 3) & 1) * 8 + (lane & 7);
    const int aKsel = (lane >> 4);
    const int bN    = ng * 32 + ((lane >> 4) & 1) * 8 + (lane & 7);
    const int bKsel = (lane >> 3) & 1;

    #pragma unroll
    for (int ks = 0; ks < 8; ks++) {
        uint32_t a[2][4];
        #pragma unroll
        for (int mt = 0; mt < 2; mt++) {
            int row = aRow + mt * 16;
            int kc  = ks * 2 + aKsel;
            ldsm_x4(sb + Q_A + row * 256 + (((kc ^ (row & 7)) << 4)), a[mt]);
        }
        uint32_t b[2][4];
        #pragma unroll
        for (int bt = 0; bt < 2; bt++) {
            int n  = bN + bt * 16;
            int kc = ks * 2 + bKsel;
            ldsm_x4(sb + Q_B + n * 256 + (((kc ^ (n & 7)) << 4)), b[bt]);
        }
        #pragma unroll
        for (int mt = 0; mt < 2; mt++)
            #pragma unroll
            for (int nt = 0; nt < 4; nt++)
                mma_f16(acc[mt][nt], a[mt], b[nt >> 1][(nt & 1) * 2], b[nt >> 1][(nt & 1) * 2 + 1]);
    }

    #pragma unroll
    for (int mt = 0; mt < 2; mt++) {
        int row = m0 + mg * 32 + mt * 16 + (lane >> 2);
        #pragma unroll
        for (int nt = 0; nt < 4; nt++) {
            int col = ng * 32 + nt * 8 + (lane & 3) * 2;
            float b0 = bq[col], b1 = bq[col + 1];
            if (row < M) {
                *reinterpret_cast<float2*>(g_Q + (size_t)row * DIM + col) =
                    make_float2(acc[mt][nt][0] + b0, acc[mt][nt][1] + b1);
                if (row + 8 < M)
                    *reinterpret_cast<float2*>(g_Q + (size_t)(row + 8) * DIM + col) =
                        make_float2(acc[mt][nt][2] + b0, acc[mt][nt][3] + b1);
            }
        }
    }
}

// ------------------------- K2b: final gemm (bf16 3-pass, N=128) --------------
#define F_A_HI 0
#define F_A_LO 32768
#define F_B_HI 65536
#define F_B_LO 98304
#define GEMMF_SMEM 131072

__global__ void __launch_bounds__(512)
k_gemm_f(const float* __restrict__ bf, float* __restrict__ outp, int M) {
    extern __shared__ char smem[];
    const uint32_t sb = smem_to_u32(smem);
    const int t    = threadIdx.x;
    const int w    = t >> 5;
    const int lane = t & 31;
    const int m0   = blockIdx.x * 128;

    #pragma unroll
    for (int i = 0; i < 4; i++) {
        int u   = t + 512 * i;
        int row = u >> 4;
        int kc  = u & 15;
        int m   = m0 + row;
        const float4* src = reinterpret_cast<const float4*>(
            g_res + (size_t)((m < M) ? m : 0) * DIM + kc * 8);
        float4 f0 = src[0], f1 = src[1];
        uint32_t h0, h1, h2, h3, l0, l1, l2, l3;
        split2(f0.x, f0.y, h0, l0); split2(f0.z, f0.w, h1, l1);
        split2(f1.x, f1.y, h2, l2); split2(f1.z, f1.w, h3, l3);
        uint32_t off = (uint32_t)row * 256 + (uint32_t)((kc ^ (row & 7)) << 4);
        *reinterpret_cast<uint4*>(smem + F_A_HI + off) = make_uint4(h0, h1, h2, h3);
        *reinterpret_cast<uint4*>(smem + F_A_LO + off) = make_uint4(l0, l1, l2, l3);
    }
    {
        uint4* dh = reinterpret_cast<uint4*>(smem + F_B_HI);
        uint4* dl = reinterpret_cast<uint4*>(smem + F_B_LO);
        #pragma unroll
        for (int i = 0; i < 4; i++) {
            int idx = t + 512 * i;
            dh[idx] = g_WFhi[idx];
            dl[idx] = g_WFlo[idx];
        }
    }
    __syncthreads();

    const int mg = w & 3;
    const int ng = w >> 2;

    float acc[2][4][4];
    #pragma unroll
    for (int mt = 0; mt < 2; mt++)
        #pragma unroll
        for (int nt = 0; nt < 4; nt++)
            #pragma unroll
            for (int j = 0; j < 4; j++) acc[mt][nt][j] = 0.f;

    const int aRow  = mg * 32 + ((lane >> 3) & 1) * 8 + (lane & 7);
    const int aKsel = (lane >> 4);
    const int bN    = ng * 32 + ((lane >> 4) & 1) * 8 + (lane & 7);
    const int bKsel = (lane >> 3) & 1;

    #pragma unroll
    for (int p = 0; p < 3; p++) {
        const uint32_t abase = sb + (p == 2 ? F_A_LO : F_A_HI);
        const uint32_t bbase = sb + (p == 1 ? F_B_LO : F_B_HI);
        #pragma unroll
        for (int ks = 0; ks < 8; ks++) {
            uint32_t a[2][4];
            #pragma unroll
            for (int mt = 0; mt < 2; mt++) {
                int row = aRow + mt * 16;
                int kc  = ks * 2 + aKsel;
                ldsm_x4(abase + row * 256 + (((kc ^ (row & 7)) << 4)), a[mt]);
            }
            uint32_t b[2][4];
            #pragma unroll
            for (int bt = 0; bt < 2; bt++) {
                int n  = bN + bt * 16;
                int kc = ks * 2 + bKsel;
                ldsm_x4(bbase + n * 256 + (((kc ^ (n & 7)) << 4)), b[bt]);
            }
            #pragma unroll
            for (int mt = 0; mt < 2; mt++)
                #pragma unroll
                for (int nt = 0; nt < 4; nt++)
                    mma_bf16(acc[mt][nt], a[mt], b[nt >> 1][(nt & 1) * 2], b[nt >> 1][(nt & 1) * 2 + 1]);
        }
    }

    #pragma unroll
    for (int mt = 0; mt < 2; mt++) {
        int row = m0 + mg * 32 + mt * 16 + (lane >> 2);
        #pragma unroll
        for (int nt = 0; nt < 4; nt++) {
            int col = ng * 32 + nt * 8 + (lane & 3) * 2;
            float b0 = bf[col], b1 = bf[col + 1];
            if (row < M) {
                *reinterpret_cast<float2*>(outp + (size_t)row * DIM + col) =
                    make_float2(acc[mt][nt][0] + b0, acc[mt][nt][1] + b1);
                if (row + 8 < M)
                    *reinterpret_cast<float2*>(outp + (size_t)(row + 8) * DIM + col) =
                        make_float2(acc[mt][nt][2] + b0, acc[mt][nt][3] + b1);
            }
        }
    }
}

// ------------------------- K3: fused attention, warp per (b,l), dual chain ---
// lane16 covers dims [8*lane16, +8); sel = lane>>4 picks key parity.
// Each iteration processes keys 4i+sel and 4i+2+sel (two independent score
// chains, shared accumulators). Keys padded to multiple of 4 with mask=0.
__global__ void __launch_bounds__(256) k_attn(const int* __restrict__ queries,
                                              const int* __restrict__ keys,
                                              const float* __restrict__ E,
                                              const float* __restrict__ bk,
                                              const float* __restrict__ bv,
                                              int L2, int M) {
    const int t      = threadIdx.x;
    const int w      = t >> 5;
    const int lane   = t & 31;
    const int lane16 = lane & 15;
    const int sel    = lane >> 4;
    const int bl     = blockIdx.x * 8 + w;

    __shared__ uint2 s_km[8][52];       // {byte offset kid*256, mask as float}

    if (bl < M) {
        for (int i = lane; i < 52; i += 32) {
            uint2 v = make_uint2(0u, 0u);
            if (i < L2) {
                int kid = keys[bl * L2 + i];
                float m = (g_Esum[kid] == 0.0f) ? 0.0f : 1.0f;
                v = make_uint2((uint32_t)kid << 8, __float_as_uint(m));
            }
            s_km[w][i] = v;
        }
    }
    __syncwarp();
    if (bl >= M) return;

    const float4* qp  = reinterpret_cast<const float4*>(g_Q + (size_t)bl * DIM + lane16 * 8);
    const float4* bkp = reinterpret_cast<const float4*>(bk + lane16 * 8);
    const float4 qa = qp[0], qb = qp[1];
    const float4 ba = bkp[0], bb = bkp[1];
    float corrp = qa.x * ba.x + qa.y * ba.y + qa.z * ba.z + qa.w * ba.w
                + qb.x * bb.x + qb.y * bb.y + qb.z * bb.z + qb.w * bb.w;

    const float RS = 0.17677669529663687f;   // 1/sqrt(32)
    const char* ekb = reinterpret_cast<const char*>(g_EKbf);
    const char* evb = reinterpret_cast<const char*>(g_EVbf);
    const uint32_t lo16 = lane16 * 16;

    float a0 = 0.f, a1 = 0.f, a2 = 0.f, a3 = 0.f;
    float a4 = 0.f, a5 = 0.f, a6 = 0.f, a7 = 0.f;
    float sumw = 0.f;

    const int np = (L2 + 3) >> 2;
    for (int i = 0; i < np; i++) {
        uint2 km0 = s_km[w][4 * i + sel];
        uint2 km1 = s_km[w][4 * i + 2 + sel];
        uint4 kr0 = *reinterpret_cast<const uint4*>(ekb + km0.x + lo16);
        uint4 kr1 = *reinterpret_cast<const uint4*>(ekb + km1.x + lo16);
        uint4 vr0 = *reinterpret_cast<const uint4*>(evb + km0.x + lo16);
        uint4 vr1 = *reinterpret_cast<const uint4*>(evb + km1.x + lo16);
        float p0 = corrp, p1 = corrp;
        p0 = fmaf(qa.x, bflo(kr0.x), p0); p1 = fmaf(qa.x, bflo(kr1.x), p1);
        p0 = fmaf(qa.y, bfhi(kr0.x), p0); p1 = fmaf(qa.y, bfhi(kr1.x), p1);
        p0 = fmaf(qa.z, bflo(kr0.y), p0); p1 = fmaf(qa.z, bflo(kr1.y), p1);
        p0 = fmaf(qa.w, bfhi(kr0.y), p0); p1 = fmaf(qa.w, bfhi(kr1.y), p1);
        p0 = fmaf(qb.x, bflo(kr0.z), p0); p1 = fmaf(qb.x, bflo(kr1.z), p1);
        p0 = fmaf(qb.y, bfhi(kr0.z), p0); p1 = fmaf(qb.y, bfhi(kr1.z), p1);
        p0 = fmaf(qb.z, bflo(kr0.w), p0); p1 = fmaf(qb.z, bflo(kr1.w), p1);
        p0 = fmaf(qb.w, bfhi(kr0.w), p0); p1 = fmaf(qb.w, bfhi(kr1.w), p1);
        p0 += __shfl_xor_sync(0xffffffffu, p0, 1);
        p1 += __shfl_xor_sync(0xffffffffu, p1, 1);
        p0 += __shfl_xor_sync(0xffffffffu, p0, 2);
        p1 += __shfl_xor_sync(0xffffffffu, p1, 2);
        float w0 = __uint_as_float(km0.y) * __expf(p0 * RS);
        float w1 = __uint_as_float(km1.y) * __expf(p1 * RS);
        a0 = fmaf(w0, bflo(vr0.x), a0); a0 = fmaf(w1, bflo(vr1.x), a0);
        a1 = fmaf(w0, bfhi(vr0.x), a1); a1 = fmaf(w1, bfhi(vr1.x), a1);
        a2 = fmaf(w0, bflo(vr0.y), a2); a2 = fmaf(w1, bflo(vr1.y), a2);
        a3 = fmaf(w0, bfhi(vr0.y), a3); a3 = fmaf(w1, bfhi(vr1.y), a3);
        a4 = fmaf(w0, bflo(vr0.z), a4); a4 = fmaf(w1, bflo(vr1.z), a4);
        a5 = fmaf(w0, bfhi(vr0.z), a5); a5 = fmaf(w1, bfhi(vr1.z), a5);
        a6 = fmaf(w0, bflo(vr0.w), a6); a6 = fmaf(w1, bflo(vr1.w), a6);
        a7 = fmaf(w0, bfhi(vr0.w), a7); a7 = fmaf(w1, bfhi(vr1.w), a7);
        sumw += w0 + w1;
    }

    // combine parities (xor 16)
    sumw += __shfl_xor_sync(0xffffffffu, sumw, 16);
    a0 += __shfl_xor_sync(0xffffffffu, a0, 16);
    a1 += __shfl_xor_sync(0xffffffffu, a1, 16);
    a2 += __shfl_xor_sync(0xffffffffu, a2, 16);
    a3 += __shfl_xor_sync(0xffffffffu, a3, 16);
    a4 += __shfl_xor_sync(0xffffffffu, a4, 16);
    a5 += __shfl_xor_sync(0xffffffffu, a5, 16);
    a6 += __shfl_xor_sync(0xffffffffu, a6, 16);
    a7 += __shfl_xor_sync(0xffffffffu, a7, 16);

    const float inv = 1.0f / sumw;
    const int   qid = queries[bl];
    const int   d0  = lane16 * 8 + sel * 4;
    const float4 bv4 = *reinterpret_cast<const float4*>(bv + d0);
    const float4 qe4 = *reinterpret_cast<const float4*>(E + (size_t)qid * DIM + d0);
    float4 o;
    if (sel == 0) {
        o.x = fmaf(a0, inv, bv4.x + qe4.x);
        o.y = fmaf(a1, inv, bv4.y + qe4.y);
        o.z = fmaf(a2, inv, bv4.z + qe4.z);
        o.w = fmaf(a3, inv, bv4.w + qe4.w);
    } else {
        o.x = fmaf(a4, inv, bv4.x + qe4.x);
        o.y = fmaf(a5, inv, bv4.y + qe4.y);
        o.z = fmaf(a6, inv, bv4.z + qe4.z);
        o.w = fmaf(a7, inv, bv4.w + qe4.w);
    }
    *reinterpret_cast<float4*>(g_res + (size_t)bl * DIM + d0) = o;
}

// ------------------------- launch --------------------------------------------
extern "C" void kernel_launch(void* const* d_in, const int* in_sizes, int n_in,
                              void* d_out, int out_size) {
    const int*   queries = (const int*)d_in[0];
    const int*   keys    = (const int*)d_in[1];
    const float* E       = (const float*)d_in[2];
    const float* Wq      = (const float*)d_in[3];
    const float* bq      = (const float*)d_in[4];
    const float* Wk      = (const float*)d_in[5];
    const float* bk      = (const float*)d_in[6];
    const float* Wv      = (const float*)d_in[7];
    const float* bv      = (const float*)d_in[8];
    const float* Wf      = (const float*)d_in[9];
    const float* bf      = (const float*)d_in[10];
    float* out = (float*)d_out;

    const int V  = in_sizes[2] / DIM;
    const int M  = in_sizes[0];
    const int L2 = in_sizes[1] / M;

    cudaFuncSetAttribute(k_proj_mma, cudaFuncAttributeMaxDynamicSharedMemorySize, PROJ_SMEM);
    cudaFuncSetAttribute(k_gemm_q,   cudaFuncAttributeMaxDynamicSharedMemorySize, GEMMQ_SMEM);
    cudaFuncSetAttribute(k_gemm_f,   cudaFuncAttributeMaxDynamicSharedMemorySize, GEMMF_SMEM);

    k_wprep<<<32, 256>>>(Wk, Wv, Wq, Wf);
    // gemm_q BEFORE proj: its streaming read of E would otherwise evict the
    // freshly written EK/EV tables from L2 right before k_attn gathers them.
    k_gemm_q<<<(M + 127) / 128, 512, GEMMQ_SMEM>>>(E, queries, bq, M);
    dim3 pg((V + 127) / 128, 2);
    k_proj_mma<<<pg, 512, PROJ_SMEM>>>(E, V);
    k_attn<<<(M + 7) / 8, 256>>>(queries, keys, E, bk, bv, L2, M);
    k_gemm_f<<<(M + 127) / 128, 512, GEMMF_SMEM>>>(bf, out, M);
}

// round 11
// speedup vs baseline: 5.0489x; 1.0003x over previous
#include <cuda_runtime.h>
#include <cuda_bf16.h>
#include <cstdint>

#define VOCAB_MAX 100000
#define BL_MAX    12800
#define DIM       128
#define NHEAD     4

// ------------------------- scratch (device globals) -------------------------
__device__ __nv_bfloat16 g_EKbf[VOCAB_MAX * DIM];   // E @ Wk  (bf16)
__device__ __nv_bfloat16 g_EVbf[VOCAB_MAX * DIM];   // E @ Wv  (bf16)
__device__ float g_Esum[VOCAB_MAX];
__device__ float g_Q[BL_MAX * DIM];
__device__ float g_res[BL_MAX * DIM];
// swizzled W^T images (n-major, k contiguous, kc ^= n&7)
__device__ uint4 g_WT16[4096];   // [Wk|Wv] fp16: [n=256][kc=16]
__device__ uint4 g_WQ16[2048];   // Wq fp16:      [n=128][kc=16]
__device__ uint4 g_WFhi[2048];   // Wf bf16 hi
__device__ uint4 g_WFlo[2048];   // Wf bf16 lo

// ------------------------- helpers ------------------------------------------
__device__ __forceinline__ uint32_t smem_to_u32(const void* p) {
    uint32_t a;
    asm("{ .reg .u64 t; cvta.to.shared.u64 t, %1; cvt.u32.u64 %0, t; }" : "=r"(a) : "l"(p));
    return a;
}
__device__ __forceinline__ uint32_t pack_bf2(float lo, float hi) {
    uint32_t r; asm("cvt.rn.bf16x2.f32 %0, %1, %2;" : "=r"(r) : "f"(hi), "f"(lo)); return r;
}
__device__ __forceinline__ uint32_t pack_h2(float lo, float hi) {
    uint32_t r; asm("cvt.rn.f16x2.f32 %0, %1, %2;" : "=r"(r) : "f"(hi), "f"(lo)); return r;
}
__device__ __forceinline__ void ldsm_x4(uint32_t addr, uint32_t* r) {
    asm volatile("ldmatrix.sync.aligned.m8n8.x4.shared.b16 {%0,%1,%2,%3}, [%4];"
                 : "=r"(r[0]), "=r"(r[1]), "=r"(r[2]), "=r"(r[3]) : "r"(addr));
}
__device__ __forceinline__ void mma_bf16(float* c, const uint32_t* a, uint32_t b0, uint32_t b1) {
    asm volatile("mma.sync.aligned.m16n8k16.row.col.f32.bf16.bf16.f32 "
                 "{%0,%1,%2,%3}, {%4,%5,%6,%7}, {%8,%9}, {%0,%1,%2,%3};"
                 : "+f"(c[0]), "+f"(c[1]), "+f"(c[2]), "+f"(c[3])
                 : "r"(a[0]), "r"(a[1]), "r"(a[2]), "r"(a[3]), "r"(b0), "r"(b1));
}
__device__ __forceinline__ void mma_f16(float* c, const uint32_t* a, uint32_t b0, uint32_t b1) {
    asm volatile("mma.sync.aligned.m16n8k16.row.col.f32.f16.f16.f32 "
                 "{%0,%1,%2,%3}, {%4,%5,%6,%7}, {%8,%9}, {%0,%1,%2,%3};"
                 : "+f"(c[0]), "+f"(c[1]), "+f"(c[2]), "+f"(c[3])
                 : "r"(a[0]), "r"(a[1]), "r"(a[2]), "r"(a[3]), "r"(b0), "r"(b1));
}
__device__ __forceinline__ void split2(float x, float y, uint32_t& h, uint32_t& l) {
    h = pack_bf2(x, y);
    l = pack_bf2(x - __uint_as_float(h << 16), y - __uint_as_float(h & 0xffff0000u));
}
__device__ __forceinline__ float bflo(uint32_t u) { return __uint_as_float(u << 16); }
__device__ __forceinline__ float bfhi(uint32_t u) { return __uint_as_float(u & 0xffff0000u); }

// ------------------------- K0: prep all W^T images ---------------------------
__global__ void k_wprep(const float* __restrict__ Wk, const float* __restrict__ Wv,
                        const float* __restrict__ Wq, const float* __restrict__ Wf) {
    int u = blockIdx.x * blockDim.x + threadIdx.x;    // 8192 units
    const float* src;
    int n, kc, kind;
    uint4 *dst16 = nullptr, *dh = nullptr, *dl = nullptr;
    if (u < 4096) {
        n = u & 255; kc = u >> 8; kind = 0;
        src = (n < 128) ? (Wk + n) : (Wv + (n - 128));
        dst16 = g_WT16 + n * 16 + (kc ^ (n & 7));
    } else if (u < 6144) {
        int u2 = u - 4096; n = u2 & 127; kc = u2 >> 7; kind = 1;
        src = Wq + n;
        dst16 = g_WQ16 + n * 16 + (kc ^ (n & 7));
    } else {
        int u2 = u - 6144; n = u2 & 127; kc = u2 >> 7; kind = 2;
        src = Wf + n;
        int idx = n * 16 + (kc ^ (n & 7));
        dh = g_WFhi + idx; dl = g_WFlo + idx;
    }
    float f[8];
    #pragma unroll
    for (int i = 0; i < 8; i++) f[i] = src[(size_t)(kc * 8 + i) * DIM];
    if (kind < 2) {
        uint32_t h[4];
        #pragma unroll
        for (int i = 0; i < 4; i++) h[i] = pack_h2(f[2 * i], f[2 * i + 1]);
        *dst16 = make_uint4(h[0], h[1], h[2], h[3]);
    } else {
        uint32_t h[4], l[4];
        #pragma unroll
        for (int i = 0; i < 4; i++) split2(f[2 * i], f[2 * i + 1], h[i], l[i]);
        *dh = make_uint4(h[0], h[1], h[2], h[3]);
        *dl = make_uint4(l[0], l[1], l[2], l[3]);
    }
}

// ------------------------- K1: fp16 HMMA projection (M=64 x N=256) -----------
// E read ONCE per tile; 2 CTAs/SM (80KB smem, 64-reg cap).
// smem: A [64 rows][256B] @0 (16KB); B [256 n][256B] @16K (64KB);
//       OUT [64 rows][512B] @80K (32KB, epilogue staging)
#define P_A   0
#define P_B   16384
#define P_OUT 81920
#define PROJ_SMEM 114688

__global__ void __launch_bounds__(512, 2)
k_proj_mma(const float* __restrict__ E, int V) {
    extern __shared__ char smem[];
    const uint32_t sb = smem_to_u32(smem);
    const int t    = threadIdx.x;
    const int w    = t >> 5;
    const int lane = t & 31;
    const int v0   = blockIdx.x * 64;

    // ---- stage A (fp16) + fused row-sum: 64 rows x 16 kc = 1024 units
    #pragma unroll
    for (int i = 0; i < 2; i++) {
        int u   = t + 512 * i;
        int row = u >> 4;
        int kc  = u & 15;
        int gr  = v0 + row;
        int grc = (gr < V) ? gr : 0;
        const float4* src = reinterpret_cast<const float4*>(E + (size_t)grc * DIM + kc * 8);
        float4 f0 = src[0], f1 = src[1];
        uint32_t h0 = pack_h2(f0.x, f0.y), h1 = pack_h2(f0.z, f0.w);
        uint32_t h2 = pack_h2(f1.x, f1.y), h3 = pack_h2(f1.z, f1.w);
        uint32_t off = (uint32_t)row * 256 + (uint32_t)((kc ^ (row & 7)) << 4);
        *reinterpret_cast<uint4*>(smem + P_A + off) = make_uint4(h0, h1, h2, h3);
        float s8 = ((f0.x + f0.y) + (f0.z + f0.w)) + ((f1.x + f1.y) + (f1.z + f1.w));
        s8 += __shfl_xor_sync(0xffffffffu, s8, 8);
        s8 += __shfl_xor_sync(0xffffffffu, s8, 4);
        s8 += __shfl_xor_sync(0xffffffffu, s8, 2);
        s8 += __shfl_xor_sync(0xffffffffu, s8, 1);
        if ((t & 15) == 0 && gr < V) g_Esum[gr] = s8;
    }
    // ---- stage B: full 64KB image (L2-resident)
    {
        uint4* d = reinterpret_cast<uint4*>(smem + P_B);
        #pragma unroll
        for (int i = 0; i < 8; i++) {
            int idx = t + 512 * i;
            d[idx] = g_WT16[idx];
        }
    }
    __syncthreads();

    // ---- compute: warp = (mg = w&3) rows mg*16.., (ng = w>>2) cols ng*64..
    const int mg = w & 3;
    const int ng = w >> 2;

    float acc[8][4];
    #pragma unroll
    for (int nt = 0; nt < 8; nt++)
        #pragma unroll
        for (int j = 0; j < 4; j++) acc[nt][j] = 0.f;

    const int aRow  = mg * 16 + ((lane >> 3) & 1) * 8 + (lane & 7);
    const int aKsel = (lane >> 4);
    const int bN    = ng * 64 + ((lane >> 4) & 1) * 8 + (lane & 7);
    const int bKsel = (lane >> 3) & 1;

    #pragma unroll
    for (int ks = 0; ks < 8; ks++) {
        uint32_t a[4];
        {
            int kc = ks * 2 + aKsel;
            ldsm_x4(sb + P_A + aRow * 256 + (((kc ^ (aRow & 7)) << 4)), a);
        }
        // first half: bt 0,1 -> nt 0..3
        {
            uint32_t b[2][4];
            #pragma unroll
            for (int bt = 0; bt < 2; bt++) {
                int n  = bN + bt * 16;
                int kc = ks * 2 + bKsel;
                ldsm_x4(sb + P_B + n * 256 + (((kc ^ (n & 7)) << 4)), b[bt]);
            }
            #pragma unroll
            for (int nt = 0; nt < 4; nt++)
                mma_f16(acc[nt], a, b[nt >> 1][(nt & 1) * 2], b[nt >> 1][(nt & 1) * 2 + 1]);
        }
        // second half: bt 2,3 -> nt 4..7
        {
            uint32_t b[2][4];
            #pragma unroll
            for (int bt = 0; bt < 2; bt++) {
                int n  = bN + (bt + 2) * 16;
                int kc = ks * 2 + bKsel;
                ldsm_x4(sb + P_B + n * 256 + (((kc ^ (n & 7)) << 4)), b[bt]);
            }
            #pragma unroll
            for (int nt = 4; nt < 8; nt++)
                mma_f16(acc[nt], a, b[(nt - 4) >> 1][(nt & 1) * 2], b[(nt - 4) >> 1][(nt & 1) * 2 + 1]);
        }
    }

    // ---- epilogue: swizzled smem staging (512B rows, xor (row&7)<<4),
    //      then fully coalesced uint4 copy to bf16 tables.
    __syncthreads();
    {
        int rl  = mg * 16 + (lane >> 2);
        int rl2 = rl + 8;
        #pragma unroll
        for (int nt = 0; nt < 8; nt++) {
            int colb = (ng * 64 + nt * 8 + (lane & 3) * 2) * 2;   // byte offset 0..511
            uint32_t b0 = pack_bf2(acc[nt][0], acc[nt][1]);
            uint32_t b1 = pack_bf2(acc[nt][2], acc[nt][3]);
            *reinterpret_cast<uint32_t*>(smem + P_OUT + rl  * 512 + (colb ^ ((rl  & 7) << 4))) = b0;
            *reinterpret_cast<uint32_t*>(smem + P_OUT + rl2 * 512 + (colb ^ ((rl2 & 7) << 4))) = b1;
        }
    }
    __syncthreads();
    {
        #pragma unroll
        for (int i = 0; i < 4; i++) {
            int idx = t + 512 * i;            // 2048 chunks of 16B (32KB)
            int row = idx >> 5, c16 = idx & 31;
            int gr = v0 + row;
            if (gr < V) {
                uint4 val = *reinterpret_cast<uint4*>(
                    smem + P_OUT + row * 512 + ((c16 * 16) ^ ((row & 7) << 4)));
                __nv_bfloat16* table = (c16 < 16) ? g_EKbf : g_EVbf;
                reinterpret_cast<uint4*>(table + (size_t)gr * DIM)[c16 & 15] = val;
            }
        }
    }
}

// ------------------------- K2a: Q gemm (fp16 single pass, N=128) -------------
#define Q_A 0
#define Q_B 32768
#define GEMMQ_SMEM 65536

__global__ void __launch_bounds__(512)
k_gemm_q(const float* __restrict__ E, const int* __restrict__ queries,
         const float* __restrict__ bq, int M) {
    extern __shared__ char smem[];
    const uint32_t sb = smem_to_u32(smem);
    const int t    = threadIdx.x;
    const int w    = t >> 5;
    const int lane = t & 31;
    const int m0   = blockIdx.x * 128;

    #pragma unroll
    for (int i = 0; i < 4; i++) {
        int u   = t + 512 * i;
        int row = u >> 4;
        int kc  = u & 15;
        int m   = m0 + row;
        int mm  = (m < M) ? m : 0;
        const float4* src = reinterpret_cast<const float4*>(E + (size_t)queries[mm] * DIM + kc * 8);
        float4 f0 = src[0], f1 = src[1];
        uint32_t h0 = pack_h2(f0.x, f0.y), h1 = pack_h2(f0.z, f0.w);
        uint32_t h2 = pack_h2(f1.x, f1.y), h3 = pack_h2(f1.z, f1.w);
        uint32_t off = (uint32_t)row * 256 + (uint32_t)((kc ^ (row & 7)) << 4);
        *reinterpret_cast<uint4*>(smem + Q_A + off) = make_uint4(h0, h1, h2, h3);
    }
    {
        uint4* d = reinterpret_cast<uint4*>(smem + Q_B);
        #pragma unroll
        for (int i = 0; i < 4; i++) {
            int idx = t + 512 * i;
            d[idx] = g_WQ16[idx];
        }
    }
    __syncthreads();

    const int mg = w & 3;
    const int ng = w >> 2;

    float acc[2][4][4];
    #pragma unroll
    for (int mt = 0; mt < 2; mt++)
        #pragma unroll
        for (int nt = 0; nt < 4; nt++)
            #pragma unroll
            for (int j = 0; j < 4; j++) acc[mt][nt][j] = 0.f;

    const int aRow  = mg * 32 + ((lane >> 3) & 1) * 8 + (lane & 7);
    const int aKsel = (lane >> 4);
    const int bN    = ng * 32 + ((lane >> 4) & 1) * 8 + (lane & 7);
    const int bKsel = (lane >> 3) & 1;

    #pragma unroll
    for (int ks = 0; ks < 8; ks++) {
        uint32_t a[2][4];
        #pragma unroll
        for (int mt = 0; mt < 2; mt++) {
            int row = aRow + mt * 16;
            int kc  = ks * 2 + aKsel;
            ldsm_x4(sb + Q_A + row * 256 + (((kc ^ (row & 7)) << 4)), a[mt]);
        }
        uint32_t b[2][4];
        #pragma unroll
        for (int bt = 0; bt < 2; bt++) {
            int n  = bN + bt * 16;
            int kc = ks * 2 + bKsel;
            ldsm_x4(sb + Q_B + n * 256 + (((kc ^ (n & 7)) << 4)), b[bt]);
        }
        #pragma unroll
        for (int mt = 0; mt < 2; mt++)
            #pragma unroll
            for (int nt = 0; nt < 4; nt++)
                mma_f16(acc[mt][nt], a[mt], b[nt >> 1][(nt & 1) * 2], b[nt >> 1][(nt & 1) * 2 + 1]);
    }

    #pragma unroll
    for (int mt = 0; mt < 2; mt++) {
        int row = m0 + mg * 32 + mt * 16 + (lane >> 2);
        #pragma unroll
        for (int nt = 0; nt < 4; nt++) {
            int col = ng * 32 + nt * 8 + (lane & 3) * 2;
            float b0 = bq[col], b1 = bq[col + 1];
            if (row < M) {
                *reinterpret_cast<float2*>(g_Q + (size_t)row * DIM + col) =
                    make_float2(acc[mt][nt][0] + b0, acc[mt][nt][1] + b1);
                if (row + 8 < M)
                    *reinterpret_cast<float2*>(g_Q + (size_t)(row + 8) * DIM + col) =
                        make_float2(acc[mt][nt][2] + b0, acc[mt][nt][3] + b1);
            }
        }
    }
}

// ------------------------- K2b: final gemm (bf16 3-pass, N=128) --------------
#define F_A_HI 0
#define F_A_LO 32768
#define F_B_HI 65536
#define F_B_LO 98304
#define GEMMF_SMEM 131072

__global__ void __launch_bounds__(512)
k_gemm_f(const float* __restrict__ bf, float* __restrict__ outp, int M) {
    extern __shared__ char smem[];
    const uint32_t sb = smem_to_u32(smem);
    const int t    = threadIdx.x;
    const int w    = t >> 5;
    const int lane = t & 31;
    const int m0   = blockIdx.x * 128;

    #pragma unroll
    for (int i = 0; i < 4; i++) {
        int u   = t + 512 * i;
        int row = u >> 4;
        int kc  = u & 15;
        int m   = m0 + row;
        const float4* src = reinterpret_cast<const float4*>(
            g_res + (size_t)((m < M) ? m : 0) * DIM + kc * 8);
        float4 f0 = src[0], f1 = src[1];
        uint32_t h0, h1, h2, h3, l0, l1, l2, l3;
        split2(f0.x, f0.y, h0, l0); split2(f0.z, f0.w, h1, l1);
        split2(f1.x, f1.y, h2, l2); split2(f1.z, f1.w, h3, l3);
        uint32_t off = (uint32_t)row * 256 + (uint32_t)((kc ^ (row & 7)) << 4);
        *reinterpret_cast<uint4*>(smem + F_A_HI + off) = make_uint4(h0, h1, h2, h3);
        *reinterpret_cast<uint4*>(smem + F_A_LO + off) = make_uint4(l0, l1, l2, l3);
    }
    {
        uint4* dh = reinterpret_cast<uint4*>(smem + F_B_HI);
        uint4* dl = reinterpret_cast<uint4*>(smem + F_B_LO);
        #pragma unroll
        for (int i = 0; i < 4; i++) {
            int idx = t + 512 * i;
            dh[idx] = g_WFhi[idx];
            dl[idx] = g_WFlo[idx];
        }
    }
    __syncthreads();

    const int mg = w & 3;
    const int ng = w >> 2;

    float acc[2][4][4];
    #pragma unroll
    for (int mt = 0; mt < 2; mt++)
        #pragma unroll
        for (int nt = 0; nt < 4; nt++)
            #pragma unroll
            for (int j = 0; j < 4; j++) acc[mt][nt][j] = 0.f;

    const int aRow  = mg * 32 + ((lane >> 3) & 1) * 8 + (lane & 7);
    const int aKsel = (lane >> 4);
    const int bN    = ng * 32 + ((lane >> 4) & 1) * 8 + (lane & 7);
    const int bKsel = (lane >> 3) & 1;

    #pragma unroll
    for (int p = 0; p < 3; p++) {
        const uint32_t abase = sb + (p == 2 ? F_A_LO : F_A_HI);
        const uint32_t bbase = sb + (p == 1 ? F_B_LO : F_B_HI);
        #pragma unroll
        for (int ks = 0; ks < 8; ks++) {
            uint32_t a[2][4];
            #pragma unroll
            for (int mt = 0; mt < 2; mt++) {
                int row = aRow + mt * 16;
                int kc  = ks * 2 + aKsel;
                ldsm_x4(abase + row * 256 + (((kc ^ (row & 7)) << 4)), a[mt]);
            }
            uint32_t b[2][4];
            #pragma unroll
            for (int bt = 0; bt < 2; bt++) {
                int n  = bN + bt * 16;
                int kc = ks * 2 + bKsel;
                ldsm_x4(bbase + n * 256 + (((kc ^ (n & 7)) << 4)), b[bt]);
            }
            #pragma unroll
            for (int mt = 0; mt < 2; mt++)
                #pragma unroll
                for (int nt = 0; nt < 4; nt++)
                    mma_bf16(acc[mt][nt], a[mt], b[nt >> 1][(nt & 1) * 2], b[nt >> 1][(nt & 1) * 2 + 1]);
        }
    }

    #pragma unroll
    for (int mt = 0; mt < 2; mt++) {
        int row = m0 + mg * 32 + mt * 16 + (lane >> 2);
        #pragma unroll
        for (int nt = 0; nt < 4; nt++) {
            int col = ng * 32 + nt * 8 + (lane & 3) * 2;
            float b0 = bf[col], b1 = bf[col + 1];
            if (row < M) {
                *reinterpret_cast<float2*>(outp + (size_t)row * DIM + col) =
                    make_float2(acc[mt][nt][0] + b0, acc[mt][nt][1] + b1);
                if (row + 8 < M)
                    *reinterpret_cast<float2*>(outp + (size_t)(row + 8) * DIM + col) =
                        make_float2(acc[mt][nt][2] + b0, acc[mt][nt][3] + b1);
            }
        }
    }
}

// ------------------------- K3: fused attention, warp per (b,l), dual chain ---
__global__ void __launch_bounds__(256) k_attn(const int* __restrict__ queries,
                                              const int* __restrict__ keys,
                                              const float* __restrict__ E,
                                              const float* __restrict__ bk,
                                              const float* __restrict__ bv,
                                              int L2, int M) {
    const int t      = threadIdx.x;
    const int w      = t >> 5;
    const int lane   = t & 31;
    const int lane16 = lane & 15;
    const int sel    = lane >> 4;
    const int bl     = blockIdx.x * 8 + w;

    __shared__ uint2 s_km[8][52];       // {byte offset kid*256, mask as float}

    if (bl < M) {
        for (int i = lane; i < 52; i += 32) {
            uint2 v = make_uint2(0u, 0u);
            if (i < L2) {
                int kid = keys[bl * L2 + i];
                float m = (g_Esum[kid] == 0.0f) ? 0.0f : 1.0f;
                v = make_uint2((uint32_t)kid << 8, __float_as_uint(m));
            }
            s_km[w][i] = v;
        }
    }
    __syncwarp();
    if (bl >= M) return;

    const float4* qp  = reinterpret_cast<const float4*>(g_Q + (size_t)bl * DIM + lane16 * 8);
    const float4* bkp = reinterpret_cast<const float4*>(bk + lane16 * 8);
    const float4 qa = qp[0], qb = qp[1];
    const float4 ba = bkp[0], bb = bkp[1];
    float corrp = qa.x * ba.x + qa.y * ba.y + qa.z * ba.z + qa.w * ba.w
                + qb.x * bb.x + qb.y * bb.y + qb.z * bb.z + qb.w * bb.w;

    const float RS = 0.17677669529663687f;   // 1/sqrt(32)
    const char* ekb = reinterpret_cast<const char*>(g_EKbf);
    const char* evb = reinterpret_cast<const char*>(g_EVbf);
    const uint32_t lo16 = lane16 * 16;

    float a0 = 0.f, a1 = 0.f, a2 = 0.f, a3 = 0.f;
    float a4 = 0.f, a5 = 0.f, a6 = 0.f, a7 = 0.f;
    float sumw = 0.f;

    const int np = (L2 + 3) >> 2;
    for (int i = 0; i < np; i++) {
        uint2 km0 = s_km[w][4 * i + sel];
        uint2 km1 = s_km[w][4 * i + 2 + sel];
        uint4 kr0 = *reinterpret_cast<const uint4*>(ekb + km0.x + lo16);
        uint4 kr1 = *reinterpret_cast<const uint4*>(ekb + km1.x + lo16);
        uint4 vr0 = *reinterpret_cast<const uint4*>(evb + km0.x + lo16);
        uint4 vr1 = *reinterpret_cast<const uint4*>(evb + km1.x + lo16);
        float p0 = corrp, p1 = corrp;
        p0 = fmaf(qa.x, bflo(kr0.x), p0); p1 = fmaf(qa.x, bflo(kr1.x), p1);
        p0 = fmaf(qa.y, bfhi(kr0.x), p0); p1 = fmaf(qa.y, bfhi(kr1.x), p1);
        p0 = fmaf(qa.z, bflo(kr0.y), p0); p1 = fmaf(qa.z, bflo(kr1.y), p1);
        p0 = fmaf(qa.w, bfhi(kr0.y), p0); p1 = fmaf(qa.w, bfhi(kr1.y), p1);
        p0 = fmaf(qb.x, bflo(kr0.z), p0); p1 = fmaf(qb.x, bflo(kr1.z), p1);
        p0 = fmaf(qb.y, bfhi(kr0.z), p0); p1 = fmaf(qb.y, bfhi(kr1.z), p1);
        p0 = fmaf(qb.z, bflo(kr0.w), p0); p1 = fmaf(qb.z, bflo(kr1.w), p1);
        p0 = fmaf(qb.w, bfhi(kr0.w), p0); p1 = fmaf(qb.w, bfhi(kr1.w), p1);
        p0 += __shfl_xor_sync(0xffffffffu, p0, 1);
        p1 += __shfl_xor_sync(0xffffffffu, p1, 1);
        p0 += __shfl_xor_sync(0xffffffffu, p0, 2);
        p1 += __shfl_xor_sync(0xffffffffu, p1, 2);
        float w0 = __uint_as_float(km0.y) * __expf(p0 * RS);
        float w1 = __uint_as_float(km1.y) * __expf(p1 * RS);
        a0 = fmaf(w0, bflo(vr0.x), a0); a0 = fmaf(w1, bflo(vr1.x), a0);
        a1 = fmaf(w0, bfhi(vr0.x), a1); a1 = fmaf(w1, bfhi(vr1.x), a1);
        a2 = fmaf(w0, bflo(vr0.y), a2); a2 = fmaf(w1, bflo(vr1.y), a2);
        a3 = fmaf(w0, bfhi(vr0.y), a3); a3 = fmaf(w1, bfhi(vr1.y), a3);
        a4 = fmaf(w0, bflo(vr0.z), a4); a4 = fmaf(w1, bflo(vr1.z), a4);
        a5 = fmaf(w0, bfhi(vr0.z), a5); a5 = fmaf(w1, bfhi(vr1.z), a5);
        a6 = fmaf(w0, bflo(vr0.w), a6); a6 = fmaf(w1, bflo(vr1.w), a6);
        a7 = fmaf(w0, bfhi(vr0.w), a7); a7 = fmaf(w1, bfhi(vr1.w), a7);
        sumw += w0 + w1;
    }

    sumw += __shfl_xor_sync(0xffffffffu, sumw, 16);
    a0 += __shfl_xor_sync(0xffffffffu, a0, 16);
    a1 += __shfl_xor_sync(0xffffffffu, a1, 16);
    a2 += __shfl_xor_sync(0xffffffffu, a2, 16);
    a3 += __shfl_xor_sync(0xffffffffu, a3, 16);
    a4 += __shfl_xor_sync(0xffffffffu, a4, 16);
    a5 += __shfl_xor_sync(0xffffffffu, a5, 16);
    a6 += __shfl_xor_sync(0xffffffffu, a6, 16);
    a7 += __shfl_xor_sync(0xffffffffu, a7, 16);

    const float inv = 1.0f / sumw;
    const int   qid = queries[bl];
    const int   d0  = lane16 * 8 + sel * 4;
    const float4 bv4 = *reinterpret_cast<const float4*>(bv + d0);
    const float4 qe4 = *reinterpret_cast<const float4*>(E + (size_t)qid * DIM + d0);
    float4 o;
    if (sel == 0) {
        o.x = fmaf(a0, inv, bv4.x + qe4.x);
        o.y = fmaf(a1, inv, bv4.y + qe4.y);
        o.z = fmaf(a2, inv, bv4.z + qe4.z);
        o.w = fmaf(a3, inv, bv4.w + qe4.w);
    } else {
        o.x = fmaf(a4, inv, bv4.x + qe4.x);
        o.y = fmaf(a5, inv, bv4.y + qe4.y);
        o.z = fmaf(a6, inv, bv4.z + qe4.z);
        o.w = fmaf(a7, inv, bv4.w + qe4.w);
    }
    *reinterpret_cast<float4*>(g_res + (size_t)bl * DIM + d0) = o;
}

// ------------------------- launch --------------------------------------------
extern "C" void kernel_launch(void* const* d_in, const int* in_sizes, int n_in,
                              void* d_out, int out_size) {
    const int*   queries = (const int*)d_in[0];
    const int*   keys    = (const int*)d_in[1];
    const float* E       = (const float*)d_in[2];
    const float* Wq      = (const float*)d_in[3];
    const float* bq      = (const float*)d_in[4];
    const float* Wk      = (const float*)d_in[5];
    const float* bk      = (const float*)d_in[6];
    const float* Wv      = (const float*)d_in[7];
    const float* bv      = (const float*)d_in[8];
    const float* Wf      = (const float*)d_in[9];
    const float* bf      = (const float*)d_in[10];
    float* out = (float*)d_out;

    const int V  = in_sizes[2] / DIM;
    const int M  = in_sizes[0];
    const int L2 = in_sizes[1] / M;

    cudaFuncSetAttribute(k_proj_mma, cudaFuncAttributeMaxDynamicSharedMemorySize, PROJ_SMEM);
    cudaFuncSetAttribute(k_gemm_q,   cudaFuncAttributeMaxDynamicSharedMemorySize, GEMMQ_SMEM);
    cudaFuncSetAttribute(k_gemm_f,   cudaFuncAttributeMaxDynamicSharedMemorySize, GEMMF_SMEM);

    k_wprep<<<32, 256>>>(Wk, Wv, Wq, Wf);
    // gemm_q before proj so its streaming E read doesn't evict the tables.
    k_gemm_q<<<(M + 127) / 128, 512, GEMMQ_SMEM>>>(E, queries, bq, M);
    k_proj_mma<<<(V + 63) / 64, 512, PROJ_SMEM>>>(E, V);
    k_attn<<<(M + 7) / 8, 256>>>(queries, keys, E, bk, bv, L2, M);
    k_gemm_f<<<(M + 127) / 128, 512, GEMMF_SMEM>>>(bf, out, M);
}

// round 12
// speedup vs baseline: 5.5519x; 1.0996x over previous
#include <cuda_runtime.h>
#include <cuda_bf16.h>
#include <cstdint>

#define VOCAB_MAX 100000
#define BL_MAX    12800
#define DIM       128
#define NHEAD     4

// ------------------------- scratch (device globals) -------------------------
__device__ __nv_bfloat16 g_EKbf[VOCAB_MAX * DIM];   // E @ Wk  (bf16)
__device__ __nv_bfloat16 g_EVbf[VOCAB_MAX * DIM];   // E @ Wv  (bf16)
__device__ float g_Esum[VOCAB_MAX];
__device__ float g_Q[BL_MAX * DIM];
__device__ float g_res[BL_MAX * DIM];
// swizzled W^T images (n-major, k contiguous, kc ^= n&7)
__device__ uint4 g_WT16[4096];   // [Wk|Wv] fp16: [n=256][kc=16]
__device__ uint4 g_WQ16[2048];   // Wq fp16:      [n=128][kc=16]
__device__ uint4 g_WFhi[2048];   // Wf bf16 hi
__device__ uint4 g_WFlo[2048];   // Wf bf16 lo

// ------------------------- helpers ------------------------------------------
__device__ __forceinline__ uint32_t smem_to_u32(const void* p) {
    uint32_t a;
    asm("{ .reg .u64 t; cvta.to.shared.u64 t, %1; cvt.u32.u64 %0, t; }" : "=r"(a) : "l"(p));
    return a;
}
__device__ __forceinline__ uint32_t pack_bf2(float lo, float hi) {
    uint32_t r; asm("cvt.rn.bf16x2.f32 %0, %1, %2;" : "=r"(r) : "f"(hi), "f"(lo)); return r;
}
__device__ __forceinline__ uint32_t pack_h2(float lo, float hi) {
    uint32_t r; asm("cvt.rn.f16x2.f32 %0, %1, %2;" : "=r"(r) : "f"(hi), "f"(lo)); return r;
}
__device__ __forceinline__ void ldsm_x4(uint32_t addr, uint32_t* r) {
    asm volatile("ldmatrix.sync.aligned.m8n8.x4.shared.b16 {%0,%1,%2,%3}, [%4];"
                 : "=r"(r[0]), "=r"(r[1]), "=r"(r[2]), "=r"(r[3]) : "r"(addr));
}
__device__ __forceinline__ void mma_bf16(float* c, const uint32_t* a, uint32_t b0, uint32_t b1) {
    asm volatile("mma.sync.aligned.m16n8k16.row.col.f32.bf16.bf16.f32 "
                 "{%0,%1,%2,%3}, {%4,%5,%6,%7}, {%8,%9}, {%0,%1,%2,%3};"
                 : "+f"(c[0]), "+f"(c[1]), "+f"(c[2]), "+f"(c[3])
                 : "r"(a[0]), "r"(a[1]), "r"(a[2]), "r"(a[3]), "r"(b0), "r"(b1));
}
__device__ __forceinline__ void mma_f16(float* c, const uint32_t* a, uint32_t b0, uint32_t b1) {
    asm volatile("mma.sync.aligned.m16n8k16.row.col.f32.f16.f16.f32 "
                 "{%0,%1,%2,%3}, {%4,%5,%6,%7}, {%8,%9}, {%0,%1,%2,%3};"
                 : "+f"(c[0]), "+f"(c[1]), "+f"(c[2]), "+f"(c[3])
                 : "r"(a[0]), "r"(a[1]), "r"(a[2]), "r"(a[3]), "r"(b0), "r"(b1));
}
__device__ __forceinline__ void split2(float x, float y, uint32_t& h, uint32_t& l) {
    h = pack_bf2(x, y);
    l = pack_bf2(x - __uint_as_float(h << 16), y - __uint_as_float(h & 0xffff0000u));
}
__device__ __forceinline__ float bflo(uint32_t u) { return __uint_as_float(u << 16); }
__device__ __forceinline__ float bfhi(uint32_t u) { return __uint_as_float(u & 0xffff0000u); }

// ------------------------- K0: prep all W^T images ---------------------------
__global__ void k_wprep(const float* __restrict__ Wk, const float* __restrict__ Wv,
                        const float* __restrict__ Wq, const float* __restrict__ Wf) {
    int u = blockIdx.x * blockDim.x + threadIdx.x;    // 8192 units
    const float* src;
    int n, kc, kind;
    uint4 *dst16 = nullptr, *dh = nullptr, *dl = nullptr;
    if (u < 4096) {
        n = u & 255; kc = u >> 8; kind = 0;
        src = (n < 128) ? (Wk + n) : (Wv + (n - 128));
        dst16 = g_WT16 + n * 16 + (kc ^ (n & 7));
    } else if (u < 6144) {
        int u2 = u - 4096; n = u2 & 127; kc = u2 >> 7; kind = 1;
        src = Wq + n;
        dst16 = g_WQ16 + n * 16 + (kc ^ (n & 7));
    } else {
        int u2 = u - 6144; n = u2 & 127; kc = u2 >> 7; kind = 2;
        src = Wf + n;
        int idx = n * 16 + (kc ^ (n & 7));
        dh = g_WFhi + idx; dl = g_WFlo + idx;
    }
    float f[8];
    #pragma unroll
    for (int i = 0; i < 8; i++) f[i] = src[(size_t)(kc * 8 + i) * DIM];
    if (kind < 2) {
        uint32_t h[4];
        #pragma unroll
        for (int i = 0; i < 4; i++) h[i] = pack_h2(f[2 * i], f[2 * i + 1]);
        *dst16 = make_uint4(h[0], h[1], h[2], h[3]);
    } else {
        uint32_t h[4], l[4];
        #pragma unroll
        for (int i = 0; i < 4; i++) split2(f[2 * i], f[2 * i + 1], h[i], l[i]);
        *dh = make_uint4(h[0], h[1], h[2], h[3]);
        *dl = make_uint4(l[0], l[1], l[2], l[3]);
    }
}

// ------------------------- K1: fused proj + Q gemm ---------------------------
// Blocks [0, nq): Q = gather(E,queries)@Wq + bq (fp16, M=128 x N=128)
// Blocks [nq, ...): EK|EV = E @ [Wk|Wv]        (fp16, M=64  x N=256)
// 112KB dyn smem, 2 CTAs/SM, 64-reg cap.
#define P_A   0
#define P_B   16384
#define P_OUT 81920
#define Q_A   0
#define Q_B   32768
#define PROJ_SMEM 114688

__device__ void gemm_q_path(char* smem, uint32_t sb,
                            const float* __restrict__ E,
                            const int* __restrict__ queries,
                            const float* __restrict__ bq, int M, int bx) {
    const int t    = threadIdx.x;
    const int w    = t >> 5;
    const int lane = t & 31;
    const int m0   = bx * 128;

    #pragma unroll
    for (int i = 0; i < 4; i++) {
        int u   = t + 512 * i;
        int row = u >> 4;
        int kc  = u & 15;
        int m   = m0 + row;
        int mm  = (m < M) ? m : 0;
        const float4* src = reinterpret_cast<const float4*>(E + (size_t)queries[mm] * DIM + kc * 8);
        float4 f0 = src[0], f1 = src[1];
        uint32_t h0 = pack_h2(f0.x, f0.y), h1 = pack_h2(f0.z, f0.w);
        uint32_t h2 = pack_h2(f1.x, f1.y), h3 = pack_h2(f1.z, f1.w);
        uint32_t off = (uint32_t)row * 256 + (uint32_t)((kc ^ (row & 7)) << 4);
        *reinterpret_cast<uint4*>(smem + Q_A + off) = make_uint4(h0, h1, h2, h3);
    }
    {
        uint4* d = reinterpret_cast<uint4*>(smem + Q_B);
        #pragma unroll
        for (int i = 0; i < 4; i++) {
            int idx = t + 512 * i;
            d[idx] = g_WQ16[idx];
        }
    }
    __syncthreads();

    const int mg = w & 3;
    const int ng = w >> 2;

    float acc[2][4][4];
    #pragma unroll
    for (int mt = 0; mt < 2; mt++)
        #pragma unroll
        for (int nt = 0; nt < 4; nt++)
            #pragma unroll
            for (int j = 0; j < 4; j++) acc[mt][nt][j] = 0.f;

    const int aRow  = mg * 32 + ((lane >> 3) & 1) * 8 + (lane & 7);
    const int aKsel = (lane >> 4);
    const int bN    = ng * 32 + ((lane >> 4) & 1) * 8 + (lane & 7);
    const int bKsel = (lane >> 3) & 1;

    #pragma unroll
    for (int ks = 0; ks < 8; ks++) {
        uint32_t a[2][4];
        #pragma unroll
        for (int mt = 0; mt < 2; mt++) {
            int row = aRow + mt * 16;
            int kc  = ks * 2 + aKsel;
            ldsm_x4(sb + Q_A + row * 256 + (((kc ^ (row & 7)) << 4)), a[mt]);
        }
        uint32_t b[2][4];
        #pragma unroll
        for (int bt = 0; bt < 2; bt++) {
            int n  = bN + bt * 16;
            int kc = ks * 2 + bKsel;
            ldsm_x4(sb + Q_B + n * 256 + (((kc ^ (n & 7)) << 4)), b[bt]);
        }
        #pragma unroll
        for (int mt = 0; mt < 2; mt++)
            #pragma unroll
            for (int nt = 0; nt < 4; nt++)
                mma_f16(acc[mt][nt], a[mt], b[nt >> 1][(nt & 1) * 2], b[nt >> 1][(nt & 1) * 2 + 1]);
    }

    #pragma unroll
    for (int mt = 0; mt < 2; mt++) {
        int row = m0 + mg * 32 + mt * 16 + (lane >> 2);
        #pragma unroll
        for (int nt = 0; nt < 4; nt++) {
            int col = ng * 32 + nt * 8 + (lane & 3) * 2;
            float b0 = bq[col], b1 = bq[col + 1];
            if (row < M) {
                *reinterpret_cast<float2*>(g_Q + (size_t)row * DIM + col) =
                    make_float2(acc[mt][nt][0] + b0, acc[mt][nt][1] + b1);
                if (row + 8 < M)
                    *reinterpret_cast<float2*>(g_Q + (size_t)(row + 8) * DIM + col) =
                        make_float2(acc[mt][nt][2] + b0, acc[mt][nt][3] + b1);
            }
        }
    }
}

__global__ void __launch_bounds__(512, 2)
k_proj_mma(const float* __restrict__ E, const int* __restrict__ queries,
           const float* __restrict__ bq, int V, int M, int nq) {
    extern __shared__ char smem[];
    const uint32_t sb = smem_to_u32(smem);

    if ((int)blockIdx.x < nq) {           // Q-gemm blocks first (wave 1)
        gemm_q_path(smem, sb, E, queries, bq, M, blockIdx.x);
        return;
    }

    const int t    = threadIdx.x;
    const int w    = t >> 5;
    const int lane = t & 31;
    const int v0   = (blockIdx.x - nq) * 64;

    // ---- stage A (fp16, evict-first E reads) + fused row-sum
    #pragma unroll
    for (int i = 0; i < 2; i++) {
        int u   = t + 512 * i;
        int row = u >> 4;
        int kc  = u & 15;
        int gr  = v0 + row;
        int grc = (gr < V) ? gr : 0;
        const float4* src = reinterpret_cast<const float4*>(E + (size_t)grc * DIM + kc * 8);
        float4 f0 = __ldcs(src);          // streaming: don't pollute L2
        float4 f1 = __ldcs(src + 1);
        uint32_t h0 = pack_h2(f0.x, f0.y), h1 = pack_h2(f0.z, f0.w);
        uint32_t h2 = pack_h2(f1.x, f1.y), h3 = pack_h2(f1.z, f1.w);
        uint32_t off = (uint32_t)row * 256 + (uint32_t)((kc ^ (row & 7)) << 4);
        *reinterpret_cast<uint4*>(smem + P_A + off) = make_uint4(h0, h1, h2, h3);
        float s8 = ((f0.x + f0.y) + (f0.z + f0.w)) + ((f1.x + f1.y) + (f1.z + f1.w));
        s8 += __shfl_xor_sync(0xffffffffu, s8, 8);
        s8 += __shfl_xor_sync(0xffffffffu, s8, 4);
        s8 += __shfl_xor_sync(0xffffffffu, s8, 2);
        s8 += __shfl_xor_sync(0xffffffffu, s8, 1);
        if ((t & 15) == 0 && gr < V) g_Esum[gr] = s8;
    }
    // ---- stage B: full 64KB image (L2-resident)
    {
        uint4* d = reinterpret_cast<uint4*>(smem + P_B);
        #pragma unroll
        for (int i = 0; i < 8; i++) {
            int idx = t + 512 * i;
            d[idx] = g_WT16[idx];
        }
    }
    __syncthreads();

    const int mg = w & 3;
    const int ng = w >> 2;

    float acc[8][4];
    #pragma unroll
    for (int nt = 0; nt < 8; nt++)
        #pragma unroll
        for (int j = 0; j < 4; j++) acc[nt][j] = 0.f;

    const int aRow  = mg * 16 + ((lane >> 3) & 1) * 8 + (lane & 7);
    const int aKsel = (lane >> 4);
    const int bN    = ng * 64 + ((lane >> 4) & 1) * 8 + (lane & 7);
    const int bKsel = (lane >> 3) & 1;

    #pragma unroll
    for (int ks = 0; ks < 8; ks++) {
        uint32_t a[4];
        {
            int kc = ks * 2 + aKsel;
            ldsm_x4(sb + P_A + aRow * 256 + (((kc ^ (aRow & 7)) << 4)), a);
        }
        {
            uint32_t b[2][4];
            #pragma unroll
            for (int bt = 0; bt < 2; bt++) {
                int n  = bN + bt * 16;
                int kc = ks * 2 + bKsel;
                ldsm_x4(sb + P_B + n * 256 + (((kc ^ (n & 7)) << 4)), b[bt]);
            }
            #pragma unroll
            for (int nt = 0; nt < 4; nt++)
                mma_f16(acc[nt], a, b[nt >> 1][(nt & 1) * 2], b[nt >> 1][(nt & 1) * 2 + 1]);
        }
        {
            uint32_t b[2][4];
            #pragma unroll
            for (int bt = 0; bt < 2; bt++) {
                int n  = bN + (bt + 2) * 16;
                int kc = ks * 2 + bKsel;
                ldsm_x4(sb + P_B + n * 256 + (((kc ^ (n & 7)) << 4)), b[bt]);
            }
            #pragma unroll
            for (int nt = 4; nt < 8; nt++)
                mma_f16(acc[nt], a, b[(nt - 4) >> 1][(nt & 1) * 2], b[(nt - 4) >> 1][(nt & 1) * 2 + 1]);
        }
    }

    // ---- epilogue: swizzled smem staging, then coalesced copy
    __syncthreads();
    {
        int rl  = mg * 16 + (lane >> 2);
        int rl2 = rl + 8;
        #pragma unroll
        for (int nt = 0; nt < 8; nt++) {
            int colb = (ng * 64 + nt * 8 + (lane & 3) * 2) * 2;
            uint32_t b0 = pack_bf2(acc[nt][0], acc[nt][1]);
            uint32_t b1 = pack_bf2(acc[nt][2], acc[nt][3]);
            *reinterpret_cast<uint32_t*>(smem + P_OUT + rl  * 512 + (colb ^ ((rl  & 7) << 4))) = b0;
            *reinterpret_cast<uint32_t*>(smem + P_OUT + rl2 * 512 + (colb ^ ((rl2 & 7) << 4))) = b1;
        }
    }
    __syncthreads();
    {
        #pragma unroll
        for (int i = 0; i < 4; i++) {
            int idx = t + 512 * i;
            int row = idx >> 5, c16 = idx & 31;
            int gr = v0 + row;
            if (gr < V) {
                uint4 val = *reinterpret_cast<uint4*>(
                    smem + P_OUT + row * 512 + ((c16 * 16) ^ ((row & 7) << 4)));
                __nv_bfloat16* table = (c16 < 16) ? g_EKbf : g_EVbf;
                reinterpret_cast<uint4*>(table + (size_t)gr * DIM)[c16 & 15] = val;
            }
        }
    }
}

// ------------------------- K2b: final gemm (bf16 3-pass, N=128) --------------
#define F_A_HI 0
#define F_A_LO 32768
#define F_B_HI 65536
#define F_B_LO 98304
#define GEMMF_SMEM 131072

__global__ void __launch_bounds__(512)
k_gemm_f(const float* __restrict__ bf, float* __restrict__ outp, int M) {
    extern __shared__ char smem[];
    const uint32_t sb = smem_to_u32(smem);
    const int t    = threadIdx.x;
    const int w    = t >> 5;
    const int lane = t & 31;
    const int m0   = blockIdx.x * 128;

    #pragma unroll
    for (int i = 0; i < 4; i++) {
        int u   = t + 512 * i;
        int row = u >> 4;
        int kc  = u & 15;
        int m   = m0 + row;
        const float4* src = reinterpret_cast<const float4*>(
            g_res + (size_t)((m < M) ? m : 0) * DIM + kc * 8);
        float4 f0 = src[0], f1 = src[1];
        uint32_t h0, h1, h2, h3, l0, l1, l2, l3;
        split2(f0.x, f0.y, h0, l0); split2(f0.z, f0.w, h1, l1);
        split2(f1.x, f1.y, h2, l2); split2(f1.z, f1.w, h3, l3);
        uint32_t off = (uint32_t)row * 256 + (uint32_t)((kc ^ (row & 7)) << 4);
        *reinterpret_cast<uint4*>(smem + F_A_HI + off) = make_uint4(h0, h1, h2, h3);
        *reinterpret_cast<uint4*>(smem + F_A_LO + off) = make_uint4(l0, l1, l2, l3);
    }
    {
        uint4* dh = reinterpret_cast<uint4*>(smem + F_B_HI);
        uint4* dl = reinterpret_cast<uint4*>(smem + F_B_LO);
        #pragma unroll
        for (int i = 0; i < 4; i++) {
            int idx = t + 512 * i;
            dh[idx] = g_WFhi[idx];
            dl[idx] = g_WFlo[idx];
        }
    }
    __syncthreads();

    const int mg = w & 3;
    const int ng = w >> 2;

    float acc[2][4][4];
    #pragma unroll
    for (int mt = 0; mt < 2; mt++)
        #pragma unroll
        for (int nt = 0; nt < 4; nt++)
            #pragma unroll
            for (int j = 0; j < 4; j++) acc[mt][nt][j] = 0.f;

    const int aRow  = mg * 32 + ((lane >> 3) & 1) * 8 + (lane & 7);
    const int aKsel = (lane >> 4);
    const int bN    = ng * 32 + ((lane >> 4) & 1) * 8 + (lane & 7);
    const int bKsel = (lane >> 3) & 1;

    #pragma unroll
    for (int p = 0; p < 3; p++) {
        const uint32_t abase = sb + (p == 2 ? F_A_LO : F_A_HI);
        const uint32_t bbase = sb + (p == 1 ? F_B_LO : F_B_HI);
        #pragma unroll
        for (int ks = 0; ks < 8; ks++) {
            uint32_t a[2][4];
            #pragma unroll
            for (int mt = 0; mt < 2; mt++) {
                int row = aRow + mt * 16;
                int kc  = ks * 2 + aKsel;
                ldsm_x4(abase + row * 256 + (((kc ^ (row & 7)) << 4)), a[mt]);
            }
            uint32_t b[2][4];
            #pragma unroll
            for (int bt = 0; bt < 2; bt++) {
                int n  = bN + bt * 16;
                int kc = ks * 2 + bKsel;
                ldsm_x4(bbase + n * 256 + (((kc ^ (n & 7)) << 4)), b[bt]);
            }
            #pragma unroll
            for (int mt = 0; mt < 2; mt++)
                #pragma unroll
                for (int nt = 0; nt < 4; nt++)
                    mma_bf16(acc[mt][nt], a[mt], b[nt >> 1][(nt & 1) * 2], b[nt >> 1][(nt & 1) * 2 + 1]);
        }
    }

    #pragma unroll
    for (int mt = 0; mt < 2; mt++) {
        int row = m0 + mg * 32 + mt * 16 + (lane >> 2);
        #pragma unroll
        for (int nt = 0; nt < 4; nt++) {
            int col = ng * 32 + nt * 8 + (lane & 3) * 2;
            float b0 = bf[col], b1 = bf[col + 1];
            if (row < M) {
                *reinterpret_cast<float2*>(outp + (size_t)row * DIM + col) =
                    make_float2(acc[mt][nt][0] + b0, acc[mt][nt][1] + b1);
                if (row + 8 < M)
                    *reinterpret_cast<float2*>(outp + (size_t)(row + 8) * DIM + col) =
                        make_float2(acc[mt][nt][2] + b0, acc[mt][nt][3] + b1);
            }
        }
    }
}

// ------------------------- K3: fused attention, warp per (b,l), dual chain ---
__global__ void __launch_bounds__(256) k_attn(const int* __restrict__ queries,
                                              const int* __restrict__ keys,
                                              const float* __restrict__ E,
                                              const float* __restrict__ bk,
                                              const float* __restrict__ bv,
                                              int L2, int M) {
    const int t      = threadIdx.x;
    const int w      = t >> 5;
    const int lane   = t & 31;
    const int lane16 = lane & 15;
    const int sel    = lane >> 4;
    const int bl     = blockIdx.x * 8 + w;

    __shared__ uint2 s_km[8][52];       // {byte offset kid*256, mask as float}

    if (bl < M) {
        for (int i = lane; i < 52; i += 32) {
            uint2 v = make_uint2(0u, 0u);
            if (i < L2) {
                int kid = keys[bl * L2 + i];
                float m = (g_Esum[kid] == 0.0f) ? 0.0f : 1.0f;
                v = make_uint2((uint32_t)kid << 8, __float_as_uint(m));
            }
            s_km[w][i] = v;
        }
    }
    __syncwarp();
    if (bl >= M) return;

    const float4* qp  = reinterpret_cast<const float4*>(g_Q + (size_t)bl * DIM + lane16 * 8);
    const float4* bkp = reinterpret_cast<const float4*>(bk + lane16 * 8);
    const float4 qa = qp[0], qb = qp[1];
    const float4 ba = bkp[0], bb = bkp[1];
    float corrp = qa.x * ba.x + qa.y * ba.y + qa.z * ba.z + qa.w * ba.w
                + qb.x * bb.x + qb.y * bb.y + qb.z * bb.z + qb.w * bb.w;

    const float RS = 0.17677669529663687f;   // 1/sqrt(32)
    const char* ekb = reinterpret_cast<const char*>(g_EKbf);
    const char* evb = reinterpret_cast<const char*>(g_EVbf);
    const uint32_t lo16 = lane16 * 16;

    float a0 = 0.f, a1 = 0.f, a2 = 0.f, a3 = 0.f;
    float a4 = 0.f, a5 = 0.f, a6 = 0.f, a7 = 0.f;
    float sumw = 0.f;

    const int np = (L2 + 3) >> 2;
    for (int i = 0; i < np; i++) {
        uint2 km0 = s_km[w][4 * i + sel];
        uint2 km1 = s_km[w][4 * i + 2 + sel];
        uint4 kr0 = *reinterpret_cast<const uint4*>(ekb + km0.x + lo16);
        uint4 kr1 = *reinterpret_cast<const uint4*>(ekb + km1.x + lo16);
        uint4 vr0 = *reinterpret_cast<const uint4*>(evb + km0.x + lo16);
        uint4 vr1 = *reinterpret_cast<const uint4*>(evb + km1.x + lo16);
        float p0 = corrp, p1 = corrp;
        p0 = fmaf(qa.x, bflo(kr0.x), p0); p1 = fmaf(qa.x, bflo(kr1.x), p1);
        p0 = fmaf(qa.y, bfhi(kr0.x), p0); p1 = fmaf(qa.y, bfhi(kr1.x), p1);
        p0 = fmaf(qa.z, bflo(kr0.y), p0); p1 = fmaf(qa.z, bflo(kr1.y), p1);
        p0 = fmaf(qa.w, bfhi(kr0.y), p0); p1 = fmaf(qa.w, bfhi(kr1.y), p1);
        p0 = fmaf(qb.x, bflo(kr0.z), p0); p1 = fmaf(qb.x, bflo(kr1.z), p1);
        p0 = fmaf(qb.y, bfhi(kr0.z), p0); p1 = fmaf(qb.y, bfhi(kr1.z), p1);
        p0 = fmaf(qb.z, bflo(kr0.w), p0); p1 = fmaf(qb.z, bflo(kr1.w), p1);
        p0 = fmaf(qb.w, bfhi(kr0.w), p0); p1 = fmaf(qb.w, bfhi(kr1.w), p1);
        p0 += __shfl_xor_sync(0xffffffffu, p0, 1);
        p1 += __shfl_xor_sync(0xffffffffu, p1, 1);
        p0 += __shfl_xor_sync(0xffffffffu, p0, 2);
        p1 += __shfl_xor_sync(0xffffffffu, p1, 2);
        float w0 = __uint_as_float(km0.y) * __expf(p0 * RS);
        float w1 = __uint_as_float(km1.y) * __expf(p1 * RS);
        a0 = fmaf(w0, bflo(vr0.x), a0); a0 = fmaf(w1, bflo(vr1.x), a0);
        a1 = fmaf(w0, bfhi(vr0.x), a1); a1 = fmaf(w1, bfhi(vr1.x), a1);
        a2 = fmaf(w0, bflo(vr0.y), a2); a2 = fmaf(w1, bflo(vr1.y), a2);
        a3 = fmaf(w0, bfhi(vr0.y), a3); a3 = fmaf(w1, bfhi(vr1.y), a3);
        a4 = fmaf(w0, bflo(vr0.z), a4); a4 = fmaf(w1, bflo(vr1.z), a4);
        a5 = fmaf(w0, bfhi(vr0.z), a5); a5 = fmaf(w1, bfhi(vr1.z), a5);
        a6 = fmaf(w0, bflo(vr0.w), a6); a6 = fmaf(w1, bflo(vr1.w), a6);
        a7 = fmaf(w0, bfhi(vr0.w), a7); a7 = fmaf(w1, bfhi(vr1.w), a7);
        sumw += w0 + w1;
    }

    sumw += __shfl_xor_sync(0xffffffffu, sumw, 16);
    a0 += __shfl_xor_sync(0xffffffffu, a0, 16);
    a1 += __shfl_xor_sync(0xffffffffu, a1, 16);
    a2 += __shfl_xor_sync(0xffffffffu, a2, 16);
    a3 += __shfl_xor_sync(0xffffffffu, a3, 16);
    a4 += __shfl_xor_sync(0xffffffffu, a4, 16);
    a5 += __shfl_xor_sync(0xffffffffu, a5, 16);
    a6 += __shfl_xor_sync(0xffffffffu, a6, 16);
    a7 += __shfl_xor_sync(0xffffffffu, a7, 16);

    const float inv = 1.0f / sumw;
    const int   qid = queries[bl];
    const int   d0  = lane16 * 8 + sel * 4;
    const float4 bv4 = *reinterpret_cast<const float4*>(bv + d0);
    const float4 qe4 = *reinterpret_cast<const float4*>(E + (size_t)qid * DIM + d0);
    float4 o;
    if (sel == 0) {
        o.x = fmaf(a0, inv, bv4.x + qe4.x);
        o.y = fmaf(a1, inv, bv4.y + qe4.y);
        o.z = fmaf(a2, inv, bv4.z + qe4.z);
        o.w = fmaf(a3, inv, bv4.w + qe4.w);
    } else {
        o.x = fmaf(a4, inv, bv4.x + qe4.x);
        o.y = fmaf(a5, inv, bv4.y + qe4.y);
        o.z = fmaf(a6, inv, bv4.z + qe4.z);
        o.w = fmaf(a7, inv, bv4.w + qe4.w);
    }
    *reinterpret_cast<float4*>(g_res + (size_t)bl * DIM + d0) = o;
}

// ------------------------- launch --------------------------------------------
extern "C" void kernel_launch(void* const* d_in, const int* in_sizes, int n_in,
                              void* d_out, int out_size) {
    const int*   queries = (const int*)d_in[0];
    const int*   keys    = (const int*)d_in[1];
    const float* E       = (const float*)d_in[2];
    const float* Wq      = (const float*)d_in[3];
    const float* bq      = (const float*)d_in[4];
    const float* Wk      = (const float*)d_in[5];
    const float* bk      = (const float*)d_in[6];
    const float* Wv      = (const float*)d_in[7];
    const float* bv      = (const float*)d_in[8];
    const float* Wf      = (const float*)d_in[9];
    const float* bf      = (const float*)d_in[10];
    float* out = (float*)d_out;

    const int V  = in_sizes[2] / DIM;
    const int M  = in_sizes[0];
    const int L2 = in_sizes[1] / M;

    cudaFuncSetAttribute(k_proj_mma, cudaFuncAttributeMaxDynamicSharedMemorySize, PROJ_SMEM);
    cudaFuncSetAttribute(k_gemm_f,   cudaFuncAttributeMaxDynamicSharedMemorySize, GEMMF_SMEM);

    const int nq    = (M + 127) / 128;
    const int nproj = (V + 63) / 64;

    k_wprep<<<32, 256>>>(Wk, Wv, Wq, Wf);
    k_proj_mma<<<nq + nproj, 512, PROJ_SMEM>>>(E, queries, bq, V, M, nq);
    k_attn<<<(M + 7) / 8, 256>>>(queries, keys, E, bk, bv, L2, M);
    k_gemm_f<<<(M + 127) / 128, 512, GEMMF_SMEM>>>(bf, out, M);
}

// round 13
// speedup vs baseline: 5.5540x; 1.0004x over previous
#include <cuda_runtime.h>
#include <cuda_bf16.h>
#include <cstdint>

#define VOCAB_MAX 100000
#define BL_MAX    12800
#define DIM       128
#define NHEAD     4

// ------------------------- scratch (device globals) -------------------------
__device__ __nv_bfloat16 g_EKbf[VOCAB_MAX * DIM];   // E @ Wk  (bf16)
__device__ __nv_bfloat16 g_EVbf[VOCAB_MAX * DIM];   // E @ Wv  (bf16)
__device__ float g_Esum[VOCAB_MAX];
__device__ float g_Q[BL_MAX * DIM];
__device__ float g_res[BL_MAX * DIM];
// swizzled W^T images (n-major, k contiguous, kc ^= n&7)
__device__ uint4 g_WT16[4096];   // [Wk|Wv] fp16: [n=256][kc=16]
__device__ uint4 g_WQ16[2048];   // Wq fp16:      [n=128][kc=16]
__device__ uint4 g_WFhi[2048];   // Wf bf16 hi
__device__ uint4 g_WFlo[2048];   // Wf bf16 lo

// ------------------------- helpers ------------------------------------------
__device__ __forceinline__ uint32_t smem_to_u32(const void* p) {
    uint32_t a;
    asm("{ .reg .u64 t; cvta.to.shared.u64 t, %1; cvt.u32.u64 %0, t; }" : "=r"(a) : "l"(p));
    return a;
}
__device__ __forceinline__ uint32_t pack_bf2(float lo, float hi) {
    uint32_t r; asm("cvt.rn.bf16x2.f32 %0, %1, %2;" : "=r"(r) : "f"(hi), "f"(lo)); return r;
}
__device__ __forceinline__ uint32_t pack_h2(float lo, float hi) {
    uint32_t r; asm("cvt.rn.f16x2.f32 %0, %1, %2;" : "=r"(r) : "f"(hi), "f"(lo)); return r;
}
__device__ __forceinline__ void ldsm_x4(uint32_t addr, uint32_t* r) {
    asm volatile("ldmatrix.sync.aligned.m8n8.x4.shared.b16 {%0,%1,%2,%3}, [%4];"
                 : "=r"(r[0]), "=r"(r[1]), "=r"(r[2]), "=r"(r[3]) : "r"(addr));
}
__device__ __forceinline__ void mma_bf16(float* c, const uint32_t* a, uint32_t b0, uint32_t b1) {
    asm volatile("mma.sync.aligned.m16n8k16.row.col.f32.bf16.bf16.f32 "
                 "{%0,%1,%2,%3}, {%4,%5,%6,%7}, {%8,%9}, {%0,%1,%2,%3};"
                 : "+f"(c[0]), "+f"(c[1]), "+f"(c[2]), "+f"(c[3])
                 : "r"(a[0]), "r"(a[1]), "r"(a[2]), "r"(a[3]), "r"(b0), "r"(b1));
}
__device__ __forceinline__ void mma_f16(float* c, const uint32_t* a, uint32_t b0, uint32_t b1) {
    asm volatile("mma.sync.aligned.m16n8k16.row.col.f32.f16.f16.f32 "
                 "{%0,%1,%2,%3}, {%4,%5,%6,%7}, {%8,%9}, {%0,%1,%2,%3};"
                 : "+f"(c[0]), "+f"(c[1]), "+f"(c[2]), "+f"(c[3])
                 : "r"(a[0]), "r"(a[1]), "r"(a[2]), "r"(a[3]), "r"(b0), "r"(b1));
}
__device__ __forceinline__ void split2(float x, float y, uint32_t& h, uint32_t& l) {
    h = pack_bf2(x, y);
    l = pack_bf2(x - __uint_as_float(h << 16), y - __uint_as_float(h & 0xffff0000u));
}
__device__ __forceinline__ float bflo(uint32_t u) { return __uint_as_float(u << 16); }
__device__ __forceinline__ float bfhi(uint32_t u) { return __uint_as_float(u & 0xffff0000u); }

// ------------------------- K0: prep all W^T images ---------------------------
__global__ void k_wprep(const float* __restrict__ Wk, const float* __restrict__ Wv,
                        const float* __restrict__ Wq, const float* __restrict__ Wf) {
    int u = blockIdx.x * blockDim.x + threadIdx.x;    // 8192 units
    const float* src;
    int n, kc, kind;
    uint4 *dst16 = nullptr, *dh = nullptr, *dl = nullptr;
    if (u < 4096) {
        n = u & 255; kc = u >> 8; kind = 0;
        src = (n < 128) ? (Wk + n) : (Wv + (n - 128));
        dst16 = g_WT16 + n * 16 + (kc ^ (n & 7));
    } else if (u < 6144) {
        int u2 = u - 4096; n = u2 & 127; kc = u2 >> 7; kind = 1;
        src = Wq + n;
        dst16 = g_WQ16 + n * 16 + (kc ^ (n & 7));
    } else {
        int u2 = u - 6144; n = u2 & 127; kc = u2 >> 7; kind = 2;
        src = Wf + n;
        int idx = n * 16 + (kc ^ (n & 7));
        dh = g_WFhi + idx; dl = g_WFlo + idx;
    }
    float f[8];
    #pragma unroll
    for (int i = 0; i < 8; i++) f[i] = src[(size_t)(kc * 8 + i) * DIM];
    if (kind < 2) {
        uint32_t h[4];
        #pragma unroll
        for (int i = 0; i < 4; i++) h[i] = pack_h2(f[2 * i], f[2 * i + 1]);
        *dst16 = make_uint4(h[0], h[1], h[2], h[3]);
    } else {
        uint32_t h[4], l[4];
        #pragma unroll
        for (int i = 0; i < 4; i++) split2(f[2 * i], f[2 * i + 1], h[i], l[i]);
        *dh = make_uint4(h[0], h[1], h[2], h[3]);
        *dl = make_uint4(l[0], l[1], l[2], l[3]);
    }
}

// ------------------------- K1: fused proj + Q gemm ---------------------------
// Blocks [0, nq): Q = gather(E,queries)@Wq + bq (fp16, M=128 x N=128)
// Blocks [nq, ...): EK|EV = E @ [Wk|Wv]        (fp16, M=64  x N=256)
#define P_A   0
#define P_B   16384
#define P_OUT 81920
#define Q_A   0
#define Q_B   32768
#define PROJ_SMEM 114688

__device__ void gemm_q_path(char* smem, uint32_t sb,
                            const float* __restrict__ E,
                            const int* __restrict__ queries,
                            const float* __restrict__ bq, int M, int bx) {
    const int t    = threadIdx.x;
    const int w    = t >> 5;
    const int lane = t & 31;
    const int m0   = bx * 128;

    #pragma unroll
    for (int i = 0; i < 4; i++) {
        int u   = t + 512 * i;
        int row = u >> 4;
        int kc  = u & 15;
        int m   = m0 + row;
        int mm  = (m < M) ? m : 0;
        const float4* src = reinterpret_cast<const float4*>(E + (size_t)queries[mm] * DIM + kc * 8);
        float4 f0 = src[0], f1 = src[1];
        uint32_t h0 = pack_h2(f0.x, f0.y), h1 = pack_h2(f0.z, f0.w);
        uint32_t h2 = pack_h2(f1.x, f1.y), h3 = pack_h2(f1.z, f1.w);
        uint32_t off = (uint32_t)row * 256 + (uint32_t)((kc ^ (row & 7)) << 4);
        *reinterpret_cast<uint4*>(smem + Q_A + off) = make_uint4(h0, h1, h2, h3);
    }
    {
        uint4* d = reinterpret_cast<uint4*>(smem + Q_B);
        #pragma unroll
        for (int i = 0; i < 4; i++) {
            int idx = t + 512 * i;
            d[idx] = g_WQ16[idx];
        }
    }
    __syncthreads();

    const int mg = w & 3;
    const int ng = w >> 2;

    float acc[2][4][4];
    #pragma unroll
    for (int mt = 0; mt < 2; mt++)
        #pragma unroll
        for (int nt = 0; nt < 4; nt++)
            #pragma unroll
            for (int j = 0; j < 4; j++) acc[mt][nt][j] = 0.f;

    const int aRow  = mg * 32 + ((lane >> 3) & 1) * 8 + (lane & 7);
    const int aKsel = (lane >> 4);
    const int bN    = ng * 32 + ((lane >> 4) & 1) * 8 + (lane & 7);
    const int bKsel = (lane >> 3) & 1;

    #pragma unroll
    for (int ks = 0; ks < 8; ks++) {
        uint32_t a[2][4];
        #pragma unroll
        for (int mt = 0; mt < 2; mt++) {
            int row = aRow + mt * 16;
            int kc  = ks * 2 + aKsel;
            ldsm_x4(sb + Q_A + row * 256 + (((kc ^ (row & 7)) << 4)), a[mt]);
        }
        uint32_t b[2][4];
        #pragma unroll
        for (int bt = 0; bt < 2; bt++) {
            int n  = bN + bt * 16;
            int kc = ks * 2 + bKsel;
            ldsm_x4(sb + Q_B + n * 256 + (((kc ^ (n & 7)) << 4)), b[bt]);
        }
        #pragma unroll
        for (int mt = 0; mt < 2; mt++)
            #pragma unroll
            for (int nt = 0; nt < 4; nt++)
                mma_f16(acc[mt][nt], a[mt], b[nt >> 1][(nt & 1) * 2], b[nt >> 1][(nt & 1) * 2 + 1]);
    }

    #pragma unroll
    for (int mt = 0; mt < 2; mt++) {
        int row = m0 + mg * 32 + mt * 16 + (lane >> 2);
        #pragma unroll
        for (int nt = 0; nt < 4; nt++) {
            int col = ng * 32 + nt * 8 + (lane & 3) * 2;
            float b0 = bq[col], b1 = bq[col + 1];
            if (row < M) {
                *reinterpret_cast<float2*>(g_Q + (size_t)row * DIM + col) =
                    make_float2(acc[mt][nt][0] + b0, acc[mt][nt][1] + b1);
                if (row + 8 < M)
                    *reinterpret_cast<float2*>(g_Q + (size_t)(row + 8) * DIM + col) =
                        make_float2(acc[mt][nt][2] + b0, acc[mt][nt][3] + b1);
            }
        }
    }
}

__global__ void __launch_bounds__(512, 2)
k_proj_mma(const float* __restrict__ E, const int* __restrict__ queries,
           const float* __restrict__ bq, int V, int M, int nq) {
    extern __shared__ char smem[];
    const uint32_t sb = smem_to_u32(smem);

    if ((int)blockIdx.x < nq) {
        gemm_q_path(smem, sb, E, queries, bq, M, blockIdx.x);
        return;
    }

    const int t    = threadIdx.x;
    const int w    = t >> 5;
    const int lane = t & 31;
    const int v0   = (blockIdx.x - nq) * 64;

    #pragma unroll
    for (int i = 0; i < 2; i++) {
        int u   = t + 512 * i;
        int row = u >> 4;
        int kc  = u & 15;
        int gr  = v0 + row;
        int grc = (gr < V) ? gr : 0;
        const float4* src = reinterpret_cast<const float4*>(E + (size_t)grc * DIM + kc * 8);
        float4 f0 = __ldcs(src);
        float4 f1 = __ldcs(src + 1);
        uint32_t h0 = pack_h2(f0.x, f0.y), h1 = pack_h2(f0.z, f0.w);
        uint32_t h2 = pack_h2(f1.x, f1.y), h3 = pack_h2(f1.z, f1.w);
        uint32_t off = (uint32_t)row * 256 + (uint32_t)((kc ^ (row & 7)) << 4);
        *reinterpret_cast<uint4*>(smem + P_A + off) = make_uint4(h0, h1, h2, h3);
        float s8 = ((f0.x + f0.y) + (f0.z + f0.w)) + ((f1.x + f1.y) + (f1.z + f1.w));
        s8 += __shfl_xor_sync(0xffffffffu, s8, 8);
        s8 += __shfl_xor_sync(0xffffffffu, s8, 4);
        s8 += __shfl_xor_sync(0xffffffffu, s8, 2);
        s8 += __shfl_xor_sync(0xffffffffu, s8, 1);
        if ((t & 15) == 0 && gr < V) g_Esum[gr] = s8;
    }
    {
        uint4* d = reinterpret_cast<uint4*>(smem + P_B);
        #pragma unroll
        for (int i = 0; i < 8; i++) {
            int idx = t + 512 * i;
            d[idx] = g_WT16[idx];
        }
    }
    __syncthreads();

    const int mg = w & 3;
    const int ng = w >> 2;

    float acc[8][4];
    #pragma unroll
    for (int nt = 0; nt < 8; nt++)
        #pragma unroll
        for (int j = 0; j < 4; j++) acc[nt][j] = 0.f;

    const int aRow  = mg * 16 + ((lane >> 3) & 1) * 8 + (lane & 7);
    const int aKsel = (lane >> 4);
    const int bN    = ng * 64 + ((lane >> 4) & 1) * 8 + (lane & 7);
    const int bKsel = (lane >> 3) & 1;

    #pragma unroll
    for (int ks = 0; ks < 8; ks++) {
        uint32_t a[4];
        {
            int kc = ks * 2 + aKsel;
            ldsm_x4(sb + P_A + aRow * 256 + (((kc ^ (aRow & 7)) << 4)), a);
        }
        {
            uint32_t b[2][4];
            #pragma unroll
            for (int bt = 0; bt < 2; bt++) {
                int n  = bN + bt * 16;
                int kc = ks * 2 + bKsel;
                ldsm_x4(sb + P_B + n * 256 + (((kc ^ (n & 7)) << 4)), b[bt]);
            }
            #pragma unroll
            for (int nt = 0; nt < 4; nt++)
                mma_f16(acc[nt], a, b[nt >> 1][(nt & 1) * 2], b[nt >> 1][(nt & 1) * 2 + 1]);
        }
        {
            uint32_t b[2][4];
            #pragma unroll
            for (int bt = 0; bt < 2; bt++) {
                int n  = bN + (bt + 2) * 16;
                int kc = ks * 2 + bKsel;
                ldsm_x4(sb + P_B + n * 256 + (((kc ^ (n & 7)) << 4)), b[bt]);
            }
            #pragma unroll
            for (int nt = 4; nt < 8; nt++)
                mma_f16(acc[nt], a, b[(nt - 4) >> 1][(nt & 1) * 2], b[(nt - 4) >> 1][(nt & 1) * 2 + 1]);
        }
    }

    __syncthreads();
    {
        int rl  = mg * 16 + (lane >> 2);
        int rl2 = rl + 8;
        #pragma unroll
        for (int nt = 0; nt < 8; nt++) {
            int colb = (ng * 64 + nt * 8 + (lane & 3) * 2) * 2;
            uint32_t b0 = pack_bf2(acc[nt][0], acc[nt][1]);
            uint32_t b1 = pack_bf2(acc[nt][2], acc[nt][3]);
            *reinterpret_cast<uint32_t*>(smem + P_OUT + rl  * 512 + (colb ^ ((rl  & 7) << 4))) = b0;
            *reinterpret_cast<uint32_t*>(smem + P_OUT + rl2 * 512 + (colb ^ ((rl2 & 7) << 4))) = b1;
        }
    }
    __syncthreads();
    {
        #pragma unroll
        for (int i = 0; i < 4; i++) {
            int idx = t + 512 * i;
            int row = idx >> 5, c16 = idx & 31;
            int gr = v0 + row;
            if (gr < V) {
                uint4 val = *reinterpret_cast<uint4*>(
                    smem + P_OUT + row * 512 + ((c16 * 16) ^ ((row & 7) << 4)));
                __nv_bfloat16* table = (c16 < 16) ? g_EKbf : g_EVbf;
                reinterpret_cast<uint4*>(table + (size_t)gr * DIM)[c16 & 15] = val;
            }
        }
    }
}

// ------------------------- K2b: final gemm (bf16 3-pass, M=64, 256 thr) ------
// 8 warps, warp tile 32x32; 200 CTAs, 2 CTAs/SM -> latency hidden by occupancy
#define F_A_HI 0
#define F_A_LO 16384
#define F_B_HI 32768
#define F_B_LO 65536
#define GEMMF_SMEM 98304

__global__ void __launch_bounds__(256, 2)
k_gemm_f(const float* __restrict__ bf, float* __restrict__ outp, int M) {
    extern __shared__ char smem[];
    const uint32_t sb = smem_to_u32(smem);
    const int t    = threadIdx.x;
    const int w    = t >> 5;
    const int lane = t & 31;
    const int m0   = blockIdx.x * 64;

    // stage A: 64 rows x 16 kc = 1024 units
    #pragma unroll
    for (int i = 0; i < 4; i++) {
        int u   = t + 256 * i;
        int row = u >> 4;
        int kc  = u & 15;
        int m   = m0 + row;
        const float4* src = reinterpret_cast<const float4*>(
            g_res + (size_t)((m < M) ? m : 0) * DIM + kc * 8);
        float4 f0 = src[0], f1 = src[1];
        uint32_t h0, h1, h2, h3, l0, l1, l2, l3;
        split2(f0.x, f0.y, h0, l0); split2(f0.z, f0.w, h1, l1);
        split2(f1.x, f1.y, h2, l2); split2(f1.z, f1.w, h3, l3);
        uint32_t off = (uint32_t)row * 256 + (uint32_t)((kc ^ (row & 7)) << 4);
        *reinterpret_cast<uint4*>(smem + F_A_HI + off) = make_uint4(h0, h1, h2, h3);
        *reinterpret_cast<uint4*>(smem + F_A_LO + off) = make_uint4(l0, l1, l2, l3);
    }
    // stage B: 2048 uint4 hi + 2048 lo
    {
        uint4* dh = reinterpret_cast<uint4*>(smem + F_B_HI);
        uint4* dl = reinterpret_cast<uint4*>(smem + F_B_LO);
        #pragma unroll
        for (int i = 0; i < 8; i++) {
            int idx = t + 256 * i;
            dh[idx] = g_WFhi[idx];
            dl[idx] = g_WFlo[idx];
        }
    }
    __syncthreads();

    const int mg = w & 1;        // 2 row groups of 32
    const int ng = w >> 1;       // 4 col groups of 32

    float acc[2][4][4];
    #pragma unroll
    for (int mt = 0; mt < 2; mt++)
        #pragma unroll
        for (int nt = 0; nt < 4; nt++)
            #pragma unroll
            for (int j = 0; j < 4; j++) acc[mt][nt][j] = 0.f;

    const int aRow  = mg * 32 + ((lane >> 3) & 1) * 8 + (lane & 7);
    const int aKsel = (lane >> 4);
    const int bN    = ng * 32 + ((lane >> 4) & 1) * 8 + (lane & 7);
    const int bKsel = (lane >> 3) & 1;

    #pragma unroll
    for (int p = 0; p < 3; p++) {
        const uint32_t abase = sb + (p == 2 ? F_A_LO : F_A_HI);
        const uint32_t bbase = sb + (p == 1 ? F_B_LO : F_B_HI);
        #pragma unroll
        for (int ks = 0; ks < 8; ks++) {
            uint32_t a[2][4];
            #pragma unroll
            for (int mt = 0; mt < 2; mt++) {
                int row = aRow + mt * 16;
                int kc  = ks * 2 + aKsel;
                ldsm_x4(abase + row * 256 + (((kc ^ (row & 7)) << 4)), a[mt]);
            }
            uint32_t b[2][4];
            #pragma unroll
            for (int bt = 0; bt < 2; bt++) {
                int n  = bN + bt * 16;
                int kc = ks * 2 + bKsel;
                ldsm_x4(bbase + n * 256 + (((kc ^ (n & 7)) << 4)), b[bt]);
            }
            #pragma unroll
            for (int mt = 0; mt < 2; mt++)
                #pragma unroll
                for (int nt = 0; nt < 4; nt++)
                    mma_bf16(acc[mt][nt], a[mt], b[nt >> 1][(nt & 1) * 2], b[nt >> 1][(nt & 1) * 2 + 1]);
        }
    }

    #pragma unroll
    for (int mt = 0; mt < 2; mt++) {
        int row = m0 + mg * 32 + mt * 16 + (lane >> 2);
        #pragma unroll
        for (int nt = 0; nt < 4; nt++) {
            int col = ng * 32 + nt * 8 + (lane & 3) * 2;
            float b0 = bf[col], b1 = bf[col + 1];
            if (row < M) {
                *reinterpret_cast<float2*>(outp + (size_t)row * DIM + col) =
                    make_float2(acc[mt][nt][0] + b0, acc[mt][nt][1] + b1);
                if (row + 8 < M)
                    *reinterpret_cast<float2*>(outp + (size_t)(row + 8) * DIM + col) =
                        make_float2(acc[mt][nt][2] + b0, acc[mt][nt][3] + b1);
            }
        }
    }
}

// ------------------------- K3: fused attention, warp per (b,l), dual chain ---
__global__ void __launch_bounds__(256) k_attn(const int* __restrict__ queries,
                                              const int* __restrict__ keys,
                                              const float* __restrict__ E,
                                              const float* __restrict__ bk,
                                              const float* __restrict__ bv,
                                              int L2, int M) {
    const int t      = threadIdx.x;
    const int w      = t >> 5;
    const int lane   = t & 31;
    const int lane16 = lane & 15;
    const int sel    = lane >> 4;
    const int bl     = blockIdx.x * 8 + w;

    __shared__ uint2 s_km[8][52];       // {byte offset kid*256, mask as float}

    if (bl < M) {
        for (int i = lane; i < 52; i += 32) {
            uint2 v = make_uint2(0u, 0u);
            if (i < L2) {
                int kid = keys[bl * L2 + i];
                float m = (g_Esum[kid] == 0.0f) ? 0.0f : 1.0f;
                v = make_uint2((uint32_t)kid << 8, __float_as_uint(m));
            }
            s_km[w][i] = v;
        }
    }
    __syncwarp();
    if (bl >= M) return;

    const float4* qp  = reinterpret_cast<const float4*>(g_Q + (size_t)bl * DIM + lane16 * 8);
    const float4* bkp = reinterpret_cast<const float4*>(bk + lane16 * 8);
    const float4 qa = qp[0], qb = qp[1];
    const float4 ba = bkp[0], bb = bkp[1];
    float corrp = qa.x * ba.x + qa.y * ba.y + qa.z * ba.z + qa.w * ba.w
                + qb.x * bb.x + qb.y * bb.y + qb.z * bb.z + qb.w * bb.w;

    const float RS = 0.17677669529663687f;   // 1/sqrt(32)
    const char* ekb = reinterpret_cast<const char*>(g_EKbf);
    const char* evb = reinterpret_cast<const char*>(g_EVbf);
    const uint32_t lo16 = lane16 * 16;

    float a0 = 0.f, a1 = 0.f, a2 = 0.f, a3 = 0.f;
    float a4 = 0.f, a5 = 0.f, a6 = 0.f, a7 = 0.f;
    float sumw = 0.f;

    const int np = (L2 + 3) >> 2;
    for (int i = 0; i < np; i++) {
        uint2 km0 = s_km[w][4 * i + sel];
        uint2 km1 = s_km[w][4 * i + 2 + sel];
        uint4 kr0 = *reinterpret_cast<const uint4*>(ekb + km0.x + lo16);
        uint4 kr1 = *reinterpret_cast<const uint4*>(ekb + km1.x + lo16);
        uint4 vr0 = *reinterpret_cast<const uint4*>(evb + km0.x + lo16);
        uint4 vr1 = *reinterpret_cast<const uint4*>(evb + km1.x + lo16);
        float p0 = corrp, p1 = corrp;
        p0 = fmaf(qa.x, bflo(kr0.x), p0); p1 = fmaf(qa.x, bflo(kr1.x), p1);
        p0 = fmaf(qa.y, bfhi(kr0.x), p0); p1 = fmaf(qa.y, bfhi(kr1.x), p1);
        p0 = fmaf(qa.z, bflo(kr0.y), p0); p1 = fmaf(qa.z, bflo(kr1.y), p1);
        p0 = fmaf(qa.w, bfhi(kr0.y), p0); p1 = fmaf(qa.w, bfhi(kr1.y), p1);
        p0 = fmaf(qb.x, bflo(kr0.z), p0); p1 = fmaf(qb.x, bflo(kr1.z), p1);
        p0 = fmaf(qb.y, bfhi(kr0.z), p0); p1 = fmaf(qb.y, bfhi(kr1.z), p1);
        p0 = fmaf(qb.z, bflo(kr0.w), p0); p1 = fmaf(qb.z, bflo(kr1.w), p1);
        p0 = fmaf(qb.w, bfhi(kr0.w), p0); p1 = fmaf(qb.w, bfhi(kr1.w), p1);
        p0 += __shfl_xor_sync(0xffffffffu, p0, 1);
        p1 += __shfl_xor_sync(0xffffffffu, p1, 1);
        p0 += __shfl_xor_sync(0xffffffffu, p0, 2);
        p1 += __shfl_xor_sync(0xffffffffu, p1, 2);
        float w0 = __uint_as_float(km0.y) * __expf(p0 * RS);
        float w1 = __uint_as_float(km1.y) * __expf(p1 * RS);
        a0 = fmaf(w0, bflo(vr0.x), a0); a0 = fmaf(w1, bflo(vr1.x), a0);
        a1 = fmaf(w0, bfhi(vr0.x), a1); a1 = fmaf(w1, bfhi(vr1.x), a1);
        a2 = fmaf(w0, bflo(vr0.y), a2); a2 = fmaf(w1, bflo(vr1.y), a2);
        a3 = fmaf(w0, bfhi(vr0.y), a3); a3 = fmaf(w1, bfhi(vr1.y), a3);
        a4 = fmaf(w0, bflo(vr0.z), a4); a4 = fmaf(w1, bflo(vr1.z), a4);
        a5 = fmaf(w0, bfhi(vr0.z), a5); a5 = fmaf(w1, bfhi(vr1.z), a5);
        a6 = fmaf(w0, bflo(vr0.w), a6); a6 = fmaf(w1, bflo(vr1.w), a6);
        a7 = fmaf(w0, bfhi(vr0.w), a7); a7 = fmaf(w1, bfhi(vr1.w), a7);
        sumw += w0 + w1;
    }

    sumw += __shfl_xor_sync(0xffffffffu, sumw, 16);
    a0 += __shfl_xor_sync(0xffffffffu, a0, 16);
    a1 += __shfl_xor_sync(0xffffffffu, a1, 16);
    a2 += __shfl_xor_sync(0xffffffffu, a2, 16);
    a3 += __shfl_xor_sync(0xffffffffu, a3, 16);
    a4 += __shfl_xor_sync(0xffffffffu, a4, 16);
    a5 += __shfl_xor_sync(0xffffffffu, a5, 16);
    a6 += __shfl_xor_sync(0xffffffffu, a6, 16);
    a7 += __shfl_xor_sync(0xffffffffu, a7, 16);

    const float inv = 1.0f / sumw;
    const int   qid = queries[bl];
    const int   d0  = lane16 * 8 + sel * 4;
    const float4 bv4 = *reinterpret_cast<const float4*>(bv + d0);
    const float4 qe4 = *reinterpret_cast<const float4*>(E + (size_t)qid * DIM + d0);
    float4 o;
    if (sel == 0) {
        o.x = fmaf(a0, inv, bv4.x + qe4.x);
        o.y = fmaf(a1, inv, bv4.y + qe4.y);
        o.z = fmaf(a2, inv, bv4.z + qe4.z);
        o.w = fmaf(a3, inv, bv4.w + qe4.w);
    } else {
        o.x = fmaf(a4, inv, bv4.x + qe4.x);
        o.y = fmaf(a5, inv, bv4.y + qe4.y);
        o.z = fmaf(a6, inv, bv4.z + qe4.z);
        o.w = fmaf(a7, inv, bv4.w + qe4.w);
    }
    *reinterpret_cast<float4*>(g_res + (size_t)bl * DIM + d0) = o;
}

// ------------------------- launch --------------------------------------------
extern "C" void kernel_launch(void* const* d_in, const int* in_sizes, int n_in,
                              void* d_out, int out_size) {
    const int*   queries = (const int*)d_in[0];
    const int*   keys    = (const int*)d_in[1];
    const float* E       = (const float*)d_in[2];
    const float* Wq      = (const float*)d_in[3];
    const float* bq      = (const float*)d_in[4];
    const float* Wk      = (const float*)d_in[5];
    const float* bk      = (const float*)d_in[6];
    const float* Wv      = (const float*)d_in[7];
    const float* bv      = (const float*)d_in[8];
    const float* Wf      = (const float*)d_in[9];
    const float* bf      = (const float*)d_in[10];
    float* out = (float*)d_out;

    const int V  = in_sizes[2] / DIM;
    const int M  = in_sizes[0];
    const int L2 = in_sizes[1] / M;

    cudaFuncSetAttribute(k_proj_mma, cudaFuncAttributeMaxDynamicSharedMemorySize, PROJ_SMEM);
    cudaFuncSetAttribute(k_gemm_f,   cudaFuncAttributeMaxDynamicSharedMemorySize, GEMMF_SMEM);

    const int nq    = (M + 127) / 128;
    const int nproj = (V + 63) / 64;

    k_wprep<<<32, 256>>>(Wk, Wv, Wq, Wf);
    k_proj_mma<<<nq + nproj, 512, PROJ_SMEM>>>(E, queries, bq, V, M, nq);
    k_attn<<<(M + 7) / 8, 256>>>(queries, keys, E, bk, bv, L2, M);
    k_gemm_f<<<(M + 63) / 64, 256, GEMMF_SMEM>>>(bf, out, M);
}

// round 14
// speedup vs baseline: 5.9678x; 1.0745x over previous
#include <cuda_runtime.h>
#include <cuda_bf16.h>
#include <cstdint>

#define VOCAB_MAX 100000
#define BL_MAX    12800
#define DIM       128
#define NHEAD     4

// ------------------------- scratch (device globals) -------------------------
__device__ __nv_bfloat16 g_EKbf[VOCAB_MAX * DIM];   // E @ Wk  (bf16)
__device__ __nv_bfloat16 g_EVbf[VOCAB_MAX * DIM];   // E @ Wv  (bf16)
__device__ float g_Esum[VOCAB_MAX];
__device__ float g_Q[BL_MAX * DIM];
__device__ float g_res[BL_MAX * DIM];
// swizzled fp16 W^T images (n-major, k contiguous, kc ^= n&7)
__device__ uint4 g_WT16[4096];   // [Wk|Wv]: [n=256][kc=16]
__device__ uint4 g_WQ16[2048];   // Wq:      [n=128][kc=16]
__device__ uint4 g_WF16[2048];   // Wf:      [n=128][kc=16]

// ------------------------- helpers ------------------------------------------
__device__ __forceinline__ uint32_t smem_to_u32(const void* p) {
    uint32_t a;
    asm("{ .reg .u64 t; cvta.to.shared.u64 t, %1; cvt.u32.u64 %0, t; }" : "=r"(a) : "l"(p));
    return a;
}
__device__ __forceinline__ uint32_t pack_bf2(float lo, float hi) {
    uint32_t r; asm("cvt.rn.bf16x2.f32 %0, %1, %2;" : "=r"(r) : "f"(hi), "f"(lo)); return r;
}
__device__ __forceinline__ uint32_t pack_h2(float lo, float hi) {
    uint32_t r; asm("cvt.rn.f16x2.f32 %0, %1, %2;" : "=r"(r) : "f"(hi), "f"(lo)); return r;
}
__device__ __forceinline__ void ldsm_x4(uint32_t addr, uint32_t* r) {
    asm volatile("ldmatrix.sync.aligned.m8n8.x4.shared.b16 {%0,%1,%2,%3}, [%4];"
                 : "=r"(r[0]), "=r"(r[1]), "=r"(r[2]), "=r"(r[3]) : "r"(addr));
}
__device__ __forceinline__ void mma_f16(float* c, const uint32_t* a, uint32_t b0, uint32_t b1) {
    asm volatile("mma.sync.aligned.m16n8k16.row.col.f32.f16.f16.f32 "
                 "{%0,%1,%2,%3}, {%4,%5,%6,%7}, {%8,%9}, {%0,%1,%2,%3};"
                 : "+f"(c[0]), "+f"(c[1]), "+f"(c[2]), "+f"(c[3])
                 : "r"(a[0]), "r"(a[1]), "r"(a[2]), "r"(a[3]), "r"(b0), "r"(b1));
}
__device__ __forceinline__ float bflo(uint32_t u) { return __uint_as_float(u << 16); }
__device__ __forceinline__ float bfhi(uint32_t u) { return __uint_as_float(u & 0xffff0000u); }

// ------------------------- K0: prep all W^T fp16 images ----------------------
__global__ void k_wprep(const float* __restrict__ Wk, const float* __restrict__ Wv,
                        const float* __restrict__ Wq, const float* __restrict__ Wf) {
    int u = blockIdx.x * blockDim.x + threadIdx.x;    // 8192 units
    const float* src;
    int n, kc;
    uint4* dst;
    if (u < 4096) {
        n = u & 255; kc = u >> 8;
        src = (n < 128) ? (Wk + n) : (Wv + (n - 128));
        dst = g_WT16 + n * 16 + (kc ^ (n & 7));
    } else if (u < 6144) {
        int u2 = u - 4096; n = u2 & 127; kc = u2 >> 7;
        src = Wq + n;
        dst = g_WQ16 + n * 16 + (kc ^ (n & 7));
    } else {
        int u2 = u - 6144; n = u2 & 127; kc = u2 >> 7;
        src = Wf + n;
        dst = g_WF16 + n * 16 + (kc ^ (n & 7));
    }
    float f[8];
    #pragma unroll
    for (int i = 0; i < 8; i++) f[i] = src[(size_t)(kc * 8 + i) * DIM];
    uint32_t h[4];
    #pragma unroll
    for (int i = 0; i < 4; i++) h[i] = pack_h2(f[2 * i], f[2 * i + 1]);
    *dst = make_uint4(h[0], h[1], h[2], h[3]);
}

// ------------------------- K1: fused proj + Q gemm ---------------------------
// Blocks [0, nq): Q = gather(E,queries)@Wq + bq (fp16, M=128 x N=128)
// Blocks [nq, ...): EK|EV = E @ [Wk|Wv]        (fp16, M=64  x N=256)
#define P_A   0
#define P_B   16384
#define P_OUT 81920
#define Q_A   0
#define Q_B   32768
#define PROJ_SMEM 114688

__device__ void gemm_q_path(char* smem, uint32_t sb,
                            const float* __restrict__ E,
                            const int* __restrict__ queries,
                            const float* __restrict__ bq, int M, int bx) {
    const int t    = threadIdx.x;
    const int w    = t >> 5;
    const int lane = t & 31;
    const int m0   = bx * 128;

    #pragma unroll
    for (int i = 0; i < 4; i++) {
        int u   = t + 512 * i;
        int row = u >> 4;
        int kc  = u & 15;
        int m   = m0 + row;
        int mm  = (m < M) ? m : 0;
        const float4* src = reinterpret_cast<const float4*>(E + (size_t)queries[mm] * DIM + kc * 8);
        float4 f0 = src[0], f1 = src[1];
        uint32_t h0 = pack_h2(f0.x, f0.y), h1 = pack_h2(f0.z, f0.w);
        uint32_t h2 = pack_h2(f1.x, f1.y), h3 = pack_h2(f1.z, f1.w);
        uint32_t off = (uint32_t)row * 256 + (uint32_t)((kc ^ (row & 7)) << 4);
        *reinterpret_cast<uint4*>(smem + Q_A + off) = make_uint4(h0, h1, h2, h3);
    }
    {
        uint4* d = reinterpret_cast<uint4*>(smem + Q_B);
        #pragma unroll
        for (int i = 0; i < 4; i++) {
            int idx = t + 512 * i;
            d[idx] = g_WQ16[idx];
        }
    }
    __syncthreads();

    const int mg = w & 3;
    const int ng = w >> 2;

    float acc[2][4][4];
    #pragma unroll
    for (int mt = 0; mt < 2; mt++)
        #pragma unroll
        for (int nt = 0; nt < 4; nt++)
            #pragma unroll
            for (int j = 0; j < 4; j++) acc[mt][nt][j] = 0.f;

    const int aRow  = mg * 32 + ((lane >> 3) & 1) * 8 + (lane & 7);
    const int aKsel = (lane >> 4);
    const int bN    = ng * 32 + ((lane >> 4) & 1) * 8 + (lane & 7);
    const int bKsel = (lane >> 3) & 1;

    #pragma unroll
    for (int ks = 0; ks < 8; ks++) {
        uint32_t a[2][4];
        #pragma unroll
        for (int mt = 0; mt < 2; mt++) {
            int row = aRow + mt * 16;
            int kc  = ks * 2 + aKsel;
            ldsm_x4(sb + Q_A + row * 256 + (((kc ^ (row & 7)) << 4)), a[mt]);
        }
        uint32_t b[2][4];
        #pragma unroll
        for (int bt = 0; bt < 2; bt++) {
            int n  = bN + bt * 16;
            int kc = ks * 2 + bKsel;
            ldsm_x4(sb + Q_B + n * 256 + (((kc ^ (n & 7)) << 4)), b[bt]);
        }
        #pragma unroll
        for (int mt = 0; mt < 2; mt++)
            #pragma unroll
            for (int nt = 0; nt < 4; nt++)
                mma_f16(acc[mt][nt], a[mt], b[nt >> 1][(nt & 1) * 2], b[nt >> 1][(nt & 1) * 2 + 1]);
    }

    #pragma unroll
    for (int mt = 0; mt < 2; mt++) {
        int row = m0 + mg * 32 + mt * 16 + (lane >> 2);
        #pragma unroll
        for (int nt = 0; nt < 4; nt++) {
            int col = ng * 32 + nt * 8 + (lane & 3) * 2;
            float b0 = bq[col], b1 = bq[col + 1];
            if (row < M) {
                *reinterpret_cast<float2*>(g_Q + (size_t)row * DIM + col) =
                    make_float2(acc[mt][nt][0] + b0, acc[mt][nt][1] + b1);
                if (row + 8 < M)
                    *reinterpret_cast<float2*>(g_Q + (size_t)(row + 8) * DIM + col) =
                        make_float2(acc[mt][nt][2] + b0, acc[mt][nt][3] + b1);
            }
        }
    }
}

__global__ void __launch_bounds__(512, 2)
k_proj_mma(const float* __restrict__ E, const int* __restrict__ queries,
           const float* __restrict__ bq, int V, int M, int nq) {
    extern __shared__ char smem[];
    const uint32_t sb = smem_to_u32(smem);

    if ((int)blockIdx.x < nq) {
        gemm_q_path(smem, sb, E, queries, bq, M, blockIdx.x);
        return;
    }

    const int t    = threadIdx.x;
    const int w    = t >> 5;
    const int lane = t & 31;
    const int v0   = (blockIdx.x - nq) * 64;

    #pragma unroll
    for (int i = 0; i < 2; i++) {
        int u   = t + 512 * i;
        int row = u >> 4;
        int kc  = u & 15;
        int gr  = v0 + row;
        int grc = (gr < V) ? gr : 0;
        const float4* src = reinterpret_cast<const float4*>(E + (size_t)grc * DIM + kc * 8);
        float4 f0 = __ldcs(src);
        float4 f1 = __ldcs(src + 1);
        uint32_t h0 = pack_h2(f0.x, f0.y), h1 = pack_h2(f0.z, f0.w);
        uint32_t h2 = pack_h2(f1.x, f1.y), h3 = pack_h2(f1.z, f1.w);
        uint32_t off = (uint32_t)row * 256 + (uint32_t)((kc ^ (row & 7)) << 4);
        *reinterpret_cast<uint4*>(smem + P_A + off) = make_uint4(h0, h1, h2, h3);
        float s8 = ((f0.x + f0.y) + (f0.z + f0.w)) + ((f1.x + f1.y) + (f1.z + f1.w));
        s8 += __shfl_xor_sync(0xffffffffu, s8, 8);
        s8 += __shfl_xor_sync(0xffffffffu, s8, 4);
        s8 += __shfl_xor_sync(0xffffffffu, s8, 2);
        s8 += __shfl_xor_sync(0xffffffffu, s8, 1);
        if ((t & 15) == 0 && gr < V) g_Esum[gr] = s8;
    }
    {
        uint4* d = reinterpret_cast<uint4*>(smem + P_B);
        #pragma unroll
        for (int i = 0; i < 8; i++) {
            int idx = t + 512 * i;
            d[idx] = g_WT16[idx];
        }
    }
    __syncthreads();

    const int mg = w & 3;
    const int ng = w >> 2;

    float acc[8][4];
    #pragma unroll
    for (int nt = 0; nt < 8; nt++)
        #pragma unroll
        for (int j = 0; j < 4; j++) acc[nt][j] = 0.f;

    const int aRow  = mg * 16 + ((lane >> 3) & 1) * 8 + (lane & 7);
    const int aKsel = (lane >> 4);
    const int bN    = ng * 64 + ((lane >> 4) & 1) * 8 + (lane & 7);
    const int bKsel = (lane >> 3) & 1;

    #pragma unroll
    for (int ks = 0; ks < 8; ks++) {
        uint32_t a[4];
        {
            int kc = ks * 2 + aKsel;
            ldsm_x4(sb + P_A + aRow * 256 + (((kc ^ (aRow & 7)) << 4)), a);
        }
        {
            uint32_t b[2][4];
            #pragma unroll
            for (int bt = 0; bt < 2; bt++) {
                int n  = bN + bt * 16;
                int kc = ks * 2 + bKsel;
                ldsm_x4(sb + P_B + n * 256 + (((kc ^ (n & 7)) << 4)), b[bt]);
            }
            #pragma unroll
            for (int nt = 0; nt < 4; nt++)
                mma_f16(acc[nt], a, b[nt >> 1][(nt & 1) * 2], b[nt >> 1][(nt & 1) * 2 + 1]);
        }
        {
            uint32_t b[2][4];
            #pragma unroll
            for (int bt = 0; bt < 2; bt++) {
                int n  = bN + (bt + 2) * 16;
                int kc = ks * 2 + bKsel;
                ldsm_x4(sb + P_B + n * 256 + (((kc ^ (n & 7)) << 4)), b[bt]);
            }
            #pragma unroll
            for (int nt = 4; nt < 8; nt++)
                mma_f16(acc[nt], a, b[(nt - 4) >> 1][(nt & 1) * 2], b[(nt - 4) >> 1][(nt & 1) * 2 + 1]);
        }
    }

    __syncthreads();
    {
        int rl  = mg * 16 + (lane >> 2);
        int rl2 = rl + 8;
        #pragma unroll
        for (int nt = 0; nt < 8; nt++) {
            int colb = (ng * 64 + nt * 8 + (lane & 3) * 2) * 2;
            uint32_t b0 = pack_bf2(acc[nt][0], acc[nt][1]);
            uint32_t b1 = pack_bf2(acc[nt][2], acc[nt][3]);
            *reinterpret_cast<uint32_t*>(smem + P_OUT + rl  * 512 + (colb ^ ((rl  & 7) << 4))) = b0;
            *reinterpret_cast<uint32_t*>(smem + P_OUT + rl2 * 512 + (colb ^ ((rl2 & 7) << 4))) = b1;
        }
    }
    __syncthreads();
    {
        #pragma unroll
        for (int i = 0; i < 4; i++) {
            int idx = t + 512 * i;
            int row = idx >> 5, c16 = idx & 31;
            int gr = v0 + row;
            if (gr < V) {
                uint4 val = *reinterpret_cast<uint4*>(
                    smem + P_OUT + row * 512 + ((c16 * 16) ^ ((row & 7) << 4)));
                __nv_bfloat16* table = (c16 < 16) ? g_EKbf : g_EVbf;
                reinterpret_cast<uint4*>(table + (size_t)gr * DIM)[c16 & 15] = val;
            }
        }
    }
}

// ------------------------- K2b: final gemm (fp16 single pass, M=64) ----------
// 256 threads, 8 warps (warp tile 32x32), smem 48KB, 3 CTAs/SM.
#define F_A 0
#define F_B 16384
#define GEMMF_SMEM 49152

__global__ void __launch_bounds__(256, 3)
k_gemm_f(const float* __restrict__ bf, float* __restrict__ outp, int M) {
    extern __shared__ char smem[];
    const uint32_t sb = smem_to_u32(smem);
    const int t    = threadIdx.x;
    const int w    = t >> 5;
    const int lane = t & 31;
    const int m0   = blockIdx.x * 64;

    // stage A (fp16): 64 rows x 16 kc = 1024 units
    #pragma unroll
    for (int i = 0; i < 4; i++) {
        int u   = t + 256 * i;
        int row = u >> 4;
        int kc  = u & 15;
        int m   = m0 + row;
        const float4* src = reinterpret_cast<const float4*>(
            g_res + (size_t)((m < M) ? m : 0) * DIM + kc * 8);
        float4 f0 = src[0], f1 = src[1];
        uint32_t h0 = pack_h2(f0.x, f0.y), h1 = pack_h2(f0.z, f0.w);
        uint32_t h2 = pack_h2(f1.x, f1.y), h3 = pack_h2(f1.z, f1.w);
        uint32_t off = (uint32_t)row * 256 + (uint32_t)((kc ^ (row & 7)) << 4);
        *reinterpret_cast<uint4*>(smem + F_A + off) = make_uint4(h0, h1, h2, h3);
    }
    // stage B: fp16 Wf image (32KB)
    {
        uint4* d = reinterpret_cast<uint4*>(smem + F_B);
        #pragma unroll
        for (int i = 0; i < 8; i++) {
            int idx = t + 256 * i;
            d[idx] = g_WF16[idx];
        }
    }
    __syncthreads();

    const int mg = w & 1;        // 2 row groups of 32
    const int ng = w >> 1;       // 4 col groups of 32

    float acc[2][4][4];
    #pragma unroll
    for (int mt = 0; mt < 2; mt++)
        #pragma unroll
        for (int nt = 0; nt < 4; nt++)
            #pragma unroll
            for (int j = 0; j < 4; j++) acc[mt][nt][j] = 0.f;

    const int aRow  = mg * 32 + ((lane >> 3) & 1) * 8 + (lane & 7);
    const int aKsel = (lane >> 4);
    const int bN    = ng * 32 + ((lane >> 4) & 1) * 8 + (lane & 7);
    const int bKsel = (lane >> 3) & 1;

    #pragma unroll
    for (int ks = 0; ks < 8; ks++) {
        uint32_t a[2][4];
        #pragma unroll
        for (int mt = 0; mt < 2; mt++) {
            int row = aRow + mt * 16;
            int kc  = ks * 2 + aKsel;
            ldsm_x4(sb + F_A + row * 256 + (((kc ^ (row & 7)) << 4)), a[mt]);
        }
        uint32_t b[2][4];
        #pragma unroll
        for (int bt = 0; bt < 2; bt++) {
            int n  = bN + bt * 16;
            int kc = ks * 2 + bKsel;
            ldsm_x4(sb + F_B + n * 256 + (((kc ^ (n & 7)) << 4)), b[bt]);
        }
        #pragma unroll
        for (int mt = 0; mt < 2; mt++)
            #pragma unroll
            for (int nt = 0; nt < 4; nt++)
                mma_f16(acc[mt][nt], a[mt], b[nt >> 1][(nt & 1) * 2], b[nt >> 1][(nt & 1) * 2 + 1]);
    }

    #pragma unroll
    for (int mt = 0; mt < 2; mt++) {
        int row = m0 + mg * 32 + mt * 16 + (lane >> 2);
        #pragma unroll
        for (int nt = 0; nt < 4; nt++) {
            int col = ng * 32 + nt * 8 + (lane & 3) * 2;
            float b0 = bf[col], b1 = bf[col + 1];
            if (row < M) {
                *reinterpret_cast<float2*>(outp + (size_t)row * DIM + col) =
                    make_float2(acc[mt][nt][0] + b0, acc[mt][nt][1] + b1);
                if (row + 8 < M)
                    *reinterpret_cast<float2*>(outp + (size_t)(row + 8) * DIM + col) =
                        make_float2(acc[mt][nt][2] + b0, acc[mt][nt][3] + b1);
            }
        }
    }
}

// ------------------------- K3: fused attention, warp per (b,l), dual chain ---
__global__ void __launch_bounds__(256) k_attn(const int* __restrict__ queries,
                                              const int* __restrict__ keys,
                                              const float* __restrict__ E,
                                              const float* __restrict__ bk,
                                              const float* __restrict__ bv,
                                              int L2, int M) {
    const int t      = threadIdx.x;
    const int w      = t >> 5;
    const int lane   = t & 31;
    const int lane16 = lane & 15;
    const int sel    = lane >> 4;
    const int bl     = blockIdx.x * 8 + w;

    __shared__ uint2 s_km[8][52];       // {byte offset kid*256, mask as float}

    if (bl < M) {
        for (int i = lane; i < 52; i += 32) {
            uint2 v = make_uint2(0u, 0u);
            if (i < L2) {
                int kid = keys[bl * L2 + i];
                float m = (g_Esum[kid] == 0.0f) ? 0.0f : 1.0f;
                v = make_uint2((uint32_t)kid << 8, __float_as_uint(m));
            }
            s_km[w][i] = v;
        }
    }
    __syncwarp();
    if (bl >= M) return;

    const float4* qp  = reinterpret_cast<const float4*>(g_Q + (size_t)bl * DIM + lane16 * 8);
    const float4* bkp = reinterpret_cast<const float4*>(bk + lane16 * 8);
    const float4 qa = qp[0], qb = qp[1];
    const float4 ba = bkp[0], bb = bkp[1];
    float corrp = qa.x * ba.x + qa.y * ba.y + qa.z * ba.z + qa.w * ba.w
                + qb.x * bb.x + qb.y * bb.y + qb.z * bb.z + qb.w * bb.w;

    const float RS = 0.17677669529663687f;   // 1/sqrt(32)
    const char* ekb = reinterpret_cast<const char*>(g_EKbf);
    const char* evb = reinterpret_cast<const char*>(g_EVbf);
    const uint32_t lo16 = lane16 * 16;

    float a0 = 0.f, a1 = 0.f, a2 = 0.f, a3 = 0.f;
    float a4 = 0.f, a5 = 0.f, a6 = 0.f, a7 = 0.f;
    float sumw = 0.f;

    const int np = (L2 + 3) >> 2;
    for (int i = 0; i < np; i++) {
        uint2 km0 = s_km[w][4 * i + sel];
        uint2 km1 = s_km[w][4 * i + 2 + sel];
        uint4 kr0 = *reinterpret_cast<const uint4*>(ekb + km0.x + lo16);
        uint4 kr1 = *reinterpret_cast<const uint4*>(ekb + km1.x + lo16);
        uint4 vr0 = *reinterpret_cast<const uint4*>(evb + km0.x + lo16);
        uint4 vr1 = *reinterpret_cast<const uint4*>(evb + km1.x + lo16);
        float p0 = corrp, p1 = corrp;
        p0 = fmaf(qa.x, bflo(kr0.x), p0); p1 = fmaf(qa.x, bflo(kr1.x), p1);
        p0 = fmaf(qa.y, bfhi(kr0.x), p0); p1 = fmaf(qa.y, bfhi(kr1.x), p1);
        p0 = fmaf(qa.z, bflo(kr0.y), p0); p1 = fmaf(qa.z, bflo(kr1.y), p1);
        p0 = fmaf(qa.w, bfhi(kr0.y), p0); p1 = fmaf(qa.w, bfhi(kr1.y), p1);
        p0 = fmaf(qb.x, bflo(kr0.z), p0); p1 = fmaf(qb.x, bflo(kr1.z), p1);
        p0 = fmaf(qb.y, bfhi(kr0.z), p0); p1 = fmaf(qb.y, bfhi(kr1.z), p1);
        p0 = fmaf(qb.z, bflo(kr0.w), p0); p1 = fmaf(qb.z, bflo(kr1.w), p1);
        p0 = fmaf(qb.w, bfhi(kr0.w), p0); p1 = fmaf(qb.w, bfhi(kr1.w), p1);
        p0 += __shfl_xor_sync(0xffffffffu, p0, 1);
        p1 += __shfl_xor_sync(0xffffffffu, p1, 1);
        p0 += __shfl_xor_sync(0xffffffffu, p0, 2);
        p1 += __shfl_xor_sync(0xffffffffu, p1, 2);
        float w0 = __uint_as_float(km0.y) * __expf(p0 * RS);
        float w1 = __uint_as_float(km1.y) * __expf(p1 * RS);
        a0 = fmaf(w0, bflo(vr0.x), a0); a0 = fmaf(w1, bflo(vr1.x), a0);
        a1 = fmaf(w0, bfhi(vr0.x), a1); a1 = fmaf(w1, bfhi(vr1.x), a1);
        a2 = fmaf(w0, bflo(vr0.y), a2); a2 = fmaf(w1, bflo(vr1.y), a2);
        a3 = fmaf(w0, bfhi(vr0.y), a3); a3 = fmaf(w1, bfhi(vr1.y), a3);
        a4 = fmaf(w0, bflo(vr0.z), a4); a4 = fmaf(w1, bflo(vr1.z), a4);
        a5 = fmaf(w0, bfhi(vr0.z), a5); a5 = fmaf(w1, bfhi(vr1.z), a5);
        a6 = fmaf(w0, bflo(vr0.w), a6); a6 = fmaf(w1, bflo(vr1.w), a6);
        a7 = fmaf(w0, bfhi(vr0.w), a7); a7 = fmaf(w1, bfhi(vr1.w), a7);
        sumw += w0 + w1;
    }

    sumw += __shfl_xor_sync(0xffffffffu, sumw, 16);
    a0 += __shfl_xor_sync(0xffffffffu, a0, 16);
    a1 += __shfl_xor_sync(0xffffffffu, a1, 16);
    a2 += __shfl_xor_sync(0xffffffffu, a2, 16);
    a3 += __shfl_xor_sync(0xffffffffu, a3, 16);
    a4 += __shfl_xor_sync(0xffffffffu, a4, 16);
    a5 += __shfl_xor_sync(0xffffffffu, a5, 16);
    a6 += __shfl_xor_sync(0xffffffffu, a6, 16);
    a7 += __shfl_xor_sync(0xffffffffu, a7, 16);

    const float inv = 1.0f / sumw;
    const int   qid = queries[bl];
    const int   d0  = lane16 * 8 + sel * 4;
    const float4 bv4 = *reinterpret_cast<const float4*>(bv + d0);
    const float4 qe4 = *reinterpret_cast<const float4*>(E + (size_t)qid * DIM + d0);
    float4 o;
    if (sel == 0) {
        o.x = fmaf(a0, inv, bv4.x + qe4.x);
        o.y = fmaf(a1, inv, bv4.y + qe4.y);
        o.z = fmaf(a2, inv, bv4.z + qe4.z);
        o.w = fmaf(a3, inv, bv4.w + qe4.w);
    } else {
        o.x = fmaf(a4, inv, bv4.x + qe4.x);
        o.y = fmaf(a5, inv, bv4.y + qe4.y);
        o.z = fmaf(a6, inv, bv4.z + qe4.z);
        o.w = fmaf(a7, inv, bv4.w + qe4.w);
    }
    *reinterpret_cast<float4*>(g_res + (size_t)bl * DIM + d0) = o;
}

// ------------------------- launch --------------------------------------------
extern "C" void kernel_launch(void* const* d_in, const int* in_sizes, int n_in,
                              void* d_out, int out_size) {
    const int*   queries = (const int*)d_in[0];
    const int*   keys    = (const int*)d_in[1];
    const float* E       = (const float*)d_in[2];
    const float* Wq      = (const float*)d_in[3];
    const float* bq      = (const float*)d_in[4];
    const float* Wk      = (const float*)d_in[5];
    const float* bk      = (const float*)d_in[6];
    const float* Wv      = (const float*)d_in[7];
    const float* bv      = (const float*)d_in[8];
    const float* Wf      = (const float*)d_in[9];
    const float* bf      = (const float*)d_in[10];
    float* out = (float*)d_out;

    const int V  = in_sizes[2] / DIM;
    const int M  = in_sizes[0];
    const int L2 = in_sizes[1] / M;

    cudaFuncSetAttribute(k_proj_mma, cudaFuncAttributeMaxDynamicSharedMemorySize, PROJ_SMEM);
    cudaFuncSetAttribute(k_gemm_f,   cudaFuncAttributeMaxDynamicSharedMemorySize, GEMMF_SMEM);

    const int nq    = (M + 127) / 128;
    const int nproj = (V + 63) / 64;

    k_wprep<<<32, 256>>>(Wk, Wv, Wq, Wf);
    k_proj_mma<<<nq + nproj, 512, PROJ_SMEM>>>(E, queries, bq, V, M, nq);
    k_attn<<<(M + 7) / 8, 256>>>(queries, keys, E, bk, bv, L2, M);
    k_gemm_f<<<(M + 63) / 64, 256, GEMMF_SMEM>>>(bf, out, M);
}